// round 1
// baseline (speedup 1.0000x reference)
#include <cuda_runtime.h>
#include <math.h>

#define N 2048
#define HIDDEN 256
#define HEADS 8
#define DK 32

// -------------------- scratch (__device__ globals; no allocs allowed) -----
__device__ float g_bias[N * N];            // 16 MB pair bias
__device__ float g_qh[HEADS * N * DK];     // head-major projected q (scaled)
__device__ float g_kh[HEADS * N * DK];
__device__ float g_vh[HEADS * N * DK];
__device__ float g_attn[N * HIDDEN];       // attention output before O-proj
__device__ float g_coef[4];                // a_dist, a_contact, a_label, const

// -------------------- bias MLP collapse -----------------------------------
__global__ void coef_kernel(const float* __restrict__ Wd1, const float* __restrict__ bd1,
                            const float* __restrict__ Wd2, const float* __restrict__ bd2,
                            const float* __restrict__ Wc1, const float* __restrict__ bc1,
                            const float* __restrict__ Wc2, const float* __restrict__ bc2)
{
    // Wd1: (2,16) row-major, Wd2: (16,1)
    float am = 0.f, al = 0.f, c0 = bd2[0] + bc2[0], cm = 0.f;
    #pragma unroll
    for (int h = 0; h < 16; h++) {
        am += Wd1[h]      * Wd2[h];
        al += Wd1[16 + h] * Wd2[h];
        c0 += bd1[h]      * Wd2[h];
        cm += Wc1[h]      * Wc2[h];
        al += Wc1[16 + h] * Wc2[h];
        c0 += bc1[h]      * Wc2[h];
    }
    g_coef[0] = am; g_coef[1] = cm; g_coef[2] = al; g_coef[3] = c0;
}

__global__ void bias_kernel(const int* __restrict__ label,
                            const float* __restrict__ dist,
                            const float* __restrict__ contact)
{
    const float am = g_coef[0], cm = g_coef[1], al = g_coef[2], c0 = g_coef[3];
    int i = blockIdx.x * blockDim.x + threadIdx.x;   // float4 index; N*N/4 total
    float4 dm = ((const float4*)dist)[i];
    float4 cv = ((const float4*)contact)[i];
    int4   lb = ((const int4*)label)[i];
    float4 o;
    o.x = fmaf(am, dm.x, fmaf(cm, cv.x, fmaf(al, (float)lb.x, c0)));
    o.y = fmaf(am, dm.y, fmaf(cm, cv.y, fmaf(al, (float)lb.y, c0)));
    o.z = fmaf(am, dm.z, fmaf(cm, cv.z, fmaf(al, (float)lb.z, c0)));
    o.w = fmaf(am, dm.w, fmaf(cm, cv.w, fmaf(al, (float)lb.w, c0)));
    ((float4*)g_bias)[i] = o;
}

// -------------------- tiled SGEMM: [M,256] @ [256,256] + bias -------------
// mode 0: out[(j/32)*M*32 + row*32 + (j%32)] = (acc + bias[j]) * scale   (head-major)
// mode 1: out[row*256 + j] = acc + bias[j]
__global__ void proj_gemm(const float* __restrict__ A, const float* __restrict__ W,
                          const float* __restrict__ bias, float* __restrict__ out,
                          float scale, int mode, int M)
{
    __shared__ float As[16][64];
    __shared__ float Bs[16][64];
    const int tid = threadIdx.x;          // 256 threads
    const int tx = tid & 15;              // 0..15 -> 4 output cols each
    const int ty = tid >> 4;              // 0..15 -> 4 output rows each
    const int m0 = blockIdx.x * 64;
    const int n0 = blockIdx.y * 64;

    float acc[4][4];
    #pragma unroll
    for (int i = 0; i < 4; i++)
        #pragma unroll
        for (int j = 0; j < 4; j++) acc[i][j] = 0.f;

    for (int kt = 0; kt < 256; kt += 16) {
        {   // A tile 64x16 -> As[k][m] (transposed)
            int r = tid >> 2, c = (tid & 3) * 4;
            float4 a = *(const float4*)&A[(m0 + r) * 256 + kt + c];
            As[c + 0][r] = a.x; As[c + 1][r] = a.y;
            As[c + 2][r] = a.z; As[c + 3][r] = a.w;
        }
        {   // W tile 16x64 -> Bs[k][n]
            int r = tid >> 4, c = (tid & 15) * 4;
            *(float4*)&Bs[r][c] = *(const float4*)&W[(kt + r) * 256 + n0 + c];
        }
        __syncthreads();
        #pragma unroll
        for (int k = 0; k < 16; k++) {
            float4 a = *(const float4*)&As[k][ty * 4];
            float4 b = *(const float4*)&Bs[k][tx * 4];
            acc[0][0] = fmaf(a.x, b.x, acc[0][0]); acc[0][1] = fmaf(a.x, b.y, acc[0][1]);
            acc[0][2] = fmaf(a.x, b.z, acc[0][2]); acc[0][3] = fmaf(a.x, b.w, acc[0][3]);
            acc[1][0] = fmaf(a.y, b.x, acc[1][0]); acc[1][1] = fmaf(a.y, b.y, acc[1][1]);
            acc[1][2] = fmaf(a.y, b.z, acc[1][2]); acc[1][3] = fmaf(a.y, b.w, acc[1][3]);
            acc[2][0] = fmaf(a.z, b.x, acc[2][0]); acc[2][1] = fmaf(a.z, b.y, acc[2][1]);
            acc[2][2] = fmaf(a.z, b.z, acc[2][2]); acc[2][3] = fmaf(a.z, b.w, acc[2][3]);
            acc[3][0] = fmaf(a.w, b.x, acc[3][0]); acc[3][1] = fmaf(a.w, b.y, acc[3][1]);
            acc[3][2] = fmaf(a.w, b.z, acc[3][2]); acc[3][3] = fmaf(a.w, b.w, acc[3][3]);
        }
        __syncthreads();
    }

    #pragma unroll
    for (int i = 0; i < 4; i++) {
        int row = m0 + ty * 4 + i;
        #pragma unroll
        for (int j = 0; j < 4; j++) {
            int col = n0 + tx * 4 + j;
            float v = acc[i][j] + bias[col];
            if (mode == 0) {
                v *= scale;
                out[(col >> 5) * (M * 32) + row * 32 + (col & 31)] = v;
            } else {
                out[row * 256 + col] = v;
            }
        }
    }
}

// -------------------- flash attention (fp32) --------------------------------
// grid (N/64, HEADS), 64 threads; each thread owns one query row.
#define BQ 64
#define BK 64
__global__ __launch_bounds__(64) void attn_kernel()
{
    __shared__ float Ks[BK * DK];
    __shared__ float Vs[BK * DK];
    __shared__ float Bs[BQ][BK + 1];

    const int t = threadIdx.x;            // 0..63
    const int h = blockIdx.y;
    const int q0 = blockIdx.x * BQ;

    const float* qrow = &g_qh[(h * N + q0 + t) * DK];
    float4 qv[8];
    #pragma unroll
    for (int w = 0; w < 8; w++) qv[w] = ((const float4*)qrow)[w];

    float m = -INFINITY, l = 0.f;
    float4 av[8];
    #pragma unroll
    for (int w = 0; w < 8; w++) av[w] = make_float4(0.f, 0.f, 0.f, 0.f);

    for (int kb = 0; kb < N; kb += BK) {
        __syncthreads();
        {   // K/V tiles: 512 float4 each, 8 per thread, coalesced
            const float4* kg = (const float4*)&g_kh[(h * N + kb) * DK];
            const float4* vg = (const float4*)&g_vh[(h * N + kb) * DK];
            #pragma unroll
            for (int i = 0; i < 8; i++) {
                ((float4*)Ks)[i * 64 + t] = kg[i * 64 + t];
                ((float4*)Vs)[i * 64 + t] = vg[i * 64 + t];
            }
        }
        {   // bias tile [BQ rows][BK cols]; step i: coalesced row
            #pragma unroll 8
            for (int i = 0; i < BQ; i++)
                Bs[i][t] = g_bias[(size_t)(q0 + i) * N + kb + t];
        }
        __syncthreads();

        #pragma unroll
        for (int c = 0; c < BK; c += 16) {
            float s[16];
            #pragma unroll
            for (int jj = 0; jj < 16; jj++) {
                const float4* kr = (const float4*)&Ks[(c + jj) * DK];
                float d0 = 0.f, d1 = 0.f, d2 = 0.f, d3 = 0.f;
                #pragma unroll
                for (int w = 0; w < 8; w++) {
                    float4 kk = kr[w], qq = qv[w];
                    d0 = fmaf(qq.x, kk.x, d0);
                    d1 = fmaf(qq.y, kk.y, d1);
                    d2 = fmaf(qq.z, kk.z, d2);
                    d3 = fmaf(qq.w, kk.w, d3);
                }
                s[jj] = (d0 + d1) + (d2 + d3) + Bs[t][c + jj];
            }
            float cmax = s[0];
            #pragma unroll
            for (int jj = 1; jj < 16; jj++) cmax = fmaxf(cmax, s[jj]);
            float mnew = fmaxf(m, cmax);
            float corr = __expf(m - mnew);
            m = mnew;
            l *= corr;
            #pragma unroll
            for (int w = 0; w < 8; w++) {
                av[w].x *= corr; av[w].y *= corr; av[w].z *= corr; av[w].w *= corr;
            }
            #pragma unroll
            for (int jj = 0; jj < 16; jj++) {
                float p = __expf(s[jj] - m);
                l += p;
                const float4* vr = (const float4*)&Vs[(c + jj) * DK];
                #pragma unroll
                for (int w = 0; w < 8; w++) {
                    av[w].x = fmaf(p, vr[w].x, av[w].x);
                    av[w].y = fmaf(p, vr[w].y, av[w].y);
                    av[w].z = fmaf(p, vr[w].z, av[w].z);
                    av[w].w = fmaf(p, vr[w].w, av[w].w);
                }
            }
        }
    }

    float inv = 1.f / l;
    float* orow = &g_attn[(q0 + t) * HIDDEN + h * DK];
    #pragma unroll
    for (int w = 0; w < 8; w++) {
        float4 o = av[w];
        o.x *= inv; o.y *= inv; o.z *= inv; o.w *= inv;
        ((float4*)orow)[w] = o;
    }
}

// -------------------- launch ------------------------------------------------
extern "C" void kernel_launch(void* const* d_in, const int* in_sizes, int n_in,
                              void* d_out, int out_size)
{
    const int*   label   = (const int*)  d_in[0];
    const float* dist    = (const float*)d_in[1];
    const float* contact = (const float*)d_in[2];
    const float* q       = (const float*)d_in[3];
    const float* k       = (const float*)d_in[4];
    const float* v       = (const float*)d_in[5];
    const float* Wq = (const float*)d_in[6];  const float* bq = (const float*)d_in[7];
    const float* Wk = (const float*)d_in[8];  const float* bk = (const float*)d_in[9];
    const float* Wv = (const float*)d_in[10]; const float* bv = (const float*)d_in[11];
    const float* Wo = (const float*)d_in[12]; const float* bo = (const float*)d_in[13];
    const float* Wd1 = (const float*)d_in[14]; const float* bd1 = (const float*)d_in[15];
    const float* Wd2 = (const float*)d_in[16]; const float* bd2 = (const float*)d_in[17];
    const float* Wc1 = (const float*)d_in[18]; const float* bc1 = (const float*)d_in[19];
    const float* Wc2 = (const float*)d_in[20]; const float* bc2 = (const float*)d_in[21];
    float* out = (float*)d_out;

    float *p_bias, *p_qh, *p_kh, *p_vh, *p_attn;
    cudaGetSymbolAddress((void**)&p_bias, g_bias);
    cudaGetSymbolAddress((void**)&p_qh,   g_qh);
    cudaGetSymbolAddress((void**)&p_kh,   g_kh);
    cudaGetSymbolAddress((void**)&p_vh,   g_vh);
    cudaGetSymbolAddress((void**)&p_attn, g_attn);

    // 1) collapse bias MLPs to 4 scalars, then materialize pair bias
    coef_kernel<<<1, 1>>>(Wd1, bd1, Wd2, bd2, Wc1, bc1, Wc2, bc2);
    bias_kernel<<<(N * N / 4) / 256, 256>>>(label, dist, contact);

    // 2) projections (head-major repack; q scaled by 1/sqrt(DK))
    dim3 ggrid(N / 64, HIDDEN / 64);
    const float scale = 1.f / sqrtf((float)DK);
    proj_gemm<<<ggrid, 256>>>(q, Wq, bq, p_qh, scale, 0, N);
    proj_gemm<<<ggrid, 256>>>(k, Wk, bk, p_kh, 1.f,   0, N);
    proj_gemm<<<ggrid, 256>>>(v, Wv, bv, p_vh, 1.f,   0, N);

    // 3) fused flash attention with precomputed bias
    attn_kernel<<<dim3(N / BQ, HEADS), 64>>>();

    // 4) output projection
    proj_gemm<<<ggrid, 256>>>(p_attn, Wo, bo, out, 1.f, 1, N);
}

// round 2
// speedup vs baseline: 1.3757x; 1.3757x over previous
#include <cuda_runtime.h>
#include <math.h>

#define N 2048
#define HIDDEN 256
#define HEADS 8
#define DK 32
#define NSPLIT 4
#define KSPAN (N / NSPLIT)

// -------------------- scratch (__device__ globals; no allocs allowed) -----
__device__ float g_bias[N * N];            // 16 MB pair bias
__device__ float g_qh[HEADS * N * DK];     // head-major projected q (scaled)
__device__ float g_kh[HEADS * N * DK];
__device__ float g_vh[HEADS * N * DK];
__device__ float g_attn[N * HIDDEN];       // attention output before O-proj
__device__ float g_coef[4];                // a_dist, a_contact, a_label, const
// split-K partials
__device__ float g_pm[NSPLIT * HEADS * N];
__device__ float g_pl[NSPLIT * HEADS * N];
__device__ float g_pav[NSPLIT * HEADS * N * DK];   // 8 MB

// -------------------- bias MLP collapse -----------------------------------
__global__ void coef_kernel(const float* __restrict__ Wd1, const float* __restrict__ bd1,
                            const float* __restrict__ Wd2, const float* __restrict__ bd2,
                            const float* __restrict__ Wc1, const float* __restrict__ bc1,
                            const float* __restrict__ Wc2, const float* __restrict__ bc2)
{
    float am = 0.f, al = 0.f, c0 = bd2[0] + bc2[0], cm = 0.f;
    #pragma unroll
    for (int h = 0; h < 16; h++) {
        am += Wd1[h]      * Wd2[h];
        al += Wd1[16 + h] * Wd2[h];
        c0 += bd1[h]      * Wd2[h];
        cm += Wc1[h]      * Wc2[h];
        al += Wc1[16 + h] * Wc2[h];
        c0 += bc1[h]      * Wc2[h];
    }
    g_coef[0] = am; g_coef[1] = cm; g_coef[2] = al; g_coef[3] = c0;
}

__global__ void bias_kernel(const int* __restrict__ label,
                            const float* __restrict__ dist,
                            const float* __restrict__ contact)
{
    const float am = g_coef[0], cm = g_coef[1], al = g_coef[2], c0 = g_coef[3];
    int i = blockIdx.x * blockDim.x + threadIdx.x;
    float4 dm = ((const float4*)dist)[i];
    float4 cv = ((const float4*)contact)[i];
    int4   lb = ((const int4*)label)[i];
    float4 o;
    o.x = fmaf(am, dm.x, fmaf(cm, cv.x, fmaf(al, (float)lb.x, c0)));
    o.y = fmaf(am, dm.y, fmaf(cm, cv.y, fmaf(al, (float)lb.y, c0)));
    o.z = fmaf(am, dm.z, fmaf(cm, cv.z, fmaf(al, (float)lb.z, c0)));
    o.w = fmaf(am, dm.w, fmaf(cm, cv.w, fmaf(al, (float)lb.w, c0)));
    ((float4*)g_bias)[i] = o;
}

// -------------------- tiled SGEMM: [M,256] @ [256,256] + bias -------------
__global__ void proj_gemm(const float* __restrict__ A, const float* __restrict__ W,
                          const float* __restrict__ bias, float* __restrict__ out,
                          float scale, int mode, int M)
{
    __shared__ float As[16][64];
    __shared__ float Bs[16][64];
    const int tid = threadIdx.x;
    const int tx = tid & 15;
    const int ty = tid >> 4;
    const int m0 = blockIdx.x * 64;
    const int n0 = blockIdx.y * 64;

    float acc[4][4];
    #pragma unroll
    for (int i = 0; i < 4; i++)
        #pragma unroll
        for (int j = 0; j < 4; j++) acc[i][j] = 0.f;

    for (int kt = 0; kt < 256; kt += 16) {
        {
            int r = tid >> 2, c = (tid & 3) * 4;
            float4 a = *(const float4*)&A[(m0 + r) * 256 + kt + c];
            As[c + 0][r] = a.x; As[c + 1][r] = a.y;
            As[c + 2][r] = a.z; As[c + 3][r] = a.w;
        }
        {
            int r = tid >> 4, c = (tid & 15) * 4;
            *(float4*)&Bs[r][c] = *(const float4*)&W[(kt + r) * 256 + n0 + c];
        }
        __syncthreads();
        #pragma unroll
        for (int k = 0; k < 16; k++) {
            float4 a = *(const float4*)&As[k][ty * 4];
            float4 b = *(const float4*)&Bs[k][tx * 4];
            acc[0][0] = fmaf(a.x, b.x, acc[0][0]); acc[0][1] = fmaf(a.x, b.y, acc[0][1]);
            acc[0][2] = fmaf(a.x, b.z, acc[0][2]); acc[0][3] = fmaf(a.x, b.w, acc[0][3]);
            acc[1][0] = fmaf(a.y, b.x, acc[1][0]); acc[1][1] = fmaf(a.y, b.y, acc[1][1]);
            acc[1][2] = fmaf(a.y, b.z, acc[1][2]); acc[1][3] = fmaf(a.y, b.w, acc[1][3]);
            acc[2][0] = fmaf(a.z, b.x, acc[2][0]); acc[2][1] = fmaf(a.z, b.y, acc[2][1]);
            acc[2][2] = fmaf(a.z, b.z, acc[2][2]); acc[2][3] = fmaf(a.z, b.w, acc[2][3]);
            acc[3][0] = fmaf(a.w, b.x, acc[3][0]); acc[3][1] = fmaf(a.w, b.y, acc[3][1]);
            acc[3][2] = fmaf(a.w, b.z, acc[3][2]); acc[3][3] = fmaf(a.w, b.w, acc[3][3]);
        }
        __syncthreads();
    }

    #pragma unroll
    for (int i = 0; i < 4; i++) {
        int row = m0 + ty * 4 + i;
        #pragma unroll
        for (int j = 0; j < 4; j++) {
            int col = n0 + tx * 4 + j;
            float v = acc[i][j] + bias[col];
            if (mode == 0) {
                v *= scale;
                out[(col >> 5) * (M * 32) + row * 32 + (col & 31)] = v;
            } else {
                out[row * 256 + col] = v;
            }
        }
    }
}

// -------------------- split-K flash attention (fp32) ----------------------
// grid (N/64, HEADS, NSPLIT), 64 threads; thread owns one query row,
// block processes KSPAN keys; partial (m,l,acc) written to scratch.
#define BQ 64
#define BK 64
__global__ __launch_bounds__(64) void attn_kernel()
{
    __shared__ float Ks[BK * DK];
    __shared__ float Vs[BK * DK];
    __shared__ float Bs[BQ][BK + 1];

    const int t = threadIdx.x;
    const int h = blockIdx.y;
    const int z = blockIdx.z;
    const int q0 = blockIdx.x * BQ;
    const int k0 = z * KSPAN;

    const float* qrow = &g_qh[(h * N + q0 + t) * DK];
    float4 qv[8];
    #pragma unroll
    for (int w = 0; w < 8; w++) qv[w] = ((const float4*)qrow)[w];

    float m = -INFINITY, l = 0.f;
    float4 av[8];
    #pragma unroll
    for (int w = 0; w < 8; w++) av[w] = make_float4(0.f, 0.f, 0.f, 0.f);

    for (int kb = k0; kb < k0 + KSPAN; kb += BK) {
        __syncthreads();
        {
            const float4* kg = (const float4*)&g_kh[(h * N + kb) * DK];
            const float4* vg = (const float4*)&g_vh[(h * N + kb) * DK];
            #pragma unroll
            for (int i = 0; i < 8; i++) {
                ((float4*)Ks)[i * 64 + t] = kg[i * 64 + t];
                ((float4*)Vs)[i * 64 + t] = vg[i * 64 + t];
            }
        }
        {
            #pragma unroll 8
            for (int i = 0; i < BQ; i++)
                Bs[i][t] = g_bias[(size_t)(q0 + i) * N + kb + t];
        }
        __syncthreads();

        #pragma unroll
        for (int c = 0; c < BK; c += 16) {
            float s[16];
            #pragma unroll
            for (int jj = 0; jj < 16; jj++) {
                const float4* kr = (const float4*)&Ks[(c + jj) * DK];
                float d0 = 0.f, d1 = 0.f, d2 = 0.f, d3 = 0.f;
                #pragma unroll
                for (int w = 0; w < 8; w++) {
                    float4 kk = kr[w], qq = qv[w];
                    d0 = fmaf(qq.x, kk.x, d0);
                    d1 = fmaf(qq.y, kk.y, d1);
                    d2 = fmaf(qq.z, kk.z, d2);
                    d3 = fmaf(qq.w, kk.w, d3);
                }
                s[jj] = (d0 + d1) + (d2 + d3) + Bs[t][c + jj];
            }
            float cmax = s[0];
            #pragma unroll
            for (int jj = 1; jj < 16; jj++) cmax = fmaxf(cmax, s[jj]);
            float mnew = fmaxf(m, cmax);
            float corr = __expf(m - mnew);
            m = mnew;
            l *= corr;
            #pragma unroll
            for (int w = 0; w < 8; w++) {
                av[w].x *= corr; av[w].y *= corr; av[w].z *= corr; av[w].w *= corr;
            }
            #pragma unroll
            for (int jj = 0; jj < 16; jj++) {
                float p = __expf(s[jj] - m);
                l += p;
                const float4* vr = (const float4*)&Vs[(c + jj) * DK];
                #pragma unroll
                for (int w = 0; w < 8; w++) {
                    av[w].x = fmaf(p, vr[w].x, av[w].x);
                    av[w].y = fmaf(p, vr[w].y, av[w].y);
                    av[w].z = fmaf(p, vr[w].z, av[w].z);
                    av[w].w = fmaf(p, vr[w].w, av[w].w);
                }
            }
        }
    }

    // write partials (unnormalized)
    const int rid = (z * HEADS + h) * N + q0 + t;
    g_pm[rid] = m;
    g_pl[rid] = l;
    float* pav = &g_pav[(size_t)rid * DK];
    #pragma unroll
    for (int w = 0; w < 8; w++) ((float4*)pav)[w] = av[w];
}

// -------------------- split-K combine ------------------------------------
// one thread per (head,row): merge NSPLIT partials, write to g_attn
__global__ void combine_kernel()
{
    int idx = blockIdx.x * blockDim.x + threadIdx.x;   // over HEADS*N
    int h = idx >> 11;          // / N
    int row = idx & (N - 1);

    float M = -INFINITY;
    #pragma unroll
    for (int s = 0; s < NSPLIT; s++)
        M = fmaxf(M, g_pm[(s * HEADS + h) * N + row]);

    float l = 0.f;
    float4 acc[8];
    #pragma unroll
    for (int w = 0; w < 8; w++) acc[w] = make_float4(0.f, 0.f, 0.f, 0.f);

    #pragma unroll
    for (int s = 0; s < NSPLIT; s++) {
        int rid = (s * HEADS + h) * N + row;
        float wgt = __expf(g_pm[rid] - M);
        l += g_pl[rid] * wgt;
        const float4* pav = (const float4*)&g_pav[(size_t)rid * DK];
        #pragma unroll
        for (int w = 0; w < 8; w++) {
            float4 a = pav[w];
            acc[w].x = fmaf(a.x, wgt, acc[w].x);
            acc[w].y = fmaf(a.y, wgt, acc[w].y);
            acc[w].z = fmaf(a.z, wgt, acc[w].z);
            acc[w].w = fmaf(a.w, wgt, acc[w].w);
        }
    }
    float inv = 1.f / l;
    float* orow = &g_attn[(size_t)row * HIDDEN + h * DK];
    #pragma unroll
    for (int w = 0; w < 8; w++) {
        float4 o = acc[w];
        o.x *= inv; o.y *= inv; o.z *= inv; o.w *= inv;
        ((float4*)orow)[w] = o;
    }
}

// -------------------- launch ------------------------------------------------
extern "C" void kernel_launch(void* const* d_in, const int* in_sizes, int n_in,
                              void* d_out, int out_size)
{
    const int*   label   = (const int*)  d_in[0];
    const float* dist    = (const float*)d_in[1];
    const float* contact = (const float*)d_in[2];
    const float* q       = (const float*)d_in[3];
    const float* k       = (const float*)d_in[4];
    const float* v       = (const float*)d_in[5];
    const float* Wq = (const float*)d_in[6];  const float* bq = (const float*)d_in[7];
    const float* Wk = (const float*)d_in[8];  const float* bk = (const float*)d_in[9];
    const float* Wv = (const float*)d_in[10]; const float* bv = (const float*)d_in[11];
    const float* Wo = (const float*)d_in[12]; const float* bo = (const float*)d_in[13];
    const float* Wd1 = (const float*)d_in[14]; const float* bd1 = (const float*)d_in[15];
    const float* Wd2 = (const float*)d_in[16]; const float* bd2 = (const float*)d_in[17];
    const float* Wc1 = (const float*)d_in[18]; const float* bc1 = (const float*)d_in[19];
    const float* Wc2 = (const float*)d_in[20]; const float* bc2 = (const float*)d_in[21];
    float* out = (float*)d_out;

    float *p_qh, *p_kh, *p_vh, *p_attn;
    cudaGetSymbolAddress((void**)&p_qh,   g_qh);
    cudaGetSymbolAddress((void**)&p_kh,   g_kh);
    cudaGetSymbolAddress((void**)&p_vh,   g_vh);
    cudaGetSymbolAddress((void**)&p_attn, g_attn);

    // 1) collapse bias MLPs to 4 scalars, then materialize pair bias
    coef_kernel<<<1, 1>>>(Wd1, bd1, Wd2, bd2, Wc1, bc1, Wc2, bc2);
    bias_kernel<<<(N * N / 4) / 256, 256>>>(label, dist, contact);

    // 2) projections (head-major repack; q scaled by 1/sqrt(DK))
    dim3 ggrid(N / 64, HIDDEN / 64);
    const float scale = 1.f / sqrtf((float)DK);
    proj_gemm<<<ggrid, 256>>>(q, Wq, bq, p_qh, scale, 0, N);
    proj_gemm<<<ggrid, 256>>>(k, Wk, bk, p_kh, 1.f,   0, N);
    proj_gemm<<<ggrid, 256>>>(v, Wv, bv, p_vh, 1.f,   0, N);

    // 3) split-K flash attention + combine
    attn_kernel<<<dim3(N / BQ, HEADS, NSPLIT), 64>>>();
    combine_kernel<<<(HEADS * N) / 128, 128>>>();

    // 4) output projection
    proj_gemm<<<ggrid, 256>>>(p_attn, Wo, bo, out, 1.f, 1, N);
}

// round 3
// speedup vs baseline: 2.3976x; 1.7428x over previous
#include <cuda_runtime.h>
#include <math.h>
#include <stdint.h>

#define N 2048
#define HIDDEN 256
#define HEADS 8
#define DK 32
#define NSPLIT 4
#define KSPAN (N / NSPLIT)

// -------------------- scratch (__device__ globals; no allocs allowed) -----
__device__ float g_bias[N * N];            // 16 MB pair bias
__device__ float g_qh[HEADS * N * DK];     // head-major projected q (scaled)
__device__ float g_kh[HEADS * N * DK];
__device__ float g_vh[HEADS * N * DK];
__device__ float g_attn[N * HIDDEN];       // attention output before O-proj
__device__ float g_coef[4];
// split-K partials
__device__ float g_pm[NSPLIT * HEADS * N];
__device__ float g_pl[NSPLIT * HEADS * N];
__device__ float g_pav[NSPLIT * HEADS * N * DK];

// -------------------- helpers ---------------------------------------------
__device__ __forceinline__ uint32_t f2tf(float f) {
    uint32_t u;
    asm("cvt.rna.tf32.f32 %0, %1;" : "=r"(u) : "f"(f));
    return u;
}

__device__ __forceinline__ void mma_tf32(float& d0, float& d1, float& d2, float& d3,
                                         uint32_t a0, uint32_t a1, uint32_t a2, uint32_t a3,
                                         uint32_t b0, uint32_t b1)
{
    asm volatile("mma.sync.aligned.m16n8k8.row.col.f32.tf32.tf32.f32 "
                 "{%0,%1,%2,%3}, {%4,%5,%6,%7}, {%8,%9}, {%0,%1,%2,%3};"
                 : "+f"(d0), "+f"(d1), "+f"(d2), "+f"(d3)
                 : "r"(a0), "r"(a1), "r"(a2), "r"(a3), "r"(b0), "r"(b1));
}

// -------------------- bias MLP collapse -----------------------------------
__global__ void coef_kernel(const float* __restrict__ Wd1, const float* __restrict__ bd1,
                            const float* __restrict__ Wd2, const float* __restrict__ bd2,
                            const float* __restrict__ Wc1, const float* __restrict__ bc1,
                            const float* __restrict__ Wc2, const float* __restrict__ bc2)
{
    float am = 0.f, al = 0.f, c0 = bd2[0] + bc2[0], cm = 0.f;
    #pragma unroll
    for (int h = 0; h < 16; h++) {
        am += Wd1[h]      * Wd2[h];
        al += Wd1[16 + h] * Wd2[h];
        c0 += bd1[h]      * Wd2[h];
        cm += Wc1[h]      * Wc2[h];
        al += Wc1[16 + h] * Wc2[h];
        c0 += bc1[h]      * Wc2[h];
    }
    g_coef[0] = am; g_coef[1] = cm; g_coef[2] = al; g_coef[3] = c0;
}

__global__ void bias_kernel(const int* __restrict__ label,
                            const float* __restrict__ dist,
                            const float* __restrict__ contact)
{
    const float am = g_coef[0], cm = g_coef[1], al = g_coef[2], c0 = g_coef[3];
    int i = blockIdx.x * blockDim.x + threadIdx.x;
    float4 dm = ((const float4*)dist)[i];
    float4 cv = ((const float4*)contact)[i];
    int4   lb = ((const int4*)label)[i];
    float4 o;
    o.x = fmaf(am, dm.x, fmaf(cm, cv.x, fmaf(al, (float)lb.x, c0)));
    o.y = fmaf(am, dm.y, fmaf(cm, cv.y, fmaf(al, (float)lb.y, c0)));
    o.z = fmaf(am, dm.z, fmaf(cm, cv.z, fmaf(al, (float)lb.z, c0)));
    o.w = fmaf(am, dm.w, fmaf(cm, cv.w, fmaf(al, (float)lb.w, c0)));
    ((float4*)g_bias)[i] = o;
}

// -------------------- tiled SGEMM: [M,256] @ [256,256] + bias -------------
__global__ void proj_gemm(const float* __restrict__ A, const float* __restrict__ W,
                          const float* __restrict__ bias, float* __restrict__ out,
                          float scale, int mode, int M)
{
    __shared__ float As[16][64];
    __shared__ float Bs[16][64];
    const int tid = threadIdx.x;
    const int tx = tid & 15;
    const int ty = tid >> 4;
    const int m0 = blockIdx.x * 64;
    const int n0 = blockIdx.y * 64;

    float acc[4][4];
    #pragma unroll
    for (int i = 0; i < 4; i++)
        #pragma unroll
        for (int j = 0; j < 4; j++) acc[i][j] = 0.f;

    for (int kt = 0; kt < 256; kt += 16) {
        {
            int r = tid >> 2, c = (tid & 3) * 4;
            float4 a = *(const float4*)&A[(m0 + r) * 256 + kt + c];
            As[c + 0][r] = a.x; As[c + 1][r] = a.y;
            As[c + 2][r] = a.z; As[c + 3][r] = a.w;
        }
        {
            int r = tid >> 4, c = (tid & 15) * 4;
            *(float4*)&Bs[r][c] = *(const float4*)&W[(kt + r) * 256 + n0 + c];
        }
        __syncthreads();
        #pragma unroll
        for (int k = 0; k < 16; k++) {
            float4 a = *(const float4*)&As[k][ty * 4];
            float4 b = *(const float4*)&Bs[k][tx * 4];
            acc[0][0] = fmaf(a.x, b.x, acc[0][0]); acc[0][1] = fmaf(a.x, b.y, acc[0][1]);
            acc[0][2] = fmaf(a.x, b.z, acc[0][2]); acc[0][3] = fmaf(a.x, b.w, acc[0][3]);
            acc[1][0] = fmaf(a.y, b.x, acc[1][0]); acc[1][1] = fmaf(a.y, b.y, acc[1][1]);
            acc[1][2] = fmaf(a.y, b.z, acc[1][2]); acc[1][3] = fmaf(a.y, b.w, acc[1][3]);
            acc[2][0] = fmaf(a.z, b.x, acc[2][0]); acc[2][1] = fmaf(a.z, b.y, acc[2][1]);
            acc[2][2] = fmaf(a.z, b.z, acc[2][2]); acc[2][3] = fmaf(a.z, b.w, acc[2][3]);
            acc[3][0] = fmaf(a.w, b.x, acc[3][0]); acc[3][1] = fmaf(a.w, b.y, acc[3][1]);
            acc[3][2] = fmaf(a.w, b.z, acc[3][2]); acc[3][3] = fmaf(a.w, b.w, acc[3][3]);
        }
        __syncthreads();
    }

    #pragma unroll
    for (int i = 0; i < 4; i++) {
        int row = m0 + ty * 4 + i;
        #pragma unroll
        for (int j = 0; j < 4; j++) {
            int col = n0 + tx * 4 + j;
            float v = acc[i][j] + bias[col];
            if (mode == 0) {
                v *= scale;
                out[(col >> 5) * (M * 32) + row * 32 + (col & 31)] = v;
            } else {
                out[row * 256 + col] = v;
            }
        }
    }
}

// -------------------- tf32 tensor-core flash attention ---------------------
// grid (N/64, HEADS, NSPLIT), 128 threads (4 warps, 16 q-rows each).
// S tile: 64 q x 64 keys via m16n8k8; PV: 64 x 32 via m16n8k8.
// K/V staged in fragment-major smem: [pair(32)][lane(32)][2] tf32 words.
__global__ __launch_bounds__(128) void attn_mma_kernel()
{
    __shared__ uint32_t KB[2048];   // 8 KB
    __shared__ uint32_t VB[2048];   // 8 KB

    const int tid  = threadIdx.x;
    const int lane = tid & 31;
    const int warp = tid >> 5;
    const int q    = lane & 3;      // threadID in group
    const int g    = lane >> 2;     // groupID
    const int h  = blockIdx.y;
    const int z  = blockIdx.z;
    const int q0 = blockIdx.x * 64;
    const int wr0 = warp * 16;
    const int row = q0 + wr0 + g;   // this thread's first q row (also row+8)

    // ---- Q fragments (held for whole kernel) ----
    uint32_t qa[4][4];
    const float* qbase = &g_qh[((size_t)h * N + row) * DK];
    #pragma unroll
    for (int s = 0; s < 4; s++) {
        int d = s * 8 + q;
        qa[s][0] = f2tf(qbase[d]);
        qa[s][1] = f2tf(qbase[8 * DK + d]);
        qa[s][2] = f2tf(qbase[d + 4]);
        qa[s][3] = f2tf(qbase[8 * DK + d + 4]);
    }

    float o[4][4];
    #pragma unroll
    for (int n = 0; n < 4; n++)
        #pragma unroll
        for (int e = 0; e < 4; e++) o[n][e] = 0.f;

    float m0 = -INFINITY, m8 = -INFINITY, l0 = 0.f, l8 = 0.f;

    const int l1 = (lane & 0x1c) | (q >> 1);
    const int l2 = l1 + 2;
    const bool odd = (q & 1);

    for (int kb = z * KSPAN; kb < z * KSPAN + KSPAN; kb += 64) {
        __syncthreads();
        // ---- cooperative fill of fragment-major K/V tiles ----
        {
            const float4* kg = (const float4*)&g_kh[((size_t)h * N + kb) * DK];
            const float4* vg = (const float4*)&g_vh[((size_t)h * N + kb) * DK];
            #pragma unroll
            for (int i = 0; i < 4; i++) {
                int idx = i * 128 + tid;
                float4 kf = kg[idx];
                float4 vf = vg[idx];
                int e   = idx * 4;
                int key = e >> 5;
                int d0  = e & 31;
                // K: element (key,d) -> thread (d&3)+4*(key&7), pair (d>>3)*8+(key>>3), slot (d>>2)&1
                {
                    int pb = (d0 >> 3) * 8 + (key & 63) / 8;
                    int bb = (d0 >> 2) & 1;
                    int tb = 4 * (key & 7);
                    uint32_t* dst = &KB[(pb * 32 + tb) * 2 + bb];
                    dst[0 * 2] = f2tf(kf.x);
                    dst[1 * 2] = f2tf(kf.y);
                    dst[2 * 2] = f2tf(kf.z);
                    dst[3 * 2] = f2tf(kf.w);
                }
                // V: element (key,d) -> thread (key&3)+4*(d&7), pair (key>>3)*4+(d>>3), slot (key>>2)&1
                {
                    int pb = ((key & 63) / 8) * 4 + (d0 >> 3);
                    int bb = (key >> 2) & 1;
                    int tb = (key & 3);
                    uint32_t* dst = &VB[(pb * 32 + tb + 4 * (d0 & 7)) * 2 + bb];
                    dst[0 * 8] = f2tf(vf.x);   // d+1 -> thread +4 -> addr +8
                    dst[1 * 8] = f2tf(vf.y);
                    dst[2 * 8] = f2tf(vf.z);
                    dst[3 * 8] = f2tf(vf.w);
                }
            }
        }
        __syncthreads();

        // ---- S = Q @ K^T ----
        float s[8][4];
        #pragma unroll
        for (int j = 0; j < 8; j++)
            #pragma unroll
            for (int e = 0; e < 4; e++) s[j][e] = 0.f;

        #pragma unroll
        for (int ks = 0; ks < 4; ks++) {
            #pragma unroll
            for (int j = 0; j < 8; j++) {
                uint2 b = *(const uint2*)&KB[((ks * 8 + j) * 32 + lane) * 2];
                mma_tf32(s[j][0], s[j][1], s[j][2], s[j][3],
                         qa[ks][0], qa[ks][1], qa[ks][2], qa[ks][3], b.x, b.y);
            }
        }

        // ---- + bias ----
        {
            const float* brow = &g_bias[(size_t)row * N + kb];
            #pragma unroll
            for (int j = 0; j < 8; j++) {
                float2 b0 = *(const float2*)&brow[8 * j + 2 * q];
                float2 b8 = *(const float2*)&brow[(size_t)8 * N + 8 * j + 2 * q];
                s[j][0] += b0.x; s[j][1] += b0.y;
                s[j][2] += b8.x; s[j][3] += b8.y;
            }
        }

        // ---- online softmax ----
        float mx0 = s[0][0], mx8 = s[0][2];
        #pragma unroll
        for (int j = 0; j < 8; j++) {
            mx0 = fmaxf(mx0, fmaxf(s[j][0], s[j][1]));
            mx8 = fmaxf(mx8, fmaxf(s[j][2], s[j][3]));
        }
        mx0 = fmaxf(mx0, __shfl_xor_sync(0xffffffffu, mx0, 1));
        mx0 = fmaxf(mx0, __shfl_xor_sync(0xffffffffu, mx0, 2));
        mx8 = fmaxf(mx8, __shfl_xor_sync(0xffffffffu, mx8, 1));
        mx8 = fmaxf(mx8, __shfl_xor_sync(0xffffffffu, mx8, 2));

        float mn0 = fmaxf(m0, mx0), mn8 = fmaxf(m8, mx8);
        float c0 = __expf(m0 - mn0), c8 = __expf(m8 - mn8);
        m0 = mn0; m8 = mn8;
        l0 *= c0;  l8 *= c8;
        #pragma unroll
        for (int n = 0; n < 4; n++) {
            o[n][0] *= c0; o[n][1] *= c0;
            o[n][2] *= c8; o[n][3] *= c8;
        }

        uint32_t pu[8][4];
        #pragma unroll
        for (int j = 0; j < 8; j++) {
            float p0 = __expf(s[j][0] - m0);
            float p1 = __expf(s[j][1] - m0);
            float p2 = __expf(s[j][2] - m8);
            float p3 = __expf(s[j][3] - m8);
            l0 += p0 + p1;
            l8 += p2 + p3;
            pu[j][0] = f2tf(p0); pu[j][1] = f2tf(p1);
            pu[j][2] = f2tf(p2); pu[j][3] = f2tf(p3);
        }

        // ---- O += P @ V ----
        #pragma unroll
        for (int j = 0; j < 8; j++) {
            uint32_t x0 = __shfl_sync(0xffffffffu, pu[j][0], l1);
            uint32_t x1 = __shfl_sync(0xffffffffu, pu[j][1], l1);
            uint32_t y0 = __shfl_sync(0xffffffffu, pu[j][2], l1);
            uint32_t y1 = __shfl_sync(0xffffffffu, pu[j][3], l1);
            uint32_t x2 = __shfl_sync(0xffffffffu, pu[j][0], l2);
            uint32_t x3 = __shfl_sync(0xffffffffu, pu[j][1], l2);
            uint32_t y2 = __shfl_sync(0xffffffffu, pu[j][2], l2);
            uint32_t y3 = __shfl_sync(0xffffffffu, pu[j][3], l2);
            uint32_t a0 = odd ? x1 : x0;
            uint32_t a1 = odd ? y1 : y0;
            uint32_t a2 = odd ? x3 : x2;
            uint32_t a3 = odd ? y3 : y2;
            #pragma unroll
            for (int n = 0; n < 4; n++) {
                uint2 b = *(const uint2*)&VB[((j * 4 + n) * 32 + lane) * 2];
                mma_tf32(o[n][0], o[n][1], o[n][2], o[n][3], a0, a1, a2, a3, b.x, b.y);
            }
        }
    }

    // ---- finalize: reduce l across quad, write partials ----
    l0 += __shfl_xor_sync(0xffffffffu, l0, 1);
    l0 += __shfl_xor_sync(0xffffffffu, l0, 2);
    l8 += __shfl_xor_sync(0xffffffffu, l8, 1);
    l8 += __shfl_xor_sync(0xffffffffu, l8, 2);

    const int rid = (z * HEADS + h) * N + q0 + wr0 + g;
    if (q == 0) {
        g_pm[rid] = m0;     g_pl[rid] = l0;
        g_pm[rid + 8] = m8; g_pl[rid + 8] = l8;
    }
    float* pav0 = &g_pav[(size_t)rid * DK];
    float* pav8 = &g_pav[(size_t)(rid + 8) * DK];
    #pragma unroll
    for (int n = 0; n < 4; n++) {
        *(float2*)&pav0[8 * n + 2 * q] = make_float2(o[n][0], o[n][1]);
        *(float2*)&pav8[8 * n + 2 * q] = make_float2(o[n][2], o[n][3]);
    }
}

// -------------------- split-K combine ------------------------------------
__global__ void combine_kernel()
{
    int idx = blockIdx.x * blockDim.x + threadIdx.x;
    int h = idx >> 11;
    int row = idx & (N - 1);

    float M = -INFINITY;
    #pragma unroll
    for (int s = 0; s < NSPLIT; s++)
        M = fmaxf(M, g_pm[(s * HEADS + h) * N + row]);

    float l = 0.f;
    float4 acc[8];
    #pragma unroll
    for (int w = 0; w < 8; w++) acc[w] = make_float4(0.f, 0.f, 0.f, 0.f);

    #pragma unroll
    for (int s = 0; s < NSPLIT; s++) {
        int rid = (s * HEADS + h) * N + row;
        float wgt = __expf(g_pm[rid] - M);
        l += g_pl[rid] * wgt;
        const float4* pav = (const float4*)&g_pav[(size_t)rid * DK];
        #pragma unroll
        for (int w = 0; w < 8; w++) {
            float4 a = pav[w];
            acc[w].x = fmaf(a.x, wgt, acc[w].x);
            acc[w].y = fmaf(a.y, wgt, acc[w].y);
            acc[w].z = fmaf(a.z, wgt, acc[w].z);
            acc[w].w = fmaf(a.w, wgt, acc[w].w);
        }
    }
    float inv = 1.f / l;
    float* orow = &g_attn[(size_t)row * HIDDEN + h * DK];
    #pragma unroll
    for (int w = 0; w < 8; w++) {
        float4 v = acc[w];
        v.x *= inv; v.y *= inv; v.z *= inv; v.w *= inv;
        ((float4*)orow)[w] = v;
    }
}

// -------------------- launch ------------------------------------------------
extern "C" void kernel_launch(void* const* d_in, const int* in_sizes, int n_in,
                              void* d_out, int out_size)
{
    const int*   label   = (const int*)  d_in[0];
    const float* dist    = (const float*)d_in[1];
    const float* contact = (const float*)d_in[2];
    const float* q       = (const float*)d_in[3];
    const float* k       = (const float*)d_in[4];
    const float* v       = (const float*)d_in[5];
    const float* Wq = (const float*)d_in[6];  const float* bq = (const float*)d_in[7];
    const float* Wk = (const float*)d_in[8];  const float* bk = (const float*)d_in[9];
    const float* Wv = (const float*)d_in[10]; const float* bv = (const float*)d_in[11];
    const float* Wo = (const float*)d_in[12]; const float* bo = (const float*)d_in[13];
    const float* Wd1 = (const float*)d_in[14]; const float* bd1 = (const float*)d_in[15];
    const float* Wd2 = (const float*)d_in[16]; const float* bd2 = (const float*)d_in[17];
    const float* Wc1 = (const float*)d_in[18]; const float* bc1 = (const float*)d_in[19];
    const float* Wc2 = (const float*)d_in[20]; const float* bc2 = (const float*)d_in[21];
    float* out = (float*)d_out;

    float *p_qh, *p_kh, *p_vh, *p_attn;
    cudaGetSymbolAddress((void**)&p_qh,   g_qh);
    cudaGetSymbolAddress((void**)&p_kh,   g_kh);
    cudaGetSymbolAddress((void**)&p_vh,   g_vh);
    cudaGetSymbolAddress((void**)&p_attn, g_attn);

    coef_kernel<<<1, 1>>>(Wd1, bd1, Wd2, bd2, Wc1, bc1, Wc2, bc2);
    bias_kernel<<<(N * N / 4) / 256, 256>>>(label, dist, contact);

    dim3 ggrid(N / 64, HIDDEN / 64);
    const float scale = 1.f / sqrtf((float)DK);
    proj_gemm<<<ggrid, 256>>>(q, Wq, bq, p_qh, scale, 0, N);
    proj_gemm<<<ggrid, 256>>>(k, Wk, bk, p_kh, 1.f,   0, N);
    proj_gemm<<<ggrid, 256>>>(v, Wv, bv, p_vh, 1.f,   0, N);

    attn_mma_kernel<<<dim3(N / 64, HEADS, NSPLIT), 128>>>();
    combine_kernel<<<(HEADS * N) / 128, 128>>>();

    proj_gemm<<<ggrid, 256>>>(p_attn, Wo, bo, out, 1.f, 1, N);
}

// round 4
// speedup vs baseline: 2.7600x; 1.1512x over previous
#include <cuda_runtime.h>
#include <math.h>
#include <stdint.h>

#define N 2048
#define HIDDEN 256
#define HEADS 8
#define DK 32
#define NSPLIT 4
#define KSPAN (N / NSPLIT)

// -------------------- scratch (__device__ globals; no allocs allowed) -----
__device__ float g_bias[N * N];            // 16 MB pair bias
__device__ float g_qh[HEADS * N * DK];     // head-major projected q (scaled)
__device__ float g_kh[HEADS * N * DK];
__device__ float g_vh[HEADS * N * DK];
__device__ float g_attn[N * HIDDEN];       // attention output before O-proj
__device__ float g_coef[4];
// split-K partials
__device__ float g_pm[NSPLIT * HEADS * N];
__device__ float g_pl[NSPLIT * HEADS * N];
__device__ float g_pav[NSPLIT * HEADS * N * DK];

// -------------------- helpers ---------------------------------------------
__device__ __forceinline__ uint32_t f2tf(float f) {
    uint32_t u;
    asm("cvt.rna.tf32.f32 %0, %1;" : "=r"(u) : "f"(f));
    return u;
}

__device__ __forceinline__ void mma_tf32(float& d0, float& d1, float& d2, float& d3,
                                         uint32_t a0, uint32_t a1, uint32_t a2, uint32_t a3,
                                         uint32_t b0, uint32_t b1)
{
    asm volatile("mma.sync.aligned.m16n8k8.row.col.f32.tf32.tf32.f32 "
                 "{%0,%1,%2,%3}, {%4,%5,%6,%7}, {%8,%9}, {%0,%1,%2,%3};"
                 : "+f"(d0), "+f"(d1), "+f"(d2), "+f"(d3)
                 : "r"(a0), "r"(a1), "r"(a2), "r"(a3), "r"(b0), "r"(b1));
}

// -------------------- bias MLP collapse -----------------------------------
__global__ void coef_kernel(const float* __restrict__ Wd1, const float* __restrict__ bd1,
                            const float* __restrict__ Wd2, const float* __restrict__ bd2,
                            const float* __restrict__ Wc1, const float* __restrict__ bc1,
                            const float* __restrict__ Wc2, const float* __restrict__ bc2)
{
    float am = 0.f, al = 0.f, c0 = bd2[0] + bc2[0], cm = 0.f;
    #pragma unroll
    for (int h = 0; h < 16; h++) {
        am += Wd1[h]      * Wd2[h];
        al += Wd1[16 + h] * Wd2[h];
        c0 += bd1[h]      * Wd2[h];
        cm += Wc1[h]      * Wc2[h];
        al += Wc1[16 + h] * Wc2[h];
        c0 += bc1[h]      * Wc2[h];
    }
    g_coef[0] = am; g_coef[1] = cm; g_coef[2] = al; g_coef[3] = c0;
}

__global__ void bias_kernel(const int* __restrict__ label,
                            const float* __restrict__ dist,
                            const float* __restrict__ contact)
{
    const float am = g_coef[0], cm = g_coef[1], al = g_coef[2], c0 = g_coef[3];
    int i = blockIdx.x * blockDim.x + threadIdx.x;
    float4 dm = ((const float4*)dist)[i];
    float4 cv = ((const float4*)contact)[i];
    int4   lb = ((const int4*)label)[i];
    float4 o;
    o.x = fmaf(am, dm.x, fmaf(cm, cv.x, fmaf(al, (float)lb.x, c0)));
    o.y = fmaf(am, dm.y, fmaf(cm, cv.y, fmaf(al, (float)lb.y, c0)));
    o.z = fmaf(am, dm.z, fmaf(cm, cv.z, fmaf(al, (float)lb.z, c0)));
    o.w = fmaf(am, dm.w, fmaf(cm, cv.w, fmaf(al, (float)lb.w, c0)));
    ((float4*)g_bias)[i] = o;
}

// -------------------- tf32 tensor-core projection GEMM --------------------
// [M,256] @ [256,256] + bias. Block 256 thr / 8 warps, tile 64x64,
// warp = 16x32 (1 M-frag x 4 N-frags). K chunks of 32, register prefetch.
// Fragment-major smem: compute does only conflict-free LDS.128/LDS.64 + mma.
__global__ __launch_bounds__(256) void proj_mma(const float* __restrict__ A,
                                                const float* __restrict__ W,
                                                const float* __restrict__ bias,
                                                float* __restrict__ out,
                                                float scale, int mode, int M)
{
    __shared__ uint4 AF[16 * 32];   // 8 KB: frag(mf*4+ks) x lane -> {a0,a1,a2,a3}
    __shared__ uint2 BF[32 * 32];   // 8 KB: frag(nf*4+ks) x lane -> {b0,b1}

    const int t    = threadIdx.x;
    const int lane = t & 31;
    const int w    = t >> 5;
    const int q    = lane & 3;
    const int g    = lane >> 2;
    const int m0   = blockIdx.x * 64;
    const int n0   = blockIdx.y * 64;
    const int mf    = w >> 1;        // warp's M-frag (0..3)
    const int nhalf = w & 1;         // warp's 32-col half

    float acc[4][4];
    #pragma unroll
    for (int j = 0; j < 4; j++)
        #pragma unroll
        for (int e = 0; e < 4; e++) acc[j][e] = 0.f;

    // loader coordinates (2 float4 each for A and B per chunk)
    const int a_m0 = t >> 3,        a_k4_0 = t & 7;          // idx t
    const int a_m1 = (t + 256) >> 3, a_k4_1 = (t + 256) & 7;  // idx t+256
    const int b_k0 = t >> 4,        b_n4_0 = t & 15;
    const int b_k1 = (t + 256) >> 4, b_n4_1 = (t + 256) & 15;

    float4 ra0, ra1, rb0, rb1;
    // prefetch chunk 0
    ra0 = *(const float4*)&A[(size_t)(m0 + a_m0) * 256 + 0 + a_k4_0 * 4];
    ra1 = *(const float4*)&A[(size_t)(m0 + a_m1) * 256 + 0 + a_k4_1 * 4];
    rb0 = *(const float4*)&W[(size_t)(0 + b_k0) * 256 + n0 + b_n4_0 * 4];
    rb1 = *(const float4*)&W[(size_t)(0 + b_k1) * 256 + n0 + b_n4_1 * 4];

    for (int c = 0; c < 8; c++) {
        __syncthreads();   // prior compute done reading smem
        // ---- store regs -> fragment-major smem (with tf32 convert) ----
        {
            // A float4 at (m, k4): ks=k4>>1, hi=k4&1; r=m&15: g_=r&7, ah=r>>3
            #pragma unroll
            for (int p = 0; p < 2; p++) {
                int m  = p ? a_m1 : a_m0;
                int k4 = p ? a_k4_1 : a_k4_0;
                float4 v = p ? ra1 : ra0;
                int frag = (m >> 4) * 4 + (k4 >> 1);
                int idx  = (k4 & 1) * 2 + ((m & 15) >> 3);
                uint32_t* dst = (uint32_t*)&AF[frag * 32 + ((m & 7) * 4)];
                dst[0 * 4 + idx] = f2tf(v.x);
                dst[1 * 4 + idx] = f2tf(v.y);
                dst[2 * 4 + idx] = f2tf(v.z);
                dst[3 * 4 + idx] = f2tf(v.w);
            }
            // B float4 at (k, n4): qq=k&3, hi=(k>>2)&1, ks=k>>3; nf=n4>>1, gb=(n4&1)*4
            #pragma unroll
            for (int p = 0; p < 2; p++) {
                int k  = p ? b_k1 : b_k0;
                int n4 = p ? b_n4_1 : b_n4_0;
                float4 v = p ? rb1 : rb0;
                int frag = (n4 >> 1) * 4 + (k >> 3);
                int hi   = (k >> 2) & 1;
                uint32_t* dst = (uint32_t*)&BF[frag * 32 + (n4 & 1) * 16 + (k & 3)];
                dst[0 * 8 + hi] = f2tf(v.x);
                dst[1 * 8 + hi] = f2tf(v.y);
                dst[2 * 8 + hi] = f2tf(v.z);
                dst[3 * 8 + hi] = f2tf(v.w);
            }
        }
        __syncthreads();

        // ---- prefetch next chunk's globals ----
        if (c < 7) {
            int kt = (c + 1) * 32;
            ra0 = *(const float4*)&A[(size_t)(m0 + a_m0) * 256 + kt + a_k4_0 * 4];
            ra1 = *(const float4*)&A[(size_t)(m0 + a_m1) * 256 + kt + a_k4_1 * 4];
            rb0 = *(const float4*)&W[(size_t)(kt + b_k0) * 256 + n0 + b_n4_0 * 4];
            rb1 = *(const float4*)&W[(size_t)(kt + b_k1) * 256 + n0 + b_n4_1 * 4];
        }

        // ---- compute: 16 mma per warp ----
        #pragma unroll
        for (int ks = 0; ks < 4; ks++) {
            uint4 a = AF[(mf * 4 + ks) * 32 + lane];
            #pragma unroll
            for (int j = 0; j < 4; j++) {
                uint2 b = BF[((nhalf * 4 + j) * 4 + ks) * 32 + lane];
                mma_tf32(acc[j][0], acc[j][1], acc[j][2], acc[j][3],
                         a.x, a.y, a.z, a.w, b.x, b.y);
            }
        }
    }

    // ---- epilogue ----
    const int row0 = m0 + mf * 16 + g;
    #pragma unroll
    for (int j = 0; j < 4; j++) {
        int col = n0 + nhalf * 32 + j * 8 + 2 * q;
        float2 bz = *(const float2*)&bias[col];
        float v00 = acc[j][0] + bz.x, v01 = acc[j][1] + bz.y;   // row0
        float v10 = acc[j][2] + bz.x, v11 = acc[j][3] + bz.y;   // row0+8
        if (mode == 0) {
            v00 *= scale; v01 *= scale; v10 *= scale; v11 *= scale;
            size_t base = (size_t)(col >> 5) * ((size_t)M * 32) + (col & 31);
            *(float2*)&out[base + (size_t)row0 * 32]       = make_float2(v00, v01);
            *(float2*)&out[base + (size_t)(row0 + 8) * 32] = make_float2(v10, v11);
        } else {
            *(float2*)&out[(size_t)row0 * 256 + col]       = make_float2(v00, v01);
            *(float2*)&out[(size_t)(row0 + 8) * 256 + col] = make_float2(v10, v11);
        }
    }
}

// -------------------- tf32 tensor-core flash attention ---------------------
__global__ __launch_bounds__(128) void attn_mma_kernel()
{
    __shared__ uint32_t KB[2048];   // 8 KB
    __shared__ uint32_t VB[2048];   // 8 KB

    const int tid  = threadIdx.x;
    const int lane = tid & 31;
    const int warp = tid >> 5;
    const int q    = lane & 3;
    const int g    = lane >> 2;
    const int h  = blockIdx.y;
    const int z  = blockIdx.z;
    const int q0 = blockIdx.x * 64;
    const int wr0 = warp * 16;
    const int row = q0 + wr0 + g;

    uint32_t qa[4][4];
    const float* qbase = &g_qh[((size_t)h * N + row) * DK];
    #pragma unroll
    for (int s = 0; s < 4; s++) {
        int d = s * 8 + q;
        qa[s][0] = f2tf(qbase[d]);
        qa[s][1] = f2tf(qbase[8 * DK + d]);
        qa[s][2] = f2tf(qbase[d + 4]);
        qa[s][3] = f2tf(qbase[8 * DK + d + 4]);
    }

    float o[4][4];
    #pragma unroll
    for (int n = 0; n < 4; n++)
        #pragma unroll
        for (int e = 0; e < 4; e++) o[n][e] = 0.f;

    float m0 = -INFINITY, m8 = -INFINITY, l0 = 0.f, l8 = 0.f;

    const int l1 = (lane & 0x1c) | (q >> 1);
    const int l2 = l1 + 2;
    const bool odd = (q & 1);

    for (int kb = z * KSPAN; kb < z * KSPAN + KSPAN; kb += 64) {
        __syncthreads();
        {
            const float4* kg = (const float4*)&g_kh[((size_t)h * N + kb) * DK];
            const float4* vg = (const float4*)&g_vh[((size_t)h * N + kb) * DK];
            #pragma unroll
            for (int i = 0; i < 4; i++) {
                int idx = i * 128 + tid;
                float4 kf = kg[idx];
                float4 vf = vg[idx];
                int e   = idx * 4;
                int key = e >> 5;
                int d0  = e & 31;
                {
                    int pb = (d0 >> 3) * 8 + (key & 63) / 8;
                    int bb = (d0 >> 2) & 1;
                    int tb = 4 * (key & 7);
                    uint32_t* dst = &KB[(pb * 32 + tb) * 2 + bb];
                    dst[0 * 2] = f2tf(kf.x);
                    dst[1 * 2] = f2tf(kf.y);
                    dst[2 * 2] = f2tf(kf.z);
                    dst[3 * 2] = f2tf(kf.w);
                }
                {
                    int pb = ((key & 63) / 8) * 4 + (d0 >> 3);
                    int bb = (key >> 2) & 1;
                    int tb = (key & 3);
                    uint32_t* dst = &VB[(pb * 32 + tb + 4 * (d0 & 7)) * 2 + bb];
                    dst[0 * 8] = f2tf(vf.x);
                    dst[1 * 8] = f2tf(vf.y);
                    dst[2 * 8] = f2tf(vf.z);
                    dst[3 * 8] = f2tf(vf.w);
                }
            }
        }
        __syncthreads();

        float s[8][4];
        #pragma unroll
        for (int j = 0; j < 8; j++)
            #pragma unroll
            for (int e = 0; e < 4; e++) s[j][e] = 0.f;

        #pragma unroll
        for (int ks = 0; ks < 4; ks++) {
            #pragma unroll
            for (int j = 0; j < 8; j++) {
                uint2 b = *(const uint2*)&KB[((ks * 8 + j) * 32 + lane) * 2];
                mma_tf32(s[j][0], s[j][1], s[j][2], s[j][3],
                         qa[ks][0], qa[ks][1], qa[ks][2], qa[ks][3], b.x, b.y);
            }
        }

        {
            const float* brow = &g_bias[(size_t)row * N + kb];
            #pragma unroll
            for (int j = 0; j < 8; j++) {
                float2 b0 = *(const float2*)&brow[8 * j + 2 * q];
                float2 b8 = *(const float2*)&brow[(size_t)8 * N + 8 * j + 2 * q];
                s[j][0] += b0.x; s[j][1] += b0.y;
                s[j][2] += b8.x; s[j][3] += b8.y;
            }
        }

        float mx0 = s[0][0], mx8 = s[0][2];
        #pragma unroll
        for (int j = 0; j < 8; j++) {
            mx0 = fmaxf(mx0, fmaxf(s[j][0], s[j][1]));
            mx8 = fmaxf(mx8, fmaxf(s[j][2], s[j][3]));
        }
        mx0 = fmaxf(mx0, __shfl_xor_sync(0xffffffffu, mx0, 1));
        mx0 = fmaxf(mx0, __shfl_xor_sync(0xffffffffu, mx0, 2));
        mx8 = fmaxf(mx8, __shfl_xor_sync(0xffffffffu, mx8, 1));
        mx8 = fmaxf(mx8, __shfl_xor_sync(0xffffffffu, mx8, 2));

        float mn0 = fmaxf(m0, mx0), mn8 = fmaxf(m8, mx8);
        float c0 = __expf(m0 - mn0), c8 = __expf(m8 - mn8);
        m0 = mn0; m8 = mn8;
        l0 *= c0;  l8 *= c8;
        #pragma unroll
        for (int n = 0; n < 4; n++) {
            o[n][0] *= c0; o[n][1] *= c0;
            o[n][2] *= c8; o[n][3] *= c8;
        }

        uint32_t pu[8][4];
        #pragma unroll
        for (int j = 0; j < 8; j++) {
            float p0 = __expf(s[j][0] - m0);
            float p1 = __expf(s[j][1] - m0);
            float p2 = __expf(s[j][2] - m8);
            float p3 = __expf(s[j][3] - m8);
            l0 += p0 + p1;
            l8 += p2 + p3;
            pu[j][0] = f2tf(p0); pu[j][1] = f2tf(p1);
            pu[j][2] = f2tf(p2); pu[j][3] = f2tf(p3);
        }

        #pragma unroll
        for (int j = 0; j < 8; j++) {
            uint32_t x0 = __shfl_sync(0xffffffffu, pu[j][0], l1);
            uint32_t x1 = __shfl_sync(0xffffffffu, pu[j][1], l1);
            uint32_t y0 = __shfl_sync(0xffffffffu, pu[j][2], l1);
            uint32_t y1 = __shfl_sync(0xffffffffu, pu[j][3], l1);
            uint32_t x2 = __shfl_sync(0xffffffffu, pu[j][0], l2);
            uint32_t x3 = __shfl_sync(0xffffffffu, pu[j][1], l2);
            uint32_t y2 = __shfl_sync(0xffffffffu, pu[j][2], l2);
            uint32_t y3 = __shfl_sync(0xffffffffu, pu[j][3], l2);
            uint32_t a0 = odd ? x1 : x0;
            uint32_t a1 = odd ? y1 : y0;
            uint32_t a2 = odd ? x3 : x2;
            uint32_t a3 = odd ? y3 : y2;
            #pragma unroll
            for (int n = 0; n < 4; n++) {
                uint2 b = *(const uint2*)&VB[((j * 4 + n) * 32 + lane) * 2];
                mma_tf32(o[n][0], o[n][1], o[n][2], o[n][3], a0, a1, a2, a3, b.x, b.y);
            }
        }
    }

    l0 += __shfl_xor_sync(0xffffffffu, l0, 1);
    l0 += __shfl_xor_sync(0xffffffffu, l0, 2);
    l8 += __shfl_xor_sync(0xffffffffu, l8, 1);
    l8 += __shfl_xor_sync(0xffffffffu, l8, 2);

    const int rid = (z * HEADS + h) * N + q0 + wr0 + g;
    if (q == 0) {
        g_pm[rid] = m0;     g_pl[rid] = l0;
        g_pm[rid + 8] = m8; g_pl[rid + 8] = l8;
    }
    float* pav0 = &g_pav[(size_t)rid * DK];
    float* pav8 = &g_pav[(size_t)(rid + 8) * DK];
    #pragma unroll
    for (int n = 0; n < 4; n++) {
        *(float2*)&pav0[8 * n + 2 * q] = make_float2(o[n][0], o[n][1]);
        *(float2*)&pav8[8 * n + 2 * q] = make_float2(o[n][2], o[n][3]);
    }
}

// -------------------- split-K combine ------------------------------------
__global__ void combine_kernel()
{
    int idx = blockIdx.x * blockDim.x + threadIdx.x;
    int h = idx >> 11;
    int row = idx & (N - 1);

    float M = -INFINITY;
    #pragma unroll
    for (int s = 0; s < NSPLIT; s++)
        M = fmaxf(M, g_pm[(s * HEADS + h) * N + row]);

    float l = 0.f;
    float4 acc[8];
    #pragma unroll
    for (int w = 0; w < 8; w++) acc[w] = make_float4(0.f, 0.f, 0.f, 0.f);

    #pragma unroll
    for (int s = 0; s < NSPLIT; s++) {
        int rid = (s * HEADS + h) * N + row;
        float wgt = __expf(g_pm[rid] - M);
        l += g_pl[rid] * wgt;
        const float4* pav = (const float4*)&g_pav[(size_t)rid * DK];
        #pragma unroll
        for (int w = 0; w < 8; w++) {
            float4 a = pav[w];
            acc[w].x = fmaf(a.x, wgt, acc[w].x);
            acc[w].y = fmaf(a.y, wgt, acc[w].y);
            acc[w].z = fmaf(a.z, wgt, acc[w].z);
            acc[w].w = fmaf(a.w, wgt, acc[w].w);
        }
    }
    float inv = 1.f / l;
    float* orow = &g_attn[(size_t)row * HIDDEN + h * DK];
    #pragma unroll
    for (int w = 0; w < 8; w++) {
        float4 v = acc[w];
        v.x *= inv; v.y *= inv; v.z *= inv; v.w *= inv;
        ((float4*)orow)[w] = v;
    }
}

// -------------------- launch ------------------------------------------------
extern "C" void kernel_launch(void* const* d_in, const int* in_sizes, int n_in,
                              void* d_out, int out_size)
{
    const int*   label   = (const int*)  d_in[0];
    const float* dist    = (const float*)d_in[1];
    const float* contact = (const float*)d_in[2];
    const float* q       = (const float*)d_in[3];
    const float* k       = (const float*)d_in[4];
    const float* v       = (const float*)d_in[5];
    const float* Wq = (const float*)d_in[6];  const float* bq = (const float*)d_in[7];
    const float* Wk = (const float*)d_in[8];  const float* bk = (const float*)d_in[9];
    const float* Wv = (const float*)d_in[10]; const float* bv = (const float*)d_in[11];
    const float* Wo = (const float*)d_in[12]; const float* bo = (const float*)d_in[13];
    const float* Wd1 = (const float*)d_in[14]; const float* bd1 = (const float*)d_in[15];
    const float* Wd2 = (const float*)d_in[16]; const float* bd2 = (const float*)d_in[17];
    const float* Wc1 = (const float*)d_in[18]; const float* bc1 = (const float*)d_in[19];
    const float* Wc2 = (const float*)d_in[20]; const float* bc2 = (const float*)d_in[21];
    float* out = (float*)d_out;

    float *p_qh, *p_kh, *p_vh, *p_attn;
    cudaGetSymbolAddress((void**)&p_qh,   g_qh);
    cudaGetSymbolAddress((void**)&p_kh,   g_kh);
    cudaGetSymbolAddress((void**)&p_vh,   g_vh);
    cudaGetSymbolAddress((void**)&p_attn, g_attn);

    coef_kernel<<<1, 1>>>(Wd1, bd1, Wd2, bd2, Wc1, bc1, Wc2, bc2);
    bias_kernel<<<(N * N / 4) / 256, 256>>>(label, dist, contact);

    dim3 ggrid(N / 64, HIDDEN / 64);
    const float scale = 1.f / sqrtf((float)DK);
    proj_mma<<<ggrid, 256>>>(q, Wq, bq, p_qh, scale, 0, N);
    proj_mma<<<ggrid, 256>>>(k, Wk, bk, p_kh, 1.f,   0, N);
    proj_mma<<<ggrid, 256>>>(v, Wv, bv, p_vh, 1.f,   0, N);

    attn_mma_kernel<<<dim3(N / 64, HEADS, NSPLIT), 128>>>();
    combine_kernel<<<(HEADS * N) / 128, 128>>>();

    proj_mma<<<ggrid, 256>>>(p_attn, Wo, bo, out, 1.f, 1, N);
}

// round 5
// speedup vs baseline: 3.4843x; 1.2624x over previous
#include <cuda_runtime.h>
#include <math.h>
#include <stdint.h>

#define N 2048
#define HIDDEN 256
#define HEADS 8
#define DK 32
#define NSPLIT 4
#define KSPAN (N / NSPLIT)
#define NCHUNK (N / 64)

// -------------------- scratch (__device__ globals; no allocs allowed) -----
__device__ float g_bias[N * N];            // 16 MB pair bias
__device__ float g_qh[HEADS * N * DK];     // head-major projected q (scaled)
__device__ float g_kh[HEADS * N * DK];
__device__ float g_vh[HEADS * N * DK];
__device__ uint32_t g_kf[HEADS * NCHUNK * 2048];   // fragment-major tf32 K
__device__ uint32_t g_vf[HEADS * NCHUNK * 2048];   // fragment-major tf32 V
__device__ float g_attn[N * HIDDEN];       // attention output before O-proj
__device__ float g_coef[4];
// split-K partials
__device__ float g_pm[NSPLIT * HEADS * N];
__device__ float g_pl[NSPLIT * HEADS * N];
__device__ float g_pav[NSPLIT * HEADS * N * DK];

// -------------------- helpers ---------------------------------------------
__device__ __forceinline__ uint32_t f2tf(float f) {
    uint32_t u;
    asm("cvt.rna.tf32.f32 %0, %1;" : "=r"(u) : "f"(f));
    return u;
}

__device__ __forceinline__ void mma_tf32(float& d0, float& d1, float& d2, float& d3,
                                         uint32_t a0, uint32_t a1, uint32_t a2, uint32_t a3,
                                         uint32_t b0, uint32_t b1)
{
    asm volatile("mma.sync.aligned.m16n8k8.row.col.f32.tf32.tf32.f32 "
                 "{%0,%1,%2,%3}, {%4,%5,%6,%7}, {%8,%9}, {%0,%1,%2,%3};"
                 : "+f"(d0), "+f"(d1), "+f"(d2), "+f"(d3)
                 : "r"(a0), "r"(a1), "r"(a2), "r"(a3), "r"(b0), "r"(b1));
}

// -------------------- bias MLP collapse -----------------------------------
__global__ void coef_kernel(const float* __restrict__ Wd1, const float* __restrict__ bd1,
                            const float* __restrict__ Wd2, const float* __restrict__ bd2,
                            const float* __restrict__ Wc1, const float* __restrict__ bc1,
                            const float* __restrict__ Wc2, const float* __restrict__ bc2)
{
    float am = 0.f, al = 0.f, c0 = bd2[0] + bc2[0], cm = 0.f;
    #pragma unroll
    for (int h = 0; h < 16; h++) {
        am += Wd1[h]      * Wd2[h];
        al += Wd1[16 + h] * Wd2[h];
        c0 += bd1[h]      * Wd2[h];
        cm += Wc1[h]      * Wc2[h];
        al += Wc1[16 + h] * Wc2[h];
        c0 += bc1[h]      * Wc2[h];
    }
    g_coef[0] = am; g_coef[1] = cm; g_coef[2] = al; g_coef[3] = c0;
}

__global__ void bias_kernel(const int* __restrict__ label,
                            const float* __restrict__ dist,
                            const float* __restrict__ contact)
{
    const float am = g_coef[0], cm = g_coef[1], al = g_coef[2], c0 = g_coef[3];
    int i = blockIdx.x * blockDim.x + threadIdx.x;
    float4 dm = ((const float4*)dist)[i];
    float4 cv = ((const float4*)contact)[i];
    int4   lb = ((const int4*)label)[i];
    float4 o;
    o.x = fmaf(am, dm.x, fmaf(cm, cv.x, fmaf(al, (float)lb.x, c0)));
    o.y = fmaf(am, dm.y, fmaf(cm, cv.y, fmaf(al, (float)lb.y, c0)));
    o.z = fmaf(am, dm.z, fmaf(cm, cv.z, fmaf(al, (float)lb.z, c0)));
    o.w = fmaf(am, dm.w, fmaf(cm, cv.w, fmaf(al, (float)lb.w, c0)));
    ((float4*)g_bias)[i] = o;
}

// -------------------- tf32 tensor-core projection GEMM body ----------------
__device__ __forceinline__ void proj_body(const float* __restrict__ A,
                                          const float* __restrict__ W,
                                          const float* __restrict__ bias,
                                          float* __restrict__ out,
                                          float scale, int mode)
{
    __shared__ uint4 AF[16 * 32];   // 8 KB
    __shared__ uint2 BF[32 * 32];   // 8 KB

    const int t    = threadIdx.x;
    const int lane = t & 31;
    const int w    = t >> 5;
    const int q    = lane & 3;
    const int g    = lane >> 2;
    const int m0   = blockIdx.x * 64;
    const int n0   = blockIdx.y * 64;
    const int mf    = w >> 1;
    const int nhalf = w & 1;

    float acc[4][4];
    #pragma unroll
    for (int j = 0; j < 4; j++)
        #pragma unroll
        for (int e = 0; e < 4; e++) acc[j][e] = 0.f;

    const int a_m0 = t >> 3,         a_k4_0 = t & 7;
    const int a_m1 = (t + 256) >> 3, a_k4_1 = (t + 256) & 7;
    const int b_k0 = t >> 4,         b_n4_0 = t & 15;
    const int b_k1 = (t + 256) >> 4, b_n4_1 = (t + 256) & 15;

    float4 ra0, ra1, rb0, rb1;
    ra0 = *(const float4*)&A[(size_t)(m0 + a_m0) * 256 + 0 + a_k4_0 * 4];
    ra1 = *(const float4*)&A[(size_t)(m0 + a_m1) * 256 + 0 + a_k4_1 * 4];
    rb0 = *(const float4*)&W[(size_t)(0 + b_k0) * 256 + n0 + b_n4_0 * 4];
    rb1 = *(const float4*)&W[(size_t)(0 + b_k1) * 256 + n0 + b_n4_1 * 4];

    for (int c = 0; c < 8; c++) {
        __syncthreads();
        {
            #pragma unroll
            for (int p = 0; p < 2; p++) {
                int m  = p ? a_m1 : a_m0;
                int k4 = p ? a_k4_1 : a_k4_0;
                float4 v = p ? ra1 : ra0;
                int frag = (m >> 4) * 4 + (k4 >> 1);
                int idx  = (k4 & 1) * 2 + ((m & 15) >> 3);
                uint32_t* dst = (uint32_t*)&AF[frag * 32 + ((m & 7) * 4)];
                dst[0 * 4 + idx] = f2tf(v.x);
                dst[1 * 4 + idx] = f2tf(v.y);
                dst[2 * 4 + idx] = f2tf(v.z);
                dst[3 * 4 + idx] = f2tf(v.w);
            }
            #pragma unroll
            for (int p = 0; p < 2; p++) {
                int k  = p ? b_k1 : b_k0;
                int n4 = p ? b_n4_1 : b_n4_0;
                float4 v = p ? rb1 : rb0;
                int frag = (n4 >> 1) * 4 + (k >> 3);
                int hi   = (k >> 2) & 1;
                uint32_t* dst = (uint32_t*)&BF[frag * 32 + (n4 & 1) * 16 + (k & 3)];
                dst[0 * 8 + hi] = f2tf(v.x);
                dst[1 * 8 + hi] = f2tf(v.y);
                dst[2 * 8 + hi] = f2tf(v.z);
                dst[3 * 8 + hi] = f2tf(v.w);
            }
        }
        __syncthreads();

        if (c < 7) {
            int kt = (c + 1) * 32;
            ra0 = *(const float4*)&A[(size_t)(m0 + a_m0) * 256 + kt + a_k4_0 * 4];
            ra1 = *(const float4*)&A[(size_t)(m0 + a_m1) * 256 + kt + a_k4_1 * 4];
            rb0 = *(const float4*)&W[(size_t)(kt + b_k0) * 256 + n0 + b_n4_0 * 4];
            rb1 = *(const float4*)&W[(size_t)(kt + b_k1) * 256 + n0 + b_n4_1 * 4];
        }

        #pragma unroll
        for (int ks = 0; ks < 4; ks++) {
            uint4 a = AF[(mf * 4 + ks) * 32 + lane];
            #pragma unroll
            for (int j = 0; j < 4; j++) {
                uint2 b = BF[((nhalf * 4 + j) * 4 + ks) * 32 + lane];
                mma_tf32(acc[j][0], acc[j][1], acc[j][2], acc[j][3],
                         a.x, a.y, a.z, a.w, b.x, b.y);
            }
        }
    }

    const int row0 = m0 + mf * 16 + g;
    #pragma unroll
    for (int j = 0; j < 4; j++) {
        int col = n0 + nhalf * 32 + j * 8 + 2 * q;
        float2 bz = *(const float2*)&bias[col];
        float v00 = acc[j][0] + bz.x, v01 = acc[j][1] + bz.y;
        float v10 = acc[j][2] + bz.x, v11 = acc[j][3] + bz.y;
        if (mode == 0) {
            v00 *= scale; v01 *= scale; v10 *= scale; v11 *= scale;
            size_t base = (size_t)(col >> 5) * ((size_t)N * 32) + (col & 31);
            *(float2*)&out[base + (size_t)row0 * 32]       = make_float2(v00, v01);
            *(float2*)&out[base + (size_t)(row0 + 8) * 32] = make_float2(v10, v11);
        } else {
            *(float2*)&out[(size_t)row0 * 256 + col]       = make_float2(v00, v01);
            *(float2*)&out[(size_t)(row0 + 8) * 256 + col] = make_float2(v10, v11);
        }
    }
}

// fused Q/K/V projections: grid.z selects which
__global__ __launch_bounds__(256) void qkv_proj(const float* __restrict__ q,
                                                const float* __restrict__ k,
                                                const float* __restrict__ v,
                                                const float* __restrict__ Wq,
                                                const float* __restrict__ Wk,
                                                const float* __restrict__ Wv,
                                                const float* __restrict__ bq,
                                                const float* __restrict__ bk,
                                                const float* __restrict__ bv,
                                                float* __restrict__ oq,
                                                float* __restrict__ ok,
                                                float* __restrict__ ov,
                                                float scale)
{
    int z = blockIdx.z;
    const float* A = (z == 0) ? q : (z == 1) ? k : v;
    const float* W = (z == 0) ? Wq : (z == 1) ? Wk : Wv;
    const float* b = (z == 0) ? bq : (z == 1) ? bk : bv;
    float* o       = (z == 0) ? oq : (z == 1) ? ok : ov;
    proj_body(A, W, b, o, (z == 0) ? scale : 1.f, 0);
}

__global__ __launch_bounds__(256) void o_proj(const float* __restrict__ A,
                                              const float* __restrict__ W,
                                              const float* __restrict__ bias,
                                              float* __restrict__ out)
{
    proj_body(A, W, bias, out, 1.f, 1);
}

// -------------------- K/V fragment repack (once, reused 32x by attn) ------
// grid (NCHUNK, HEADS), 128 threads. Converts head-major fp32 K/V into
// fragment-major tf32 global tiles (2048 words per 64-key chunk).
__global__ __launch_bounds__(128) void repack_kernel()
{
    const int tid = threadIdx.x;
    const int ck  = blockIdx.x;
    const int h   = blockIdx.y;

    const float4* kg = (const float4*)&g_kh[((size_t)h * N + ck * 64) * DK];
    const float4* vg = (const float4*)&g_vh[((size_t)h * N + ck * 64) * DK];
    uint32_t* KD = &g_kf[(size_t)(h * NCHUNK + ck) * 2048];
    uint32_t* VD = &g_vf[(size_t)(h * NCHUNK + ck) * 2048];

    #pragma unroll
    for (int i = 0; i < 4; i++) {
        int idx = i * 128 + tid;
        float4 kf = kg[idx];
        float4 vf = vg[idx];
        int e   = idx * 4;
        int key = e >> 5;
        int d0  = e & 31;
        {
            int pb = (d0 >> 3) * 8 + (key & 63) / 8;
            int bb = (d0 >> 2) & 1;
            int tb = 4 * (key & 7);
            uint32_t* dst = &KD[(pb * 32 + tb) * 2 + bb];
            dst[0 * 2] = f2tf(kf.x);
            dst[1 * 2] = f2tf(kf.y);
            dst[2 * 2] = f2tf(kf.z);
            dst[3 * 2] = f2tf(kf.w);
        }
        {
            int pb = ((key & 63) / 8) * 4 + (d0 >> 3);
            int bb = (key >> 2) & 1;
            int tb = (key & 3);
            uint32_t* dst = &VD[(pb * 32 + tb + 4 * (d0 & 7)) * 2 + bb];
            dst[0 * 8] = f2tf(vf.x);
            dst[1 * 8] = f2tf(vf.y);
            dst[2 * 8] = f2tf(vf.z);
            dst[3 * 8] = f2tf(vf.w);
        }
    }
}

// -------------------- tf32 tensor-core flash attention ---------------------
// grid (N/64, HEADS, NSPLIT), 128 threads. Tiles arrive pre-repacked:
// fill is a pure uint4 copy (no cvt, no scatter).
__global__ __launch_bounds__(128) void attn_mma_kernel()
{
    __shared__ uint32_t KB[2048];   // 8 KB
    __shared__ uint32_t VB[2048];   // 8 KB

    const int tid  = threadIdx.x;
    const int lane = tid & 31;
    const int warp = tid >> 5;
    const int q    = lane & 3;
    const int g    = lane >> 2;
    const int h  = blockIdx.y;
    const int z  = blockIdx.z;
    const int q0 = blockIdx.x * 64;
    const int wr0 = warp * 16;
    const int row = q0 + wr0 + g;

    uint32_t qa[4][4];
    const float* qbase = &g_qh[((size_t)h * N + row) * DK];
    #pragma unroll
    for (int s = 0; s < 4; s++) {
        int d = s * 8 + q;
        qa[s][0] = f2tf(qbase[d]);
        qa[s][1] = f2tf(qbase[8 * DK + d]);
        qa[s][2] = f2tf(qbase[d + 4]);
        qa[s][3] = f2tf(qbase[8 * DK + d + 4]);
    }

    float o[4][4];
    #pragma unroll
    for (int n = 0; n < 4; n++)
        #pragma unroll
        for (int e = 0; e < 4; e++) o[n][e] = 0.f;

    float m0 = -INFINITY, m8 = -INFINITY, l0 = 0.f, l8 = 0.f;

    const int l1 = (lane & 0x1c) | (q >> 1);
    const int l2 = l1 + 2;
    const bool odd = (q & 1);

    const int ck0 = (z * KSPAN) / 64;
    for (int cc = 0; cc < KSPAN / 64; cc++) {
        const int ck = ck0 + cc;
        const int kb = ck * 64;
        __syncthreads();
        {   // plain coalesced copy of pre-repacked tiles
            const uint4* ks = (const uint4*)&g_kf[(size_t)(h * NCHUNK + ck) * 2048];
            const uint4* vs = (const uint4*)&g_vf[(size_t)(h * NCHUNK + ck) * 2048];
            #pragma unroll
            for (int i = 0; i < 4; i++) {
                ((uint4*)KB)[i * 128 + tid] = ks[i * 128 + tid];
                ((uint4*)VB)[i * 128 + tid] = vs[i * 128 + tid];
            }
        }
        __syncthreads();

        float s[8][4];
        #pragma unroll
        for (int j = 0; j < 8; j++)
            #pragma unroll
            for (int e = 0; e < 4; e++) s[j][e] = 0.f;

        #pragma unroll
        for (int ks = 0; ks < 4; ks++) {
            #pragma unroll
            for (int j = 0; j < 8; j++) {
                uint2 b = *(const uint2*)&KB[((ks * 8 + j) * 32 + lane) * 2];
                mma_tf32(s[j][0], s[j][1], s[j][2], s[j][3],
                         qa[ks][0], qa[ks][1], qa[ks][2], qa[ks][3], b.x, b.y);
            }
        }

        {
            const float* brow = &g_bias[(size_t)row * N + kb];
            #pragma unroll
            for (int j = 0; j < 8; j++) {
                float2 b0 = *(const float2*)&brow[8 * j + 2 * q];
                float2 b8 = *(const float2*)&brow[(size_t)8 * N + 8 * j + 2 * q];
                s[j][0] += b0.x; s[j][1] += b0.y;
                s[j][2] += b8.x; s[j][3] += b8.y;
            }
        }

        float mx0 = s[0][0], mx8 = s[0][2];
        #pragma unroll
        for (int j = 0; j < 8; j++) {
            mx0 = fmaxf(mx0, fmaxf(s[j][0], s[j][1]));
            mx8 = fmaxf(mx8, fmaxf(s[j][2], s[j][3]));
        }
        mx0 = fmaxf(mx0, __shfl_xor_sync(0xffffffffu, mx0, 1));
        mx0 = fmaxf(mx0, __shfl_xor_sync(0xffffffffu, mx0, 2));
        mx8 = fmaxf(mx8, __shfl_xor_sync(0xffffffffu, mx8, 1));
        mx8 = fmaxf(mx8, __shfl_xor_sync(0xffffffffu, mx8, 2));

        float mn0 = fmaxf(m0, mx0), mn8 = fmaxf(m8, mx8);
        float c0 = __expf(m0 - mn0), c8 = __expf(m8 - mn8);
        m0 = mn0; m8 = mn8;
        l0 *= c0;  l8 *= c8;
        #pragma unroll
        for (int n = 0; n < 4; n++) {
            o[n][0] *= c0; o[n][1] *= c0;
            o[n][2] *= c8; o[n][3] *= c8;
        }

        uint32_t pu[8][4];
        #pragma unroll
        for (int j = 0; j < 8; j++) {
            float p0 = __expf(s[j][0] - m0);
            float p1 = __expf(s[j][1] - m0);
            float p2 = __expf(s[j][2] - m8);
            float p3 = __expf(s[j][3] - m8);
            l0 += p0 + p1;
            l8 += p2 + p3;
            pu[j][0] = f2tf(p0); pu[j][1] = f2tf(p1);
            pu[j][2] = f2tf(p2); pu[j][3] = f2tf(p3);
        }

        #pragma unroll
        for (int j = 0; j < 8; j++) {
            uint32_t x0 = __shfl_sync(0xffffffffu, pu[j][0], l1);
            uint32_t x1 = __shfl_sync(0xffffffffu, pu[j][1], l1);
            uint32_t y0 = __shfl_sync(0xffffffffu, pu[j][2], l1);
            uint32_t y1 = __shfl_sync(0xffffffffu, pu[j][3], l1);
            uint32_t x2 = __shfl_sync(0xffffffffu, pu[j][0], l2);
            uint32_t x3 = __shfl_sync(0xffffffffu, pu[j][1], l2);
            uint32_t y2 = __shfl_sync(0xffffffffu, pu[j][2], l2);
            uint32_t y3 = __shfl_sync(0xffffffffu, pu[j][3], l2);
            uint32_t a0 = odd ? x1 : x0;
            uint32_t a1 = odd ? y1 : y0;
            uint32_t a2 = odd ? x3 : x2;
            uint32_t a3 = odd ? y3 : y2;
            #pragma unroll
            for (int n = 0; n < 4; n++) {
                uint2 b = *(const uint2*)&VB[((j * 4 + n) * 32 + lane) * 2];
                mma_tf32(o[n][0], o[n][1], o[n][2], o[n][3], a0, a1, a2, a3, b.x, b.y);
            }
        }
    }

    l0 += __shfl_xor_sync(0xffffffffu, l0, 1);
    l0 += __shfl_xor_sync(0xffffffffu, l0, 2);
    l8 += __shfl_xor_sync(0xffffffffu, l8, 1);
    l8 += __shfl_xor_sync(0xffffffffu, l8, 2);

    const int rid = (z * HEADS + h) * N + q0 + wr0 + g;
    if (q == 0) {
        g_pm[rid] = m0;     g_pl[rid] = l0;
        g_pm[rid + 8] = m8; g_pl[rid + 8] = l8;
    }
    float* pav0 = &g_pav[(size_t)rid * DK];
    float* pav8 = &g_pav[(size_t)(rid + 8) * DK];
    #pragma unroll
    for (int n = 0; n < 4; n++) {
        *(float2*)&pav0[8 * n + 2 * q] = make_float2(o[n][0], o[n][1]);
        *(float2*)&pav8[8 * n + 2 * q] = make_float2(o[n][2], o[n][3]);
    }
}

// -------------------- split-K combine ------------------------------------
__global__ void combine_kernel()
{
    int idx = blockIdx.x * blockDim.x + threadIdx.x;
    int h = idx >> 11;
    int row = idx & (N - 1);

    float M = -INFINITY;
    #pragma unroll
    for (int s = 0; s < NSPLIT; s++)
        M = fmaxf(M, g_pm[(s * HEADS + h) * N + row]);

    float l = 0.f;
    float4 acc[8];
    #pragma unroll
    for (int w = 0; w < 8; w++) acc[w] = make_float4(0.f, 0.f, 0.f, 0.f);

    #pragma unroll
    for (int s = 0; s < NSPLIT; s++) {
        int rid = (s * HEADS + h) * N + row;
        float wgt = __expf(g_pm[rid] - M);
        l += g_pl[rid] * wgt;
        const float4* pav = (const float4*)&g_pav[(size_t)rid * DK];
        #pragma unroll
        for (int w = 0; w < 8; w++) {
            float4 a = pav[w];
            acc[w].x = fmaf(a.x, wgt, acc[w].x);
            acc[w].y = fmaf(a.y, wgt, acc[w].y);
            acc[w].z = fmaf(a.z, wgt, acc[w].z);
            acc[w].w = fmaf(a.w, wgt, acc[w].w);
        }
    }
    float inv = 1.f / l;
    float* orow = &g_attn[(size_t)row * HIDDEN + h * DK];
    #pragma unroll
    for (int w = 0; w < 8; w++) {
        float4 v = acc[w];
        v.x *= inv; v.y *= inv; v.z *= inv; v.w *= inv;
        ((float4*)orow)[w] = v;
    }
}

// -------------------- launch ------------------------------------------------
extern "C" void kernel_launch(void* const* d_in, const int* in_sizes, int n_in,
                              void* d_out, int out_size)
{
    const int*   label   = (const int*)  d_in[0];
    const float* dist    = (const float*)d_in[1];
    const float* contact = (const float*)d_in[2];
    const float* q       = (const float*)d_in[3];
    const float* k       = (const float*)d_in[4];
    const float* v       = (const float*)d_in[5];
    const float* Wq = (const float*)d_in[6];  const float* bq = (const float*)d_in[7];
    const float* Wk = (const float*)d_in[8];  const float* bk = (const float*)d_in[9];
    const float* Wv = (const float*)d_in[10]; const float* bv = (const float*)d_in[11];
    const float* Wo = (const float*)d_in[12]; const float* bo = (const float*)d_in[13];
    const float* Wd1 = (const float*)d_in[14]; const float* bd1 = (const float*)d_in[15];
    const float* Wd2 = (const float*)d_in[16]; const float* bd2 = (const float*)d_in[17];
    const float* Wc1 = (const float*)d_in[18]; const float* bc1 = (const float*)d_in[19];
    const float* Wc2 = (const float*)d_in[20]; const float* bc2 = (const float*)d_in[21];
    float* out = (float*)d_out;

    float *p_qh, *p_kh, *p_vh, *p_attn;
    cudaGetSymbolAddress((void**)&p_qh,   g_qh);
    cudaGetSymbolAddress((void**)&p_kh,   g_kh);
    cudaGetSymbolAddress((void**)&p_vh,   g_vh);
    cudaGetSymbolAddress((void**)&p_attn, g_attn);

    coef_kernel<<<1, 1>>>(Wd1, bd1, Wd2, bd2, Wc1, bc1, Wc2, bc2);
    bias_kernel<<<(N * N / 4) / 256, 256>>>(label, dist, contact);

    const float scale = 1.f / sqrtf((float)DK);
    qkv_proj<<<dim3(N / 64, HIDDEN / 64, 3), 256>>>(q, k, v, Wq, Wk, Wv,
                                                    bq, bk, bv, p_qh, p_kh, p_vh, scale);
    repack_kernel<<<dim3(NCHUNK, HEADS), 128>>>();

    attn_mma_kernel<<<dim3(N / 64, HEADS, NSPLIT), 128>>>();
    combine_kernel<<<(HEADS * N) / 128, 128>>>();

    o_proj<<<dim3(N / 64, HIDDEN / 64), 256>>>(p_attn, Wo, bo, out);
}

// round 6
// speedup vs baseline: 3.7529x; 1.0771x over previous
#include <cuda_runtime.h>
#include <math.h>
#include <stdint.h>

#define N 2048
#define HIDDEN 256
#define HEADS 8
#define DK 32
#define NSPLIT 4
#define KSPAN (N / NSPLIT)
#define NCHUNK (N / 64)

// -------------------- scratch (__device__ globals; no allocs allowed) -----
__device__ float g_bias[N * N];                    // 16 MB pair bias
__device__ float g_qh[HEADS * N * DK];             // head-major projected q (scaled)
__device__ uint32_t g_kf[HEADS * NCHUNK * 2048];   // fragment-major tf32 K
__device__ uint32_t g_vf[HEADS * NCHUNK * 2048];   // fragment-major tf32 V
__device__ float g_attn[N * HIDDEN];               // attention output before O-proj
__device__ float g_coef[4];
// split-K partials
__device__ float g_pm[NSPLIT * HEADS * N];
__device__ float g_pl[NSPLIT * HEADS * N];
__device__ float g_pav[NSPLIT * HEADS * N * DK];

// -------------------- helpers ---------------------------------------------
__device__ __forceinline__ uint32_t f2tf(float f) {
    uint32_t u;
    asm("cvt.rna.tf32.f32 %0, %1;" : "=r"(u) : "f"(f));
    return u;
}

__device__ __forceinline__ void mma_tf32(float& d0, float& d1, float& d2, float& d3,
                                         uint32_t a0, uint32_t a1, uint32_t a2, uint32_t a3,
                                         uint32_t b0, uint32_t b1)
{
    asm volatile("mma.sync.aligned.m16n8k8.row.col.f32.tf32.tf32.f32 "
                 "{%0,%1,%2,%3}, {%4,%5,%6,%7}, {%8,%9}, {%0,%1,%2,%3};"
                 : "+f"(d0), "+f"(d1), "+f"(d2), "+f"(d3)
                 : "r"(a0), "r"(a1), "r"(a2), "r"(a3), "r"(b0), "r"(b1));
}

__device__ __forceinline__ void cp16(uint32_t smem_dst, const void* gsrc) {
    asm volatile("cp.async.cg.shared.global [%0], [%1], 16;"
                 :: "r"(smem_dst), "l"(gsrc));
}

// fragment-major addressing (must match attn's smem fragment layout)
__device__ __forceinline__ int kaddr(int key, int d) {
    return ((d >> 3) * 8 + (key >> 3)) * 64 + (4 * (key & 7) + (d & 3)) * 2 + ((d >> 2) & 1);
}
__device__ __forceinline__ int vaddr(int key, int d) {
    return ((key >> 3) * 4 + (d >> 3)) * 64 + ((key & 3) + 4 * (d & 7)) * 2 + ((key >> 2) & 1);
}

// -------------------- bias MLP collapse -----------------------------------
__global__ void coef_kernel(const float* __restrict__ Wd1, const float* __restrict__ bd1,
                            const float* __restrict__ Wd2, const float* __restrict__ bd2,
                            const float* __restrict__ Wc1, const float* __restrict__ bc1,
                            const float* __restrict__ Wc2, const float* __restrict__ bc2)
{
    float am = 0.f, al = 0.f, c0 = bd2[0] + bc2[0], cm = 0.f;
    #pragma unroll
    for (int h = 0; h < 16; h++) {
        am += Wd1[h]      * Wd2[h];
        al += Wd1[16 + h] * Wd2[h];
        c0 += bd1[h]      * Wd2[h];
        cm += Wc1[h]      * Wc2[h];
        al += Wc1[16 + h] * Wc2[h];
        c0 += bc1[h]      * Wc2[h];
    }
    g_coef[0] = am; g_coef[1] = cm; g_coef[2] = al; g_coef[3] = c0;
}

__global__ void bias_kernel(const int* __restrict__ label,
                            const float* __restrict__ dist,
                            const float* __restrict__ contact)
{
    const float am = g_coef[0], cm = g_coef[1], al = g_coef[2], c0 = g_coef[3];
    int i = blockIdx.x * blockDim.x + threadIdx.x;
    float4 dm = ((const float4*)dist)[i];
    float4 cv = ((const float4*)contact)[i];
    int4   lb = ((const int4*)label)[i];
    float4 o;
    o.x = fmaf(am, dm.x, fmaf(cm, cv.x, fmaf(al, (float)lb.x, c0)));
    o.y = fmaf(am, dm.y, fmaf(cm, cv.y, fmaf(al, (float)lb.y, c0)));
    o.z = fmaf(am, dm.z, fmaf(cm, cv.z, fmaf(al, (float)lb.z, c0)));
    o.w = fmaf(am, dm.w, fmaf(cm, cv.w, fmaf(al, (float)lb.w, c0)));
    ((float4*)g_bias)[i] = o;
}

// -------------------- tf32 tensor-core projection GEMM body ----------------
// mode 0: head-major scaled (Q)   mode 1: row-major (O output)
// mode 2: K fragment-major tf32   mode 3: V fragment-major tf32
__device__ __forceinline__ void proj_body(const float* __restrict__ A,
                                          const float* __restrict__ W,
                                          const float* __restrict__ bias,
                                          float* __restrict__ out,
                                          float scale, int mode)
{
    __shared__ uint4 AF[16 * 32];   // 8 KB
    __shared__ uint2 BF[32 * 32];   // 8 KB

    const int t    = threadIdx.x;
    const int lane = t & 31;
    const int w    = t >> 5;
    const int q    = lane & 3;
    const int g    = lane >> 2;
    const int m0   = blockIdx.x * 64;
    const int n0   = blockIdx.y * 64;
    const int mf    = w >> 1;
    const int nhalf = w & 1;

    float acc[4][4];
    #pragma unroll
    for (int j = 0; j < 4; j++)
        #pragma unroll
        for (int e = 0; e < 4; e++) acc[j][e] = 0.f;

    const int a_m0 = t >> 3,         a_k4_0 = t & 7;
    const int a_m1 = (t + 256) >> 3, a_k4_1 = (t + 256) & 7;
    const int b_k0 = t >> 4,         b_n4_0 = t & 15;
    const int b_k1 = (t + 256) >> 4, b_n4_1 = (t + 256) & 15;

    float4 ra0, ra1, rb0, rb1;
    ra0 = *(const float4*)&A[(size_t)(m0 + a_m0) * 256 + 0 + a_k4_0 * 4];
    ra1 = *(const float4*)&A[(size_t)(m0 + a_m1) * 256 + 0 + a_k4_1 * 4];
    rb0 = *(const float4*)&W[(size_t)(0 + b_k0) * 256 + n0 + b_n4_0 * 4];
    rb1 = *(const float4*)&W[(size_t)(0 + b_k1) * 256 + n0 + b_n4_1 * 4];

    for (int c = 0; c < 8; c++) {
        __syncthreads();
        {
            #pragma unroll
            for (int p = 0; p < 2; p++) {
                int m  = p ? a_m1 : a_m0;
                int k4 = p ? a_k4_1 : a_k4_0;
                float4 v = p ? ra1 : ra0;
                int frag = (m >> 4) * 4 + (k4 >> 1);
                int idx  = (k4 & 1) * 2 + ((m & 15) >> 3);
                uint32_t* dst = (uint32_t*)&AF[frag * 32 + ((m & 7) * 4)];
                dst[0 * 4 + idx] = f2tf(v.x);
                dst[1 * 4 + idx] = f2tf(v.y);
                dst[2 * 4 + idx] = f2tf(v.z);
                dst[3 * 4 + idx] = f2tf(v.w);
            }
            #pragma unroll
            for (int p = 0; p < 2; p++) {
                int k  = p ? b_k1 : b_k0;
                int n4 = p ? b_n4_1 : b_n4_0;
                float4 v = p ? rb1 : rb0;
                int frag = (n4 >> 1) * 4 + (k >> 3);
                int hi   = (k >> 2) & 1;
                uint32_t* dst = (uint32_t*)&BF[frag * 32 + (n4 & 1) * 16 + (k & 3)];
                dst[0 * 8 + hi] = f2tf(v.x);
                dst[1 * 8 + hi] = f2tf(v.y);
                dst[2 * 8 + hi] = f2tf(v.z);
                dst[3 * 8 + hi] = f2tf(v.w);
            }
        }
        __syncthreads();

        if (c < 7) {
            int kt = (c + 1) * 32;
            ra0 = *(const float4*)&A[(size_t)(m0 + a_m0) * 256 + kt + a_k4_0 * 4];
            ra1 = *(const float4*)&A[(size_t)(m0 + a_m1) * 256 + kt + a_k4_1 * 4];
            rb0 = *(const float4*)&W[(size_t)(kt + b_k0) * 256 + n0 + b_n4_0 * 4];
            rb1 = *(const float4*)&W[(size_t)(kt + b_k1) * 256 + n0 + b_n4_1 * 4];
        }

        #pragma unroll
        for (int ks = 0; ks < 4; ks++) {
            uint4 a = AF[(mf * 4 + ks) * 32 + lane];
            #pragma unroll
            for (int j = 0; j < 4; j++) {
                uint2 b = BF[((nhalf * 4 + j) * 4 + ks) * 32 + lane];
                mma_tf32(acc[j][0], acc[j][1], acc[j][2], acc[j][3],
                         a.x, a.y, a.z, a.w, b.x, b.y);
            }
        }
    }

    const int row0 = m0 + mf * 16 + g;
    const int key0 = mf * 16 + g;       // key index within 64-chunk (modes 2/3)
    const int ck   = m0 >> 6;
    #pragma unroll
    for (int j = 0; j < 4; j++) {
        int col = n0 + nhalf * 32 + j * 8 + 2 * q;
        float2 bz = *(const float2*)&bias[col];
        float v00 = acc[j][0] + bz.x, v01 = acc[j][1] + bz.y;
        float v10 = acc[j][2] + bz.x, v11 = acc[j][3] + bz.y;
        if (mode == 0) {
            v00 *= scale; v01 *= scale; v10 *= scale; v11 *= scale;
            size_t base = (size_t)(col >> 5) * ((size_t)N * 32) + (col & 31);
            *(float2*)&out[base + (size_t)row0 * 32]       = make_float2(v00, v01);
            *(float2*)&out[base + (size_t)(row0 + 8) * 32] = make_float2(v10, v11);
        } else if (mode == 1) {
            *(float2*)&out[(size_t)row0 * 256 + col]       = make_float2(v00, v01);
            *(float2*)&out[(size_t)(row0 + 8) * 256 + col] = make_float2(v10, v11);
        } else {
            int hh = col >> 5, dd = col & 31;
            size_t base = ((size_t)hh * NCHUNK + ck) * 2048;
            if (mode == 2) {
                uint32_t* KD = &g_kf[base];
                KD[kaddr(key0,     dd)]     = f2tf(v00);
                KD[kaddr(key0,     dd + 1)] = f2tf(v01);
                KD[kaddr(key0 + 8, dd)]     = f2tf(v10);
                KD[kaddr(key0 + 8, dd + 1)] = f2tf(v11);
            } else {
                uint32_t* VD = &g_vf[base];
                VD[vaddr(key0,     dd)]     = f2tf(v00);
                VD[vaddr(key0,     dd + 1)] = f2tf(v01);
                VD[vaddr(key0 + 8, dd)]     = f2tf(v10);
                VD[vaddr(key0 + 8, dd + 1)] = f2tf(v11);
            }
        }
    }
}

// fused Q/K/V projections: grid.z selects which; K/V write fragments directly
__global__ __launch_bounds__(256) void qkv_proj(const float* __restrict__ q,
                                                const float* __restrict__ k,
                                                const float* __restrict__ v,
                                                const float* __restrict__ Wq,
                                                const float* __restrict__ Wk,
                                                const float* __restrict__ Wv,
                                                const float* __restrict__ bq,
                                                const float* __restrict__ bk,
                                                const float* __restrict__ bv,
                                                float* __restrict__ oq,
                                                float scale)
{
    int z = blockIdx.z;
    if (z == 0)      proj_body(q, Wq, bq, oq,      scale, 0);
    else if (z == 1) proj_body(k, Wk, bk, nullptr, 1.f,   2);
    else             proj_body(v, Wv, bv, nullptr, 1.f,   3);
}

__global__ __launch_bounds__(256) void o_proj(const float* __restrict__ A,
                                              const float* __restrict__ W,
                                              const float* __restrict__ bias,
                                              float* __restrict__ out)
{
    proj_body(A, W, bias, out, 1.f, 1);
}

// -------------------- tf32 tensor-core flash attention ---------------------
// grid (N/64, HEADS, NSPLIT), 128 threads. cp.async double-buffered K/V,
// bias prefetched to registers before the tile wait.
__global__ __launch_bounds__(128) void attn_mma_kernel()
{
    __shared__ uint32_t KB[2][2048];   // 2 x 8 KB
    __shared__ uint32_t VB[2][2048];

    const int tid  = threadIdx.x;
    const int lane = tid & 31;
    const int warp = tid >> 5;
    const int q    = lane & 3;
    const int g    = lane >> 2;
    const int h  = blockIdx.y;
    const int z  = blockIdx.z;
    const int q0 = blockIdx.x * 64;
    const int wr0 = warp * 16;
    const int row = q0 + wr0 + g;

    uint32_t qa[4][4];
    const float* qbase = &g_qh[((size_t)h * N + row) * DK];
    #pragma unroll
    for (int s = 0; s < 4; s++) {
        int d = s * 8 + q;
        qa[s][0] = f2tf(qbase[d]);
        qa[s][1] = f2tf(qbase[8 * DK + d]);
        qa[s][2] = f2tf(qbase[d + 4]);
        qa[s][3] = f2tf(qbase[8 * DK + d + 4]);
    }

    float o[4][4];
    #pragma unroll
    for (int n = 0; n < 4; n++)
        #pragma unroll
        for (int e = 0; e < 4; e++) o[n][e] = 0.f;

    float m0 = -INFINITY, m8 = -INFINITY, l0 = 0.f, l8 = 0.f;

    const int l1 = (lane & 0x1c) | (q >> 1);
    const int l2 = l1 + 2;
    const bool odd = (q & 1);

    const int ck0 = (z * KSPAN) / 64;
    const int nch = KSPAN / 64;

    // prologue: fill buffer 0 with chunk ck0
    {
        const uint4* ks = (const uint4*)&g_kf[(size_t)(h * NCHUNK + ck0) * 2048];
        const uint4* vs = (const uint4*)&g_vf[(size_t)(h * NCHUNK + ck0) * 2048];
        #pragma unroll
        for (int i = 0; i < 4; i++) {
            int idx = i * 128 + tid;
            cp16((uint32_t)__cvta_generic_to_shared(&KB[0][idx * 4]), ks + idx);
            cp16((uint32_t)__cvta_generic_to_shared(&VB[0][idx * 4]), vs + idx);
        }
        asm volatile("cp.async.commit_group;");
    }

    for (int cc = 0; cc < nch; cc++) {
        const int cur = cc & 1;
        const int kb = (ck0 + cc) * 64;

        // prefetch bias into registers (overlaps with cp.async wait + mma)
        float2 bb0[8], bb8[8];
        {
            const float* brow = &g_bias[(size_t)row * N + kb];
            #pragma unroll
            for (int j = 0; j < 8; j++) {
                bb0[j] = *(const float2*)&brow[8 * j + 2 * q];
                bb8[j] = *(const float2*)&brow[(size_t)8 * N + 8 * j + 2 * q];
            }
        }

        // issue next chunk into the other buffer, then wait for current
        if (cc + 1 < nch) {
            const int nxt = ck0 + cc + 1;
            const uint4* ks = (const uint4*)&g_kf[(size_t)(h * NCHUNK + nxt) * 2048];
            const uint4* vs = (const uint4*)&g_vf[(size_t)(h * NCHUNK + nxt) * 2048];
            #pragma unroll
            for (int i = 0; i < 4; i++) {
                int idx = i * 128 + tid;
                cp16((uint32_t)__cvta_generic_to_shared(&KB[1 - cur][idx * 4]), ks + idx);
                cp16((uint32_t)__cvta_generic_to_shared(&VB[1 - cur][idx * 4]), vs + idx);
            }
            asm volatile("cp.async.commit_group;");
            asm volatile("cp.async.wait_group 1;");
        } else {
            asm volatile("cp.async.wait_group 0;");
        }
        __syncthreads();

        const uint32_t* KBc = KB[cur];
        const uint32_t* VBc = VB[cur];

        float s[8][4];
        #pragma unroll
        for (int j = 0; j < 8; j++)
            #pragma unroll
            for (int e = 0; e < 4; e++) s[j][e] = 0.f;

        #pragma unroll
        for (int ks = 0; ks < 4; ks++) {
            #pragma unroll
            for (int j = 0; j < 8; j++) {
                uint2 b = *(const uint2*)&KBc[((ks * 8 + j) * 32 + lane) * 2];
                mma_tf32(s[j][0], s[j][1], s[j][2], s[j][3],
                         qa[ks][0], qa[ks][1], qa[ks][2], qa[ks][3], b.x, b.y);
            }
        }

        #pragma unroll
        for (int j = 0; j < 8; j++) {
            s[j][0] += bb0[j].x; s[j][1] += bb0[j].y;
            s[j][2] += bb8[j].x; s[j][3] += bb8[j].y;
        }

        float mx0 = s[0][0], mx8 = s[0][2];
        #pragma unroll
        for (int j = 0; j < 8; j++) {
            mx0 = fmaxf(mx0, fmaxf(s[j][0], s[j][1]));
            mx8 = fmaxf(mx8, fmaxf(s[j][2], s[j][3]));
        }
        mx0 = fmaxf(mx0, __shfl_xor_sync(0xffffffffu, mx0, 1));
        mx0 = fmaxf(mx0, __shfl_xor_sync(0xffffffffu, mx0, 2));
        mx8 = fmaxf(mx8, __shfl_xor_sync(0xffffffffu, mx8, 1));
        mx8 = fmaxf(mx8, __shfl_xor_sync(0xffffffffu, mx8, 2));

        float mn0 = fmaxf(m0, mx0), mn8 = fmaxf(m8, mx8);
        float c0 = __expf(m0 - mn0), c8 = __expf(m8 - mn8);
        m0 = mn0; m8 = mn8;
        l0 *= c0;  l8 *= c8;
        #pragma unroll
        for (int n = 0; n < 4; n++) {
            o[n][0] *= c0; o[n][1] *= c0;
            o[n][2] *= c8; o[n][3] *= c8;
        }

        uint32_t pu[8][4];
        #pragma unroll
        for (int j = 0; j < 8; j++) {
            float p0 = __expf(s[j][0] - m0);
            float p1 = __expf(s[j][1] - m0);
            float p2 = __expf(s[j][2] - m8);
            float p3 = __expf(s[j][3] - m8);
            l0 += p0 + p1;
            l8 += p2 + p3;
            pu[j][0] = f2tf(p0); pu[j][1] = f2tf(p1);
            pu[j][2] = f2tf(p2); pu[j][3] = f2tf(p3);
        }

        #pragma unroll
        for (int j = 0; j < 8; j++) {
            uint32_t x0 = __shfl_sync(0xffffffffu, pu[j][0], l1);
            uint32_t x1 = __shfl_sync(0xffffffffu, pu[j][1], l1);
            uint32_t y0 = __shfl_sync(0xffffffffu, pu[j][2], l1);
            uint32_t y1 = __shfl_sync(0xffffffffu, pu[j][3], l1);
            uint32_t x2 = __shfl_sync(0xffffffffu, pu[j][0], l2);
            uint32_t x3 = __shfl_sync(0xffffffffu, pu[j][1], l2);
            uint32_t y2 = __shfl_sync(0xffffffffu, pu[j][2], l2);
            uint32_t y3 = __shfl_sync(0xffffffffu, pu[j][3], l2);
            uint32_t a0 = odd ? x1 : x0;
            uint32_t a1 = odd ? y1 : y0;
            uint32_t a2 = odd ? x3 : x2;
            uint32_t a3 = odd ? y3 : y2;
            #pragma unroll
            for (int n = 0; n < 4; n++) {
                uint2 b = *(const uint2*)&VBc[((j * 4 + n) * 32 + lane) * 2];
                mma_tf32(o[n][0], o[n][1], o[n][2], o[n][3], a0, a1, a2, a3, b.x, b.y);
            }
        }
        __syncthreads();   // all reads of buf[cur] done before it is refilled
    }

    l0 += __shfl_xor_sync(0xffffffffu, l0, 1);
    l0 += __shfl_xor_sync(0xffffffffu, l0, 2);
    l8 += __shfl_xor_sync(0xffffffffu, l8, 1);
    l8 += __shfl_xor_sync(0xffffffffu, l8, 2);

    const int rid = (z * HEADS + h) * N + q0 + wr0 + g;
    if (q == 0) {
        g_pm[rid] = m0;     g_pl[rid] = l0;
        g_pm[rid + 8] = m8; g_pl[rid + 8] = l8;
    }
    float* pav0 = &g_pav[(size_t)rid * DK];
    float* pav8 = &g_pav[(size_t)(rid + 8) * DK];
    #pragma unroll
    for (int n = 0; n < 4; n++) {
        *(float2*)&pav0[8 * n + 2 * q] = make_float2(o[n][0], o[n][1]);
        *(float2*)&pav8[8 * n + 2 * q] = make_float2(o[n][2], o[n][3]);
    }
}

// -------------------- split-K combine ------------------------------------
__global__ void combine_kernel()
{
    int idx = blockIdx.x * blockDim.x + threadIdx.x;
    int h = idx >> 11;
    int row = idx & (N - 1);

    float M = -INFINITY;
    #pragma unroll
    for (int s = 0; s < NSPLIT; s++)
        M = fmaxf(M, g_pm[(s * HEADS + h) * N + row]);

    float l = 0.f;
    float4 acc[8];
    #pragma unroll
    for (int w = 0; w < 8; w++) acc[w] = make_float4(0.f, 0.f, 0.f, 0.f);

    #pragma unroll
    for (int s = 0; s < NSPLIT; s++) {
        int rid = (s * HEADS + h) * N + row;
        float wgt = __expf(g_pm[rid] - M);
        l += g_pl[rid] * wgt;
        const float4* pav = (const float4*)&g_pav[(size_t)rid * DK];
        #pragma unroll
        for (int w = 0; w < 8; w++) {
            float4 a = pav[w];
            acc[w].x = fmaf(a.x, wgt, acc[w].x);
            acc[w].y = fmaf(a.y, wgt, acc[w].y);
            acc[w].z = fmaf(a.z, wgt, acc[w].z);
            acc[w].w = fmaf(a.w, wgt, acc[w].w);
        }
    }
    float inv = 1.f / l;
    float* orow = &g_attn[(size_t)row * HIDDEN + h * DK];
    #pragma unroll
    for (int w = 0; w < 8; w++) {
        float4 v = acc[w];
        v.x *= inv; v.y *= inv; v.z *= inv; v.w *= inv;
        ((float4*)orow)[w] = v;
    }
}

// -------------------- launch ------------------------------------------------
extern "C" void kernel_launch(void* const* d_in, const int* in_sizes, int n_in,
                              void* d_out, int out_size)
{
    const int*   label   = (const int*)  d_in[0];
    const float* dist    = (const float*)d_in[1];
    const float* contact = (const float*)d_in[2];
    const float* q       = (const float*)d_in[3];
    const float* k       = (const float*)d_in[4];
    const float* v       = (const float*)d_in[5];
    const float* Wq = (const float*)d_in[6];  const float* bq = (const float*)d_in[7];
    const float* Wk = (const float*)d_in[8];  const float* bk = (const float*)d_in[9];
    const float* Wv = (const float*)d_in[10]; const float* bv = (const float*)d_in[11];
    const float* Wo = (const float*)d_in[12]; const float* bo = (const float*)d_in[13];
    const float* Wd1 = (const float*)d_in[14]; const float* bd1 = (const float*)d_in[15];
    const float* Wd2 = (const float*)d_in[16]; const float* bd2 = (const float*)d_in[17];
    const float* Wc1 = (const float*)d_in[18]; const float* bc1 = (const float*)d_in[19];
    const float* Wc2 = (const float*)d_in[20]; const float* bc2 = (const float*)d_in[21];
    float* out = (float*)d_out;

    float *p_qh, *p_attn;
    cudaGetSymbolAddress((void**)&p_qh,   g_qh);
    cudaGetSymbolAddress((void**)&p_attn, g_attn);

    coef_kernel<<<1, 1>>>(Wd1, bd1, Wd2, bd2, Wc1, bc1, Wc2, bc2);
    bias_kernel<<<(N * N / 4) / 256, 256>>>(label, dist, contact);

    const float scale = 1.f / sqrtf((float)DK);
    qkv_proj<<<dim3(N / 64, HIDDEN / 64, 3), 256>>>(q, k, v, Wq, Wk, Wv,
                                                    bq, bk, bv, p_qh, scale);

    attn_mma_kernel<<<dim3(N / 64, HEADS, NSPLIT), 128>>>();
    combine_kernel<<<(HEADS * N) / 128, 128>>>();

    o_proj<<<dim3(N / 64, HIDDEN / 64), 256>>>(p_attn, Wo, bo, out);
}

// round 7
// speedup vs baseline: 4.5420x; 1.2102x over previous
#include <cuda_runtime.h>
#include <cuda_fp16.h>
#include <math.h>
#include <stdint.h>

#define N 2048
#define HIDDEN 256
#define HEADS 8
#define DK 32
#define NSPLIT 4
#define KSPAN (N / NSPLIT)
#define NCHUNK (N / 64)

// -------------------- scratch (__device__ globals; no allocs allowed) -----
__device__ float g_bias[N * N];                    // 16 MB pair bias
__device__ float g_qh[HEADS * N * DK];             // head-major projected q (scaled)
__device__ uint32_t g_kf[HEADS * NCHUNK * 1024];   // fragment-major fp16 K (m16n8k16 B)
__device__ uint32_t g_vf[HEADS * NCHUNK * 1024];   // fragment-major fp16 V (m16n8k16 B)
__device__ float g_attn[N * HIDDEN];               // attention output before O-proj
__device__ float g_coef[4];
// split-K partials
__device__ float g_pm[NSPLIT * HEADS * N];
__device__ float g_pl[NSPLIT * HEADS * N];
__device__ float g_pav[NSPLIT * HEADS * N * DK];

// -------------------- helpers ---------------------------------------------
__device__ __forceinline__ uint32_t f2tf(float f) {
    uint32_t u;
    asm("cvt.rna.tf32.f32 %0, %1;" : "=r"(u) : "f"(f));
    return u;
}

__device__ __forceinline__ uint32_t packh2(float lo, float hi) {
    __half2 h = __floats2half2_rn(lo, hi);
    return *reinterpret_cast<uint32_t*>(&h);
}

__device__ __forceinline__ void mma_tf32(float& d0, float& d1, float& d2, float& d3,
                                         uint32_t a0, uint32_t a1, uint32_t a2, uint32_t a3,
                                         uint32_t b0, uint32_t b1)
{
    asm volatile("mma.sync.aligned.m16n8k8.row.col.f32.tf32.tf32.f32 "
                 "{%0,%1,%2,%3}, {%4,%5,%6,%7}, {%8,%9}, {%0,%1,%2,%3};"
                 : "+f"(d0), "+f"(d1), "+f"(d2), "+f"(d3)
                 : "r"(a0), "r"(a1), "r"(a2), "r"(a3), "r"(b0), "r"(b1));
}

__device__ __forceinline__ void mma_f16(float& d0, float& d1, float& d2, float& d3,
                                        uint32_t a0, uint32_t a1, uint32_t a2, uint32_t a3,
                                        uint32_t b0, uint32_t b1)
{
    asm volatile("mma.sync.aligned.m16n8k16.row.col.f32.f16.f16.f32 "
                 "{%0,%1,%2,%3}, {%4,%5,%6,%7}, {%8,%9}, {%0,%1,%2,%3};"
                 : "+f"(d0), "+f"(d1), "+f"(d2), "+f"(d3)
                 : "r"(a0), "r"(a1), "r"(a2), "r"(a3), "r"(b0), "r"(b1));
}

__device__ __forceinline__ void cp16(uint32_t smem_dst, const void* gsrc) {
    asm volatile("cp.async.cg.shared.global [%0], [%1], 16;"
                 :: "r"(smem_dst), "l"(gsrc));
}

// K fragment word index (fp16x2 packed over d-pairs): B-frag of m16n8k16
// frag = (d/16)*8 + key/8 ; lane = (key%8)*4 + (d%8)/2 ; reg = (d%16)/8
__device__ __forceinline__ int kaddr16(int key, int d) {
    return ((d >> 4) * 8 + (key >> 3)) * 64 + ((key & 7) * 4 + ((d & 7) >> 1)) * 2 + ((d >> 3) & 1);
}
// V fragment half index (fp16x2 packed over key-pairs)
// frag = (key/16)*4 + d/8 ; lane = (d%8)*4 + (key%8)/2 ; reg = (key%16)/8 ; half = key%2
__device__ __forceinline__ int vaddr16h(int key, int d) {
    return ((((key >> 4) * 4 + (d >> 3)) * 32 + (d & 7) * 4 + ((key & 7) >> 1)) * 2
            + ((key >> 3) & 1)) * 2 + (key & 1);
}

// -------------------- bias MLP collapse -----------------------------------
__global__ void coef_kernel(const float* __restrict__ Wd1, const float* __restrict__ bd1,
                            const float* __restrict__ Wd2, const float* __restrict__ bd2,
                            const float* __restrict__ Wc1, const float* __restrict__ bc1,
                            const float* __restrict__ Wc2, const float* __restrict__ bc2)
{
    float am = 0.f, al = 0.f, c0 = bd2[0] + bc2[0], cm = 0.f;
    #pragma unroll
    for (int h = 0; h < 16; h++) {
        am += Wd1[h]      * Wd2[h];
        al += Wd1[16 + h] * Wd2[h];
        c0 += bd1[h]      * Wd2[h];
        cm += Wc1[h]      * Wc2[h];
        al += Wc1[16 + h] * Wc2[h];
        c0 += bc1[h]      * Wc2[h];
    }
    g_coef[0] = am; g_coef[1] = cm; g_coef[2] = al; g_coef[3] = c0;
}

__global__ void bias_kernel(const int* __restrict__ label,
                            const float* __restrict__ dist,
                            const float* __restrict__ contact)
{
    const float am = g_coef[0], cm = g_coef[1], al = g_coef[2], c0 = g_coef[3];
    int i = blockIdx.x * blockDim.x + threadIdx.x;
    float4 dm = ((const float4*)dist)[i];
    float4 cv = ((const float4*)contact)[i];
    int4   lb = ((const int4*)label)[i];
    float4 o;
    o.x = fmaf(am, dm.x, fmaf(cm, cv.x, fmaf(al, (float)lb.x, c0)));
    o.y = fmaf(am, dm.y, fmaf(cm, cv.y, fmaf(al, (float)lb.y, c0)));
    o.z = fmaf(am, dm.z, fmaf(cm, cv.z, fmaf(al, (float)lb.z, c0)));
    o.w = fmaf(am, dm.w, fmaf(cm, cv.w, fmaf(al, (float)lb.w, c0)));
    ((float4*)g_bias)[i] = o;
}

// -------------------- tf32 tensor-core projection GEMM body ----------------
// mode 0: head-major scaled (Q)   mode 1: row-major (O output)
// mode 2: K fp16 fragment-major   mode 3: V fp16 fragment-major
__device__ __forceinline__ void proj_body(const float* __restrict__ A,
                                          const float* __restrict__ W,
                                          const float* __restrict__ bias,
                                          float* __restrict__ out,
                                          float scale, int mode)
{
    __shared__ uint4 AF[16 * 32];   // 8 KB
    __shared__ uint2 BF[32 * 32];   // 8 KB

    const int t    = threadIdx.x;
    const int lane = t & 31;
    const int w    = t >> 5;
    const int q    = lane & 3;
    const int g    = lane >> 2;
    const int m0   = blockIdx.x * 64;
    const int n0   = blockIdx.y * 64;
    const int mf    = w >> 1;
    const int nhalf = w & 1;

    float acc[4][4];
    #pragma unroll
    for (int j = 0; j < 4; j++)
        #pragma unroll
        for (int e = 0; e < 4; e++) acc[j][e] = 0.f;

    const int a_m0 = t >> 3,         a_k4_0 = t & 7;
    const int a_m1 = (t + 256) >> 3, a_k4_1 = (t + 256) & 7;
    const int b_k0 = t >> 4,         b_n4_0 = t & 15;
    const int b_k1 = (t + 256) >> 4, b_n4_1 = (t + 256) & 15;

    float4 ra0, ra1, rb0, rb1;
    ra0 = *(const float4*)&A[(size_t)(m0 + a_m0) * 256 + 0 + a_k4_0 * 4];
    ra1 = *(const float4*)&A[(size_t)(m0 + a_m1) * 256 + 0 + a_k4_1 * 4];
    rb0 = *(const float4*)&W[(size_t)(0 + b_k0) * 256 + n0 + b_n4_0 * 4];
    rb1 = *(const float4*)&W[(size_t)(0 + b_k1) * 256 + n0 + b_n4_1 * 4];

    for (int c = 0; c < 8; c++) {
        __syncthreads();
        {
            #pragma unroll
            for (int p = 0; p < 2; p++) {
                int m  = p ? a_m1 : a_m0;
                int k4 = p ? a_k4_1 : a_k4_0;
                float4 v = p ? ra1 : ra0;
                int frag = (m >> 4) * 4 + (k4 >> 1);
                int idx  = (k4 & 1) * 2 + ((m & 15) >> 3);
                uint32_t* dst = (uint32_t*)&AF[frag * 32 + ((m & 7) * 4)];
                dst[0 * 4 + idx] = f2tf(v.x);
                dst[1 * 4 + idx] = f2tf(v.y);
                dst[2 * 4 + idx] = f2tf(v.z);
                dst[3 * 4 + idx] = f2tf(v.w);
            }
            #pragma unroll
            for (int p = 0; p < 2; p++) {
                int k  = p ? b_k1 : b_k0;
                int n4 = p ? b_n4_1 : b_n4_0;
                float4 v = p ? rb1 : rb0;
                int frag = (n4 >> 1) * 4 + (k >> 3);
                int hi   = (k >> 2) & 1;
                uint32_t* dst = (uint32_t*)&BF[frag * 32 + (n4 & 1) * 16 + (k & 3)];
                dst[0 * 8 + hi] = f2tf(v.x);
                dst[1 * 8 + hi] = f2tf(v.y);
                dst[2 * 8 + hi] = f2tf(v.z);
                dst[3 * 8 + hi] = f2tf(v.w);
            }
        }
        __syncthreads();

        if (c < 7) {
            int kt = (c + 1) * 32;
            ra0 = *(const float4*)&A[(size_t)(m0 + a_m0) * 256 + kt + a_k4_0 * 4];
            ra1 = *(const float4*)&A[(size_t)(m0 + a_m1) * 256 + kt + a_k4_1 * 4];
            rb0 = *(const float4*)&W[(size_t)(kt + b_k0) * 256 + n0 + b_n4_0 * 4];
            rb1 = *(const float4*)&W[(size_t)(kt + b_k1) * 256 + n0 + b_n4_1 * 4];
        }

        #pragma unroll
        for (int ks = 0; ks < 4; ks++) {
            uint4 a = AF[(mf * 4 + ks) * 32 + lane];
            #pragma unroll
            for (int j = 0; j < 4; j++) {
                uint2 b = BF[((nhalf * 4 + j) * 4 + ks) * 32 + lane];
                mma_tf32(acc[j][0], acc[j][1], acc[j][2], acc[j][3],
                         a.x, a.y, a.z, a.w, b.x, b.y);
            }
        }
    }

    const int row0 = m0 + mf * 16 + g;
    const int key0 = mf * 16 + g;       // key index within 64-chunk (modes 2/3)
    const int ck   = m0 >> 6;
    #pragma unroll
    for (int j = 0; j < 4; j++) {
        int col = n0 + nhalf * 32 + j * 8 + 2 * q;
        float2 bz = *(const float2*)&bias[col];
        float v00 = acc[j][0] + bz.x, v01 = acc[j][1] + bz.y;
        float v10 = acc[j][2] + bz.x, v11 = acc[j][3] + bz.y;
        if (mode == 0) {
            v00 *= scale; v01 *= scale; v10 *= scale; v11 *= scale;
            size_t base = (size_t)(col >> 5) * ((size_t)N * 32) + (col & 31);
            *(float2*)&out[base + (size_t)row0 * 32]       = make_float2(v00, v01);
            *(float2*)&out[base + (size_t)(row0 + 8) * 32] = make_float2(v10, v11);
        } else if (mode == 1) {
            *(float2*)&out[(size_t)row0 * 256 + col]       = make_float2(v00, v01);
            *(float2*)&out[(size_t)(row0 + 8) * 256 + col] = make_float2(v10, v11);
        } else {
            int hh = col >> 5, dd = col & 31;
            if (mode == 2) {
                uint32_t* KD = &g_kf[((size_t)hh * NCHUNK + ck) * 1024];
                KD[kaddr16(key0,     dd)] = packh2(v00, v01);
                KD[kaddr16(key0 + 8, dd)] = packh2(v10, v11);
            } else {
                __half* VD = (__half*)&g_vf[((size_t)hh * NCHUNK + ck) * 1024];
                VD[vaddr16h(key0,     dd)]     = __float2half_rn(v00);
                VD[vaddr16h(key0,     dd + 1)] = __float2half_rn(v01);
                VD[vaddr16h(key0 + 8, dd)]     = __float2half_rn(v10);
                VD[vaddr16h(key0 + 8, dd + 1)] = __float2half_rn(v11);
            }
        }
    }
}

// fused Q/K/V projections: grid.z selects which; K/V write fp16 fragments
__global__ __launch_bounds__(256) void qkv_proj(const float* __restrict__ q,
                                                const float* __restrict__ k,
                                                const float* __restrict__ v,
                                                const float* __restrict__ Wq,
                                                const float* __restrict__ Wk,
                                                const float* __restrict__ Wv,
                                                const float* __restrict__ bq,
                                                const float* __restrict__ bk,
                                                const float* __restrict__ bv,
                                                float* __restrict__ oq,
                                                float scale)
{
    int z = blockIdx.z;
    if (z == 0)      proj_body(q, Wq, bq, oq,      scale, 0);
    else if (z == 1) proj_body(k, Wk, bk, nullptr, 1.f,   2);
    else             proj_body(v, Wv, bv, nullptr, 1.f,   3);
}

__global__ __launch_bounds__(256) void o_proj(const float* __restrict__ A,
                                              const float* __restrict__ W,
                                              const float* __restrict__ bias,
                                              float* __restrict__ out)
{
    proj_body(A, W, bias, out, 1.f, 1);
}

// -------------------- fp16 tensor-core flash attention ---------------------
// grid (N/64, HEADS, NSPLIT), 128 threads. m16n8k16 fp16 mma, fp32 accum.
// P C-fragments map directly onto A-fragments: zero shuffles.
__global__ __launch_bounds__(128) void attn_mma_kernel()
{
    __shared__ uint32_t KB[2][1024];   // 2 x 4 KB fp16 K fragments
    __shared__ uint32_t VB[2][1024];   // 2 x 4 KB fp16 V fragments

    const int tid  = threadIdx.x;
    const int lane = tid & 31;
    const int warp = tid >> 5;
    const int q    = lane & 3;
    const int g    = lane >> 2;
    const int h  = blockIdx.y;
    const int z  = blockIdx.z;
    const int q0 = blockIdx.x * 64;
    const int wr0 = warp * 16;
    const int row = q0 + wr0 + g;

    // Q A-fragments (fp16x2), held for whole kernel: 2 k16-steps over DK=32
    uint32_t qa[2][4];
    {
        const float* q0p = &g_qh[((size_t)h * N + row) * DK];
        const float* q8p = q0p + 8 * DK;
        #pragma unroll
        for (int ks = 0; ks < 2; ks++) {
            int d = ks * 16 + 2 * q;
            qa[ks][0] = packh2(q0p[d],     q0p[d + 1]);
            qa[ks][1] = packh2(q8p[d],     q8p[d + 1]);
            qa[ks][2] = packh2(q0p[d + 8], q0p[d + 9]);
            qa[ks][3] = packh2(q8p[d + 8], q8p[d + 9]);
        }
    }

    float o[4][4];
    #pragma unroll
    for (int n = 0; n < 4; n++)
        #pragma unroll
        for (int e = 0; e < 4; e++) o[n][e] = 0.f;

    float m0 = -INFINITY, m8 = -INFINITY, l0 = 0.f, l8 = 0.f;

    const int ck0 = (z * KSPAN) / 64;
    const int nch = KSPAN / 64;

    // prologue: fill buffer 0 (4KB K + 4KB V = 2+2 cp16 per thread)
    {
        const uint4* ks = (const uint4*)&g_kf[(size_t)(h * NCHUNK + ck0) * 1024];
        const uint4* vs = (const uint4*)&g_vf[(size_t)(h * NCHUNK + ck0) * 1024];
        #pragma unroll
        for (int i = 0; i < 2; i++) {
            int idx = i * 128 + tid;
            cp16((uint32_t)__cvta_generic_to_shared(&KB[0][idx * 4]), ks + idx);
            cp16((uint32_t)__cvta_generic_to_shared(&VB[0][idx * 4]), vs + idx);
        }
        asm volatile("cp.async.commit_group;");
    }

    for (int cc = 0; cc < nch; cc++) {
        const int cur = cc & 1;
        const int kb = (ck0 + cc) * 64;

        // prefetch bias into registers (overlaps with cp.async wait + mma)
        float2 bb0[8], bb8[8];
        {
            const float* brow = &g_bias[(size_t)row * N + kb];
            #pragma unroll
            for (int j = 0; j < 8; j++) {
                bb0[j] = *(const float2*)&brow[8 * j + 2 * q];
                bb8[j] = *(const float2*)&brow[(size_t)8 * N + 8 * j + 2 * q];
            }
        }

        if (cc + 1 < nch) {
            const int nxt = ck0 + cc + 1;
            const uint4* ks = (const uint4*)&g_kf[(size_t)(h * NCHUNK + nxt) * 1024];
            const uint4* vs = (const uint4*)&g_vf[(size_t)(h * NCHUNK + nxt) * 1024];
            #pragma unroll
            for (int i = 0; i < 2; i++) {
                int idx = i * 128 + tid;
                cp16((uint32_t)__cvta_generic_to_shared(&KB[1 - cur][idx * 4]), ks + idx);
                cp16((uint32_t)__cvta_generic_to_shared(&VB[1 - cur][idx * 4]), vs + idx);
            }
            asm volatile("cp.async.commit_group;");
            asm volatile("cp.async.wait_group 1;");
        } else {
            asm volatile("cp.async.wait_group 0;");
        }
        __syncthreads();

        const uint32_t* KBc = KB[cur];
        const uint32_t* VBc = VB[cur];

        // ---- S = Q @ K^T : 16 mma m16n8k16 ----
        float s[8][4];
        #pragma unroll
        for (int j = 0; j < 8; j++)
            #pragma unroll
            for (int e = 0; e < 4; e++) s[j][e] = 0.f;

        #pragma unroll
        for (int ks = 0; ks < 2; ks++) {
            #pragma unroll
            for (int j = 0; j < 8; j++) {
                uint2 b = *(const uint2*)&KBc[((ks * 8 + j) * 32 + lane) * 2];
                mma_f16(s[j][0], s[j][1], s[j][2], s[j][3],
                        qa[ks][0], qa[ks][1], qa[ks][2], qa[ks][3], b.x, b.y);
            }
        }

        #pragma unroll
        for (int j = 0; j < 8; j++) {
            s[j][0] += bb0[j].x; s[j][1] += bb0[j].y;
            s[j][2] += bb8[j].x; s[j][3] += bb8[j].y;
        }

        // ---- online softmax ----
        float mx0 = s[0][0], mx8 = s[0][2];
        #pragma unroll
        for (int j = 0; j < 8; j++) {
            mx0 = fmaxf(mx0, fmaxf(s[j][0], s[j][1]));
            mx8 = fmaxf(mx8, fmaxf(s[j][2], s[j][3]));
        }
        mx0 = fmaxf(mx0, __shfl_xor_sync(0xffffffffu, mx0, 1));
        mx0 = fmaxf(mx0, __shfl_xor_sync(0xffffffffu, mx0, 2));
        mx8 = fmaxf(mx8, __shfl_xor_sync(0xffffffffu, mx8, 1));
        mx8 = fmaxf(mx8, __shfl_xor_sync(0xffffffffu, mx8, 2));

        float mn0 = fmaxf(m0, mx0), mn8 = fmaxf(m8, mx8);
        float c0 = __expf(m0 - mn0), c8 = __expf(m8 - mn8);
        m0 = mn0; m8 = mn8;
        l0 *= c0;  l8 *= c8;
        #pragma unroll
        for (int n = 0; n < 4; n++) {
            o[n][0] *= c0; o[n][1] *= c0;
            o[n][2] *= c8; o[n][3] *= c8;
        }

        float p[8][4];
        #pragma unroll
        for (int j = 0; j < 8; j++) {
            p[j][0] = __expf(s[j][0] - m0);
            p[j][1] = __expf(s[j][1] - m0);
            p[j][2] = __expf(s[j][2] - m8);
            p[j][3] = __expf(s[j][3] - m8);
            l0 += p[j][0] + p[j][1];
            l8 += p[j][2] + p[j][3];
        }

        // ---- O += P @ V : 16 mma m16n8k16, C->A direct (no shuffles) ----
        #pragma unroll
        for (int kk = 0; kk < 4; kk++) {
            uint32_t a0 = packh2(p[2 * kk][0],     p[2 * kk][1]);
            uint32_t a1 = packh2(p[2 * kk][2],     p[2 * kk][3]);
            uint32_t a2 = packh2(p[2 * kk + 1][0], p[2 * kk + 1][1]);
            uint32_t a3 = packh2(p[2 * kk + 1][2], p[2 * kk + 1][3]);
            #pragma unroll
            for (int n = 0; n < 4; n++) {
                uint2 b = *(const uint2*)&VBc[((kk * 4 + n) * 32 + lane) * 2];
                mma_f16(o[n][0], o[n][1], o[n][2], o[n][3], a0, a1, a2, a3, b.x, b.y);
            }
        }
        __syncthreads();   // all reads of buf[cur] done before it is refilled
    }

    l0 += __shfl_xor_sync(0xffffffffu, l0, 1);
    l0 += __shfl_xor_sync(0xffffffffu, l0, 2);
    l8 += __shfl_xor_sync(0xffffffffu, l8, 1);
    l8 += __shfl_xor_sync(0xffffffffu, l8, 2);

    const int rid = (z * HEADS + h) * N + q0 + wr0 + g;
    if (q == 0) {
        g_pm[rid] = m0;     g_pl[rid] = l0;
        g_pm[rid + 8] = m8; g_pl[rid + 8] = l8;
    }
    float* pav0 = &g_pav[(size_t)rid * DK];
    float* pav8 = &g_pav[(size_t)(rid + 8) * DK];
    #pragma unroll
    for (int n = 0; n < 4; n++) {
        *(float2*)&pav0[8 * n + 2 * q] = make_float2(o[n][0], o[n][1]);
        *(float2*)&pav8[8 * n + 2 * q] = make_float2(o[n][2], o[n][3]);
    }
}

// -------------------- split-K combine ------------------------------------
__global__ void combine_kernel()
{
    int idx = blockIdx.x * blockDim.x + threadIdx.x;
    int h = idx >> 11;
    int row = idx & (N - 1);

    float M = -INFINITY;
    #pragma unroll
    for (int s = 0; s < NSPLIT; s++)
        M = fmaxf(M, g_pm[(s * HEADS + h) * N + row]);

    float l = 0.f;
    float4 acc[8];
    #pragma unroll
    for (int w = 0; w < 8; w++) acc[w] = make_float4(0.f, 0.f, 0.f, 0.f);

    #pragma unroll
    for (int s = 0; s < NSPLIT; s++) {
        int rid = (s * HEADS + h) * N + row;
        float wgt = __expf(g_pm[rid] - M);
        l += g_pl[rid] * wgt;
        const float4* pav = (const float4*)&g_pav[(size_t)rid * DK];
        #pragma unroll
        for (int w = 0; w < 8; w++) {
            float4 a = pav[w];
            acc[w].x = fmaf(a.x, wgt, acc[w].x);
            acc[w].y = fmaf(a.y, wgt, acc[w].y);
            acc[w].z = fmaf(a.z, wgt, acc[w].z);
            acc[w].w = fmaf(a.w, wgt, acc[w].w);
        }
    }
    float inv = 1.f / l;
    float* orow = &g_attn[(size_t)row * HIDDEN + h * DK];
    #pragma unroll
    for (int w = 0; w < 8; w++) {
        float4 v = acc[w];
        v.x *= inv; v.y *= inv; v.z *= inv; v.w *= inv;
        ((float4*)orow)[w] = v;
    }
}

// -------------------- launch ------------------------------------------------
extern "C" void kernel_launch(void* const* d_in, const int* in_sizes, int n_in,
                              void* d_out, int out_size)
{
    const int*   label   = (const int*)  d_in[0];
    const float* dist    = (const float*)d_in[1];
    const float* contact = (const float*)d_in[2];
    const float* q       = (const float*)d_in[3];
    const float* k       = (const float*)d_in[4];
    const float* v       = (const float*)d_in[5];
    const float* Wq = (const float*)d_in[6];  const float* bq = (const float*)d_in[7];
    const float* Wk = (const float*)d_in[8];  const float* bk = (const float*)d_in[9];
    const float* Wv = (const float*)d_in[10]; const float* bv = (const float*)d_in[11];
    const float* Wo = (const float*)d_in[12]; const float* bo = (const float*)d_in[13];
    const float* Wd1 = (const float*)d_in[14]; const float* bd1 = (const float*)d_in[15];
    const float* Wd2 = (const float*)d_in[16]; const float* bd2 = (const float*)d_in[17];
    const float* Wc1 = (const float*)d_in[18]; const float* bc1 = (const float*)d_in[19];
    const float* Wc2 = (const float*)d_in[20]; const float* bc2 = (const float*)d_in[21];
    float* out = (float*)d_out;

    float *p_qh, *p_attn;
    cudaGetSymbolAddress((void**)&p_qh,   g_qh);
    cudaGetSymbolAddress((void**)&p_attn, g_attn);

    coef_kernel<<<1, 1>>>(Wd1, bd1, Wd2, bd2, Wc1, bc1, Wc2, bc2);
    bias_kernel<<<(N * N / 4) / 256, 256>>>(label, dist, contact);

    const float scale = 1.f / sqrtf((float)DK);
    qkv_proj<<<dim3(N / 64, HIDDEN / 64, 3), 256>>>(q, k, v, Wq, Wk, Wv,
                                                    bq, bk, bv, p_qh, scale);

    attn_mma_kernel<<<dim3(N / 64, HEADS, NSPLIT), 128>>>();
    combine_kernel<<<(HEADS * N) / 128, 128>>>();

    o_proj<<<dim3(N / 64, HIDDEN / 64), 256>>>(p_attn, Wo, bo, out);
}

// round 8
// speedup vs baseline: 5.0672x; 1.1156x over previous
#include <cuda_runtime.h>
#include <cuda_fp16.h>
#include <math.h>
#include <stdint.h>

#define N 2048
#define HIDDEN 256
#define HEADS 8
#define DK 32
#define NSPLIT 4
#define KSPAN (N / NSPLIT)
#define NCHUNK (N / 64)
#define BSTRIDE 68   // bias smem row stride in words (16B-aligned, conflict-light)

// -------------------- scratch (__device__ globals; no allocs allowed) -----
__device__ float g_bias[N * N];                    // 16 MB pair bias
__device__ float g_qh[HEADS * N * DK];             // head-major projected q (scaled)
__device__ uint32_t g_kf[HEADS * NCHUNK * 1024];   // fragment-major fp16 K (m16n8k16 B)
__device__ uint32_t g_vf[HEADS * NCHUNK * 1024];   // fragment-major fp16 V (m16n8k16 B)
// split-K partials
__device__ float g_pm[NSPLIT * HEADS * N];
__device__ float g_pl[NSPLIT * HEADS * N];
__device__ float g_pav[NSPLIT * HEADS * N * DK];

// -------------------- helpers ---------------------------------------------
__device__ __forceinline__ uint32_t f2tf(float f) {
    uint32_t u;
    asm("cvt.rna.tf32.f32 %0, %1;" : "=r"(u) : "f"(f));
    return u;
}

__device__ __forceinline__ uint32_t packh2(float lo, float hi) {
    __half2 h = __floats2half2_rn(lo, hi);
    return *reinterpret_cast<uint32_t*>(&h);
}

__device__ __forceinline__ void mma_tf32(float& d0, float& d1, float& d2, float& d3,
                                         uint32_t a0, uint32_t a1, uint32_t a2, uint32_t a3,
                                         uint32_t b0, uint32_t b1)
{
    asm volatile("mma.sync.aligned.m16n8k8.row.col.f32.tf32.tf32.f32 "
                 "{%0,%1,%2,%3}, {%4,%5,%6,%7}, {%8,%9}, {%0,%1,%2,%3};"
                 : "+f"(d0), "+f"(d1), "+f"(d2), "+f"(d3)
                 : "r"(a0), "r"(a1), "r"(a2), "r"(a3), "r"(b0), "r"(b1));
}

__device__ __forceinline__ void mma_f16(float& d0, float& d1, float& d2, float& d3,
                                        uint32_t a0, uint32_t a1, uint32_t a2, uint32_t a3,
                                        uint32_t b0, uint32_t b1)
{
    asm volatile("mma.sync.aligned.m16n8k16.row.col.f32.f16.f16.f32 "
                 "{%0,%1,%2,%3}, {%4,%5,%6,%7}, {%8,%9}, {%0,%1,%2,%3};"
                 : "+f"(d0), "+f"(d1), "+f"(d2), "+f"(d3)
                 : "r"(a0), "r"(a1), "r"(a2), "r"(a3), "r"(b0), "r"(b1));
}

__device__ __forceinline__ void cp16(uint32_t smem_dst, const void* gsrc) {
    asm volatile("cp.async.cg.shared.global [%0], [%1], 16;"
                 :: "r"(smem_dst), "l"(gsrc));
}

// K fragment word index (fp16x2 packed over d-pairs): B-frag of m16n8k16
__device__ __forceinline__ int kaddr16(int key, int d) {
    return ((d >> 4) * 8 + (key >> 3)) * 64 + ((key & 7) * 4 + ((d & 7) >> 1)) * 2 + ((d >> 3) & 1);
}
// V fragment half index (fp16x2 packed over key-pairs)
__device__ __forceinline__ int vaddr16h(int key, int d) {
    return ((((key >> 4) * 4 + (d >> 3)) * 32 + (d & 7) * 4 + ((key & 7) >> 1)) * 2
            + ((key >> 3) & 1)) * 2 + (key & 1);
}

// -------------------- bias kernel (coef MLP collapse inlined) -------------
__global__ void bias_kernel(const int* __restrict__ label,
                            const float* __restrict__ dist,
                            const float* __restrict__ contact,
                            const float* __restrict__ Wd1, const float* __restrict__ bd1,
                            const float* __restrict__ Wd2, const float* __restrict__ bd2,
                            const float* __restrict__ Wc1, const float* __restrict__ bc1,
                            const float* __restrict__ Wc2, const float* __restrict__ bc2)
{
    __shared__ float4 cf;
    if (threadIdx.x == 0) {
        float am = 0.f, al = 0.f, c0 = bd2[0] + bc2[0], cm = 0.f;
        #pragma unroll
        for (int h = 0; h < 16; h++) {
            am += Wd1[h]      * Wd2[h];
            al += Wd1[16 + h] * Wd2[h];
            c0 += bd1[h]      * Wd2[h];
            cm += Wc1[h]      * Wc2[h];
            al += Wc1[16 + h] * Wc2[h];
            c0 += bc1[h]      * Wc2[h];
        }
        cf = make_float4(am, cm, al, c0);
    }
    __syncthreads();
    const float am = cf.x, cm = cf.y, al = cf.z, c0 = cf.w;

    int i = blockIdx.x * blockDim.x + threadIdx.x;
    float4 dm = ((const float4*)dist)[i];
    float4 cv = ((const float4*)contact)[i];
    int4   lb = ((const int4*)label)[i];
    float4 o;
    o.x = fmaf(am, dm.x, fmaf(cm, cv.x, fmaf(al, (float)lb.x, c0)));
    o.y = fmaf(am, dm.y, fmaf(cm, cv.y, fmaf(al, (float)lb.y, c0)));
    o.z = fmaf(am, dm.z, fmaf(cm, cv.z, fmaf(al, (float)lb.z, c0)));
    o.w = fmaf(am, dm.w, fmaf(cm, cv.w, fmaf(al, (float)lb.w, c0)));
    ((float4*)g_bias)[i] = o;
}

// -------------------- tf32 tensor-core projection GEMM body ----------------
// mode 0: head-major scaled (Q)   mode 2: K fp16 fragment-major
// mode 3: V fp16 fragment-major
__device__ __forceinline__ void proj_body(const float* __restrict__ A,
                                          const float* __restrict__ W,
                                          const float* __restrict__ bias,
                                          float* __restrict__ out,
                                          float scale, int mode)
{
    __shared__ uint4 AF[16 * 32];   // 8 KB
    __shared__ uint2 BF[32 * 32];   // 8 KB

    const int t    = threadIdx.x;
    const int lane = t & 31;
    const int w    = t >> 5;
    const int q    = lane & 3;
    const int g    = lane >> 2;
    const int m0   = blockIdx.x * 64;
    const int n0   = blockIdx.y * 64;
    const int mf    = w >> 1;
    const int nhalf = w & 1;

    float acc[4][4];
    #pragma unroll
    for (int j = 0; j < 4; j++)
        #pragma unroll
        for (int e = 0; e < 4; e++) acc[j][e] = 0.f;

    const int a_m0 = t >> 3,         a_k4_0 = t & 7;
    const int a_m1 = (t + 256) >> 3, a_k4_1 = (t + 256) & 7;
    const int b_k0 = t >> 4,         b_n4_0 = t & 15;
    const int b_k1 = (t + 256) >> 4, b_n4_1 = (t + 256) & 15;

    float4 ra0, ra1, rb0, rb1;
    ra0 = *(const float4*)&A[(size_t)(m0 + a_m0) * 256 + 0 + a_k4_0 * 4];
    ra1 = *(const float4*)&A[(size_t)(m0 + a_m1) * 256 + 0 + a_k4_1 * 4];
    rb0 = *(const float4*)&W[(size_t)(0 + b_k0) * 256 + n0 + b_n4_0 * 4];
    rb1 = *(const float4*)&W[(size_t)(0 + b_k1) * 256 + n0 + b_n4_1 * 4];

    for (int c = 0; c < 8; c++) {
        __syncthreads();
        {
            #pragma unroll
            for (int p = 0; p < 2; p++) {
                int m  = p ? a_m1 : a_m0;
                int k4 = p ? a_k4_1 : a_k4_0;
                float4 v = p ? ra1 : ra0;
                int frag = (m >> 4) * 4 + (k4 >> 1);
                int idx  = (k4 & 1) * 2 + ((m & 15) >> 3);
                uint32_t* dst = (uint32_t*)&AF[frag * 32 + ((m & 7) * 4)];
                dst[0 * 4 + idx] = f2tf(v.x);
                dst[1 * 4 + idx] = f2tf(v.y);
                dst[2 * 4 + idx] = f2tf(v.z);
                dst[3 * 4 + idx] = f2tf(v.w);
            }
            #pragma unroll
            for (int p = 0; p < 2; p++) {
                int k  = p ? b_k1 : b_k0;
                int n4 = p ? b_n4_1 : b_n4_0;
                float4 v = p ? rb1 : rb0;
                int frag = (n4 >> 1) * 4 + (k >> 3);
                int hi   = (k >> 2) & 1;
                uint32_t* dst = (uint32_t*)&BF[frag * 32 + (n4 & 1) * 16 + (k & 3)];
                dst[0 * 8 + hi] = f2tf(v.x);
                dst[1 * 8 + hi] = f2tf(v.y);
                dst[2 * 8 + hi] = f2tf(v.z);
                dst[3 * 8 + hi] = f2tf(v.w);
            }
        }
        __syncthreads();

        if (c < 7) {
            int kt = (c + 1) * 32;
            ra0 = *(const float4*)&A[(size_t)(m0 + a_m0) * 256 + kt + a_k4_0 * 4];
            ra1 = *(const float4*)&A[(size_t)(m0 + a_m1) * 256 + kt + a_k4_1 * 4];
            rb0 = *(const float4*)&W[(size_t)(kt + b_k0) * 256 + n0 + b_n4_0 * 4];
            rb1 = *(const float4*)&W[(size_t)(kt + b_k1) * 256 + n0 + b_n4_1 * 4];
        }

        #pragma unroll
        for (int ks = 0; ks < 4; ks++) {
            uint4 a = AF[(mf * 4 + ks) * 32 + lane];
            #pragma unroll
            for (int j = 0; j < 4; j++) {
                uint2 b = BF[((nhalf * 4 + j) * 4 + ks) * 32 + lane];
                mma_tf32(acc[j][0], acc[j][1], acc[j][2], acc[j][3],
                         a.x, a.y, a.z, a.w, b.x, b.y);
            }
        }
    }

    const int row0 = m0 + mf * 16 + g;
    const int key0 = mf * 16 + g;
    const int ck   = m0 >> 6;
    #pragma unroll
    for (int j = 0; j < 4; j++) {
        int col = n0 + nhalf * 32 + j * 8 + 2 * q;
        float2 bz = *(const float2*)&bias[col];
        float v00 = acc[j][0] + bz.x, v01 = acc[j][1] + bz.y;
        float v10 = acc[j][2] + bz.x, v11 = acc[j][3] + bz.y;
        if (mode == 0) {
            v00 *= scale; v01 *= scale; v10 *= scale; v11 *= scale;
            size_t base = (size_t)(col >> 5) * ((size_t)N * 32) + (col & 31);
            *(float2*)&out[base + (size_t)row0 * 32]       = make_float2(v00, v01);
            *(float2*)&out[base + (size_t)(row0 + 8) * 32] = make_float2(v10, v11);
        } else {
            int hh = col >> 5, dd = col & 31;
            if (mode == 2) {
                uint32_t* KD = &g_kf[((size_t)hh * NCHUNK + ck) * 1024];
                KD[kaddr16(key0,     dd)] = packh2(v00, v01);
                KD[kaddr16(key0 + 8, dd)] = packh2(v10, v11);
            } else {
                __half* VD = (__half*)&g_vf[((size_t)hh * NCHUNK + ck) * 1024];
                VD[vaddr16h(key0,     dd)]     = __float2half_rn(v00);
                VD[vaddr16h(key0,     dd + 1)] = __float2half_rn(v01);
                VD[vaddr16h(key0 + 8, dd)]     = __float2half_rn(v10);
                VD[vaddr16h(key0 + 8, dd + 1)] = __float2half_rn(v11);
            }
        }
    }
}

// fused Q/K/V projections
__global__ __launch_bounds__(256) void qkv_proj(const float* __restrict__ q,
                                                const float* __restrict__ k,
                                                const float* __restrict__ v,
                                                const float* __restrict__ Wq,
                                                const float* __restrict__ Wk,
                                                const float* __restrict__ Wv,
                                                const float* __restrict__ bq,
                                                const float* __restrict__ bk,
                                                const float* __restrict__ bv,
                                                float* __restrict__ oq,
                                                float scale)
{
    int z = blockIdx.z;
    if (z == 0)      proj_body(q, Wq, bq, oq,      scale, 0);
    else if (z == 1) proj_body(k, Wk, bk, nullptr, 1.f,   2);
    else             proj_body(v, Wv, bv, nullptr, 1.f,   3);
}

// -------------------- O-projection with fused split-K combine -------------
// A[row][32h+d] is computed on the fly from split-K partials:
//   A = sum_s (exp(pm_s - M)/l) * pav_s   (weights staged in smem per (row,head))
__global__ __launch_bounds__(256) void o_proj_fused(const float* __restrict__ W,
                                                    const float* __restrict__ bo,
                                                    float* __restrict__ out)
{
    __shared__ uint4 AF[16 * 32];   // 8 KB
    __shared__ uint2 BF[32 * 32];   // 8 KB
    __shared__ float4 WC[64][8];    // 8 KB: [row_local][head] = wgt_s/l

    const int t    = threadIdx.x;
    const int lane = t & 31;
    const int w    = t >> 5;
    const int q    = lane & 3;
    const int g    = lane >> 2;
    const int m0   = blockIdx.x * 64;
    const int n0   = blockIdx.y * 64;
    const int mf    = w >> 1;
    const int nhalf = w & 1;

    // ---- prologue: combine weights for this block's 64 rows x 8 heads ----
    #pragma unroll
    for (int p = 0; p < 2; p++) {
        int idx = t + p * 256;          // 0..511
        int r = idx >> 3, hh = idx & 7;
        int row = m0 + r;
        float pm[4], pl[4];
        float M = -INFINITY;
        #pragma unroll
        for (int s = 0; s < 4; s++) {
            pm[s] = g_pm[(s * HEADS + hh) * N + row];
            pl[s] = g_pl[(s * HEADS + hh) * N + row];
            M = fmaxf(M, pm[s]);
        }
        float wgt[4], l = 0.f;
        #pragma unroll
        for (int s = 0; s < 4; s++) { wgt[s] = __expf(pm[s] - M); l += pl[s] * wgt[s]; }
        float inv = 1.f / l;
        WC[r][hh] = make_float4(wgt[0] * inv, wgt[1] * inv, wgt[2] * inv, wgt[3] * inv);
    }

    float acc[4][4];
    #pragma unroll
    for (int j = 0; j < 4; j++)
        #pragma unroll
        for (int e = 0; e < 4; e++) acc[j][e] = 0.f;

    const int a_m0 = t >> 3,         a_k4_0 = t & 7;
    const int a_m1 = (t + 256) >> 3, a_k4_1 = (t + 256) & 7;
    const int b_k0 = t >> 4,         b_n4_0 = t & 15;
    const int b_k1 = (t + 256) >> 4, b_n4_1 = (t + 256) & 15;

    float4 pv[2][4];   // split partials for the two A slots
    float4 rb0, rb1;
    // prefetch chunk 0 (head 0)
    #pragma unroll
    for (int p = 0; p < 2; p++) {
        int m  = p ? a_m1 : a_m0;
        int d0 = (p ? a_k4_1 : a_k4_0) * 4;
        #pragma unroll
        for (int s = 0; s < 4; s++)
            pv[p][s] = *(const float4*)&g_pav[(((size_t)(s * HEADS + 0)) * N + m0 + m) * DK + d0];
    }
    rb0 = *(const float4*)&W[(size_t)(0 + b_k0) * 256 + n0 + b_n4_0 * 4];
    rb1 = *(const float4*)&W[(size_t)(0 + b_k1) * 256 + n0 + b_n4_1 * 4];

    for (int c = 0; c < 8; c++) {
        __syncthreads();   // also covers WC readiness on c==0
        {
            #pragma unroll
            for (int p = 0; p < 2; p++) {
                int m  = p ? a_m1 : a_m0;
                int k4 = p ? a_k4_1 : a_k4_0;
                float4 wc = WC[m][c];
                float4 v;
                v.x = wc.x * pv[p][0].x + wc.y * pv[p][1].x + wc.z * pv[p][2].x + wc.w * pv[p][3].x;
                v.y = wc.x * pv[p][0].y + wc.y * pv[p][1].y + wc.z * pv[p][2].y + wc.w * pv[p][3].y;
                v.z = wc.x * pv[p][0].z + wc.y * pv[p][1].z + wc.z * pv[p][2].z + wc.w * pv[p][3].z;
                v.w = wc.x * pv[p][0].w + wc.y * pv[p][1].w + wc.z * pv[p][2].w + wc.w * pv[p][3].w;
                int frag = (m >> 4) * 4 + (k4 >> 1);
                int idx  = (k4 & 1) * 2 + ((m & 15) >> 3);
                uint32_t* dst = (uint32_t*)&AF[frag * 32 + ((m & 7) * 4)];
                dst[0 * 4 + idx] = f2tf(v.x);
                dst[1 * 4 + idx] = f2tf(v.y);
                dst[2 * 4 + idx] = f2tf(v.z);
                dst[3 * 4 + idx] = f2tf(v.w);
            }
            #pragma unroll
            for (int p = 0; p < 2; p++) {
                int k  = p ? b_k1 : b_k0;
                int n4 = p ? b_n4_1 : b_n4_0;
                float4 v = p ? rb1 : rb0;
                int frag = (n4 >> 1) * 4 + (k >> 3);
                int hi   = (k >> 2) & 1;
                uint32_t* dst = (uint32_t*)&BF[frag * 32 + (n4 & 1) * 16 + (k & 3)];
                dst[0 * 8 + hi] = f2tf(v.x);
                dst[1 * 8 + hi] = f2tf(v.y);
                dst[2 * 8 + hi] = f2tf(v.z);
                dst[3 * 8 + hi] = f2tf(v.w);
            }
        }
        __syncthreads();

        if (c < 7) {
            int hh = c + 1;
            #pragma unroll
            for (int p = 0; p < 2; p++) {
                int m  = p ? a_m1 : a_m0;
                int d0 = (p ? a_k4_1 : a_k4_0) * 4;
                #pragma unroll
                for (int s = 0; s < 4; s++)
                    pv[p][s] = *(const float4*)&g_pav[(((size_t)(s * HEADS + hh)) * N + m0 + m) * DK + d0];
            }
            int kt = hh * 32;
            rb0 = *(const float4*)&W[(size_t)(kt + b_k0) * 256 + n0 + b_n4_0 * 4];
            rb1 = *(const float4*)&W[(size_t)(kt + b_k1) * 256 + n0 + b_n4_1 * 4];
        }

        #pragma unroll
        for (int ks = 0; ks < 4; ks++) {
            uint4 a = AF[(mf * 4 + ks) * 32 + lane];
            #pragma unroll
            for (int j = 0; j < 4; j++) {
                uint2 b = BF[((nhalf * 4 + j) * 4 + ks) * 32 + lane];
                mma_tf32(acc[j][0], acc[j][1], acc[j][2], acc[j][3],
                         a.x, a.y, a.z, a.w, b.x, b.y);
            }
        }
    }

    const int row0 = m0 + mf * 16 + g;
    #pragma unroll
    for (int j = 0; j < 4; j++) {
        int col = n0 + nhalf * 32 + j * 8 + 2 * q;
        float2 bz = *(const float2*)&bo[col];
        *(float2*)&out[(size_t)row0 * 256 + col] =
            make_float2(acc[j][0] + bz.x, acc[j][1] + bz.y);
        *(float2*)&out[(size_t)(row0 + 8) * 256 + col] =
            make_float2(acc[j][2] + bz.x, acc[j][3] + bz.y);
    }
}

// -------------------- fp16 tensor-core flash attention ---------------------
// grid (N/64, HEADS, NSPLIT), 128 threads. cp.async double-buffered K/V AND
// bias tiles (dynamic smem, 51.2 KB).
__global__ __launch_bounds__(128) void attn_mma_kernel()
{
    extern __shared__ uint32_t dsm[];
    uint32_t* KBb = dsm;                     // [2][1024]
    uint32_t* VBb = dsm + 2048;              // [2][1024]
    float*    BSb = (float*)(dsm + 4096);    // [2][64*BSTRIDE]

    const int tid  = threadIdx.x;
    const int lane = tid & 31;
    const int warp = tid >> 5;
    const int q    = lane & 3;
    const int g    = lane >> 2;
    const int h  = blockIdx.y;
    const int z  = blockIdx.z;
    const int q0 = blockIdx.x * 64;
    const int wr0 = warp * 16;
    const int row = q0 + wr0 + g;

    uint32_t qa[2][4];
    {
        const float* q0p = &g_qh[((size_t)h * N + row) * DK];
        const float* q8p = q0p + 8 * DK;
        #pragma unroll
        for (int ks = 0; ks < 2; ks++) {
            int d = ks * 16 + 2 * q;
            qa[ks][0] = packh2(q0p[d],     q0p[d + 1]);
            qa[ks][1] = packh2(q8p[d],     q8p[d + 1]);
            qa[ks][2] = packh2(q0p[d + 8], q0p[d + 9]);
            qa[ks][3] = packh2(q8p[d + 8], q8p[d + 9]);
        }
    }

    float o[4][4];
    #pragma unroll
    for (int n = 0; n < 4; n++)
        #pragma unroll
        for (int e = 0; e < 4; e++) o[n][e] = 0.f;

    float m0 = -INFINITY, m8 = -INFINITY, l0 = 0.f, l8 = 0.f;

    const int ck0 = (z * KSPAN) / 64;
    const int nch = KSPAN / 64;

    // fill helper (K/V fragments + bias tile) for chunk ck into buffer buf
    auto fill = [&](int buf, int ck) {
        const uint4* ks = (const uint4*)&g_kf[(size_t)(h * NCHUNK + ck) * 1024];
        const uint4* vs = (const uint4*)&g_vf[(size_t)(h * NCHUNK + ck) * 1024];
        #pragma unroll
        for (int i = 0; i < 2; i++) {
            int idx = i * 128 + tid;
            cp16((uint32_t)__cvta_generic_to_shared(&KBb[buf * 1024 + idx * 4]), ks + idx);
            cp16((uint32_t)__cvta_generic_to_shared(&VBb[buf * 1024 + idx * 4]), vs + idx);
        }
        const float* bsrc = &g_bias[(size_t)q0 * N + ck * 64];
        float* bdst = &BSb[buf * 64 * BSTRIDE];
        #pragma unroll
        for (int i = 0; i < 8; i++) {
            int idx = i * 128 + tid;        // 0..1023 float4s
            int r = idx >> 4, c4 = idx & 15;
            cp16((uint32_t)__cvta_generic_to_shared(&bdst[r * BSTRIDE + c4 * 4]),
                 &bsrc[(size_t)r * N + c4 * 4]);
        }
    };

    fill(0, ck0);
    asm volatile("cp.async.commit_group;");

    for (int cc = 0; cc < nch; cc++) {
        const int cur = cc & 1;

        if (cc + 1 < nch) {
            fill(1 - cur, ck0 + cc + 1);
            asm volatile("cp.async.commit_group;");
            asm volatile("cp.async.wait_group 1;");
        } else {
            asm volatile("cp.async.wait_group 0;");
        }
        __syncthreads();

        const uint32_t* KBc = &KBb[cur * 1024];
        const uint32_t* VBc = &VBb[cur * 1024];
        const float*    BSc = &BSb[cur * 64 * BSTRIDE];

        // ---- S = Q @ K^T ----
        float s[8][4];
        #pragma unroll
        for (int j = 0; j < 8; j++)
            #pragma unroll
            for (int e = 0; e < 4; e++) s[j][e] = 0.f;

        #pragma unroll
        for (int ks = 0; ks < 2; ks++) {
            #pragma unroll
            for (int j = 0; j < 8; j++) {
                uint2 b = *(const uint2*)&KBc[((ks * 8 + j) * 32 + lane) * 2];
                mma_f16(s[j][0], s[j][1], s[j][2], s[j][3],
                        qa[ks][0], qa[ks][1], qa[ks][2], qa[ks][3], b.x, b.y);
            }
        }

        // ---- + bias (from staged smem tile) ----
        {
            const float* br0 = &BSc[(wr0 + g) * BSTRIDE];
            const float* br8 = br0 + 8 * BSTRIDE;
            #pragma unroll
            for (int j = 0; j < 8; j++) {
                float2 b0 = *(const float2*)&br0[8 * j + 2 * q];
                float2 b8 = *(const float2*)&br8[8 * j + 2 * q];
                s[j][0] += b0.x; s[j][1] += b0.y;
                s[j][2] += b8.x; s[j][3] += b8.y;
            }
        }

        // ---- online softmax ----
        float mx0 = s[0][0], mx8 = s[0][2];
        #pragma unroll
        for (int j = 0; j < 8; j++) {
            mx0 = fmaxf(mx0, fmaxf(s[j][0], s[j][1]));
            mx8 = fmaxf(mx8, fmaxf(s[j][2], s[j][3]));
        }
        mx0 = fmaxf(mx0, __shfl_xor_sync(0xffffffffu, mx0, 1));
        mx0 = fmaxf(mx0, __shfl_xor_sync(0xffffffffu, mx0, 2));
        mx8 = fmaxf(mx8, __shfl_xor_sync(0xffffffffu, mx8, 1));
        mx8 = fmaxf(mx8, __shfl_xor_sync(0xffffffffu, mx8, 2));

        float mn0 = fmaxf(m0, mx0), mn8 = fmaxf(m8, mx8);
        float c0 = __expf(m0 - mn0), c8 = __expf(m8 - mn8);
        m0 = mn0; m8 = mn8;
        l0 *= c0;  l8 *= c8;
        #pragma unroll
        for (int n = 0; n < 4; n++) {
            o[n][0] *= c0; o[n][1] *= c0;
            o[n][2] *= c8; o[n][3] *= c8;
        }

        float p[8][4];
        #pragma unroll
        for (int j = 0; j < 8; j++) {
            p[j][0] = __expf(s[j][0] - m0);
            p[j][1] = __expf(s[j][1] - m0);
            p[j][2] = __expf(s[j][2] - m8);
            p[j][3] = __expf(s[j][3] - m8);
            l0 += p[j][0] + p[j][1];
            l8 += p[j][2] + p[j][3];
        }

        // ---- O += P @ V ----
        #pragma unroll
        for (int kk = 0; kk < 4; kk++) {
            uint32_t a0 = packh2(p[2 * kk][0],     p[2 * kk][1]);
            uint32_t a1 = packh2(p[2 * kk][2],     p[2 * kk][3]);
            uint32_t a2 = packh2(p[2 * kk + 1][0], p[2 * kk + 1][1]);
            uint32_t a3 = packh2(p[2 * kk + 1][2], p[2 * kk + 1][3]);
            #pragma unroll
            for (int n = 0; n < 4; n++) {
                uint2 b = *(const uint2*)&VBc[((kk * 4 + n) * 32 + lane) * 2];
                mma_f16(o[n][0], o[n][1], o[n][2], o[n][3], a0, a1, a2, a3, b.x, b.y);
            }
        }
        __syncthreads();
    }

    l0 += __shfl_xor_sync(0xffffffffu, l0, 1);
    l0 += __shfl_xor_sync(0xffffffffu, l0, 2);
    l8 += __shfl_xor_sync(0xffffffffu, l8, 1);
    l8 += __shfl_xor_sync(0xffffffffu, l8, 2);

    const int rid = (z * HEADS + h) * N + q0 + wr0 + g;
    if (q == 0) {
        g_pm[rid] = m0;     g_pl[rid] = l0;
        g_pm[rid + 8] = m8; g_pl[rid + 8] = l8;
    }
    float* pav0 = &g_pav[(size_t)rid * DK];
    float* pav8 = &g_pav[(size_t)(rid + 8) * DK];
    #pragma unroll
    for (int n = 0; n < 4; n++) {
        *(float2*)&pav0[8 * n + 2 * q] = make_float2(o[n][0], o[n][1]);
        *(float2*)&pav8[8 * n + 2 * q] = make_float2(o[n][2], o[n][3]);
    }
}

// -------------------- launch ------------------------------------------------
extern "C" void kernel_launch(void* const* d_in, const int* in_sizes, int n_in,
                              void* d_out, int out_size)
{
    const int*   label   = (const int*)  d_in[0];
    const float* dist    = (const float*)d_in[1];
    const float* contact = (const float*)d_in[2];
    const float* q       = (const float*)d_in[3];
    const float* k       = (const float*)d_in[4];
    const float* v       = (const float*)d_in[5];
    const float* Wq = (const float*)d_in[6];  const float* bq = (const float*)d_in[7];
    const float* Wk = (const float*)d_in[8];  const float* bk = (const float*)d_in[9];
    const float* Wv = (const float*)d_in[10]; const float* bv = (const float*)d_in[11];
    const float* Wo = (const float*)d_in[12]; const float* bo = (const float*)d_in[13];
    const float* Wd1 = (const float*)d_in[14]; const float* bd1 = (const float*)d_in[15];
    const float* Wd2 = (const float*)d_in[16]; const float* bd2 = (const float*)d_in[17];
    const float* Wc1 = (const float*)d_in[18]; const float* bc1 = (const float*)d_in[19];
    const float* Wc2 = (const float*)d_in[20]; const float* bc2 = (const float*)d_in[21];
    float* out = (float*)d_out;

    float* p_qh;
    cudaGetSymbolAddress((void**)&p_qh, g_qh);

    bias_kernel<<<(N * N / 4) / 256, 256>>>(label, dist, contact,
                                            Wd1, bd1, Wd2, bd2, Wc1, bc1, Wc2, bc2);

    const float scale = 1.f / sqrtf((float)DK);
    qkv_proj<<<dim3(N / 64, HIDDEN / 64, 3), 256>>>(q, k, v, Wq, Wk, Wv,
                                                    bq, bk, bv, p_qh, scale);

    const int attn_smem = 4096 * 4 + 2 * 64 * BSTRIDE * 4;   // 51200 B
    static int smem_set = 0;
    if (!smem_set) {
        cudaFuncSetAttribute(attn_mma_kernel,
                             cudaFuncAttributeMaxDynamicSharedMemorySize, attn_smem);
        smem_set = 1;
    }
    attn_mma_kernel<<<dim3(N / 64, HEADS, NSPLIT), 128, attn_smem>>>();

    o_proj_fused<<<dim3(N / 64, HIDDEN / 64), 256>>>(Wo, bo, out);
}

// round 9
// speedup vs baseline: 5.4429x; 1.0741x over previous
#include <cuda_runtime.h>
#include <cuda_fp16.h>
#include <math.h>
#include <stdint.h>

#define N 2048
#define HIDDEN 256
#define HEADS 8
#define DK 32
#define NSPLIT 4
#define KSPAN (N / NSPLIT)
#define NCHUNK (N / 64)
#define BSTR 72   // bias smem row stride in halves (16B-aligned rows: 144B)

// -------------------- scratch (__device__ globals; no allocs allowed) -----
__device__ __half g_bias[N * N];                   // 8 MB fp16 pair bias
__device__ float g_qh[HEADS * N * DK];             // head-major projected q (scaled)
__device__ uint32_t g_kf[HEADS * NCHUNK * 1024];   // fragment-major fp16 K (m16n8k16 B)
__device__ uint32_t g_vf[HEADS * NCHUNK * 1024];   // fragment-major fp16 V (m16n8k16 B)
// split-K partials
__device__ float g_pm[NSPLIT * HEADS * N];
__device__ float g_pl[NSPLIT * HEADS * N];
__device__ float g_pav[NSPLIT * HEADS * N * DK];

// -------------------- helpers ---------------------------------------------
__device__ __forceinline__ uint32_t f2tf(float f) {
    uint32_t u;
    asm("cvt.rna.tf32.f32 %0, %1;" : "=r"(u) : "f"(f));
    return u;
}

__device__ __forceinline__ uint32_t packh2(float lo, float hi) {
    __half2 h = __floats2half2_rn(lo, hi);
    return *reinterpret_cast<uint32_t*>(&h);
}

__device__ __forceinline__ void mma_tf32(float& d0, float& d1, float& d2, float& d3,
                                         uint32_t a0, uint32_t a1, uint32_t a2, uint32_t a3,
                                         uint32_t b0, uint32_t b1)
{
    asm volatile("mma.sync.aligned.m16n8k8.row.col.f32.tf32.tf32.f32 "
                 "{%0,%1,%2,%3}, {%4,%5,%6,%7}, {%8,%9}, {%0,%1,%2,%3};"
                 : "+f"(d0), "+f"(d1), "+f"(d2), "+f"(d3)
                 : "r"(a0), "r"(a1), "r"(a2), "r"(a3), "r"(b0), "r"(b1));
}

__device__ __forceinline__ void mma_f16(float& d0, float& d1, float& d2, float& d3,
                                        uint32_t a0, uint32_t a1, uint32_t a2, uint32_t a3,
                                        uint32_t b0, uint32_t b1)
{
    asm volatile("mma.sync.aligned.m16n8k16.row.col.f32.f16.f16.f32 "
                 "{%0,%1,%2,%3}, {%4,%5,%6,%7}, {%8,%9}, {%0,%1,%2,%3};"
                 : "+f"(d0), "+f"(d1), "+f"(d2), "+f"(d3)
                 : "r"(a0), "r"(a1), "r"(a2), "r"(a3), "r"(b0), "r"(b1));
}

__device__ __forceinline__ void cp16(uint32_t smem_dst, const void* gsrc) {
    asm volatile("cp.async.cg.shared.global [%0], [%1], 16;"
                 :: "r"(smem_dst), "l"(gsrc));
}

// K fragment word index (fp16x2 packed over d-pairs): B-frag of m16n8k16
__device__ __forceinline__ int kaddr16(int key, int d) {
    return ((d >> 4) * 8 + (key >> 3)) * 64 + ((key & 7) * 4 + ((d & 7) >> 1)) * 2 + ((d >> 3) & 1);
}
// V fragment half index (fp16x2 packed over key-pairs)
__device__ __forceinline__ int vaddr16h(int key, int d) {
    return ((((key >> 4) * 4 + (d >> 3)) * 32 + (d & 7) * 4 + ((key & 7) >> 1)) * 2
            + ((key >> 3) & 1)) * 2 + (key & 1);
}

// -------------------- bias kernel (coef MLP collapse inlined, fp16 out) ----
__global__ void bias_kernel(const int* __restrict__ label,
                            const float* __restrict__ dist,
                            const float* __restrict__ contact,
                            const float* __restrict__ Wd1, const float* __restrict__ bd1,
                            const float* __restrict__ Wd2, const float* __restrict__ bd2,
                            const float* __restrict__ Wc1, const float* __restrict__ bc1,
                            const float* __restrict__ Wc2, const float* __restrict__ bc2)
{
    __shared__ float4 cf;
    if (threadIdx.x == 0) {
        float am = 0.f, al = 0.f, c0 = bd2[0] + bc2[0], cm = 0.f;
        #pragma unroll
        for (int h = 0; h < 16; h++) {
            am += Wd1[h]      * Wd2[h];
            al += Wd1[16 + h] * Wd2[h];
            c0 += bd1[h]      * Wd2[h];
            cm += Wc1[h]      * Wc2[h];
            al += Wc1[16 + h] * Wc2[h];
            c0 += bc1[h]      * Wc2[h];
        }
        cf = make_float4(am, cm, al, c0);
    }
    __syncthreads();
    const float am = cf.x, cm = cf.y, al = cf.z, c0 = cf.w;

    int i = blockIdx.x * blockDim.x + threadIdx.x;   // float4 index
    float4 dm = ((const float4*)dist)[i];
    float4 cv = ((const float4*)contact)[i];
    int4   lb = ((const int4*)label)[i];
    float ox = fmaf(am, dm.x, fmaf(cm, cv.x, fmaf(al, (float)lb.x, c0)));
    float oy = fmaf(am, dm.y, fmaf(cm, cv.y, fmaf(al, (float)lb.y, c0)));
    float oz = fmaf(am, dm.z, fmaf(cm, cv.z, fmaf(al, (float)lb.z, c0)));
    float ow = fmaf(am, dm.w, fmaf(cm, cv.w, fmaf(al, (float)lb.w, c0)));
    uint2 r;
    r.x = packh2(ox, oy);
    r.y = packh2(oz, ow);
    ((uint2*)g_bias)[i] = r;
}

// -------------------- tf32 projection GEMM body (double-buffered smem) -----
// mode 0: head-major scaled (Q)   mode 2: K fp16 fragment-major
// mode 3: V fp16 fragment-major
__device__ __forceinline__ void proj_body(const float* __restrict__ A,
                                          const float* __restrict__ W,
                                          const float* __restrict__ bias,
                                          float* __restrict__ out,
                                          float scale, int mode)
{
    __shared__ uint4 AF[2][16 * 32];   // 16 KB
    __shared__ uint2 BF[2][32 * 32];   // 16 KB

    const int t    = threadIdx.x;
    const int lane = t & 31;
    const int w    = t >> 5;
    const int q    = lane & 3;
    const int g    = lane >> 2;
    const int m0   = blockIdx.x * 64;
    const int n0   = blockIdx.y * 64;
    const int mf    = w >> 1;
    const int nhalf = w & 1;

    float acc[4][4];
    #pragma unroll
    for (int j = 0; j < 4; j++)
        #pragma unroll
        for (int e = 0; e < 4; e++) acc[j][e] = 0.f;

    const int a_m0 = t >> 3,         a_k4_0 = t & 7;
    const int a_m1 = (t + 256) >> 3, a_k4_1 = (t + 256) & 7;
    const int b_k0 = t >> 4,         b_n4_0 = t & 15;
    const int b_k1 = (t + 256) >> 4, b_n4_1 = (t + 256) & 15;

    float4 ra0, ra1, rb0, rb1;
    ra0 = *(const float4*)&A[(size_t)(m0 + a_m0) * 256 + 0 + a_k4_0 * 4];
    ra1 = *(const float4*)&A[(size_t)(m0 + a_m1) * 256 + 0 + a_k4_1 * 4];
    rb0 = *(const float4*)&W[(size_t)(0 + b_k0) * 256 + n0 + b_n4_0 * 4];
    rb1 = *(const float4*)&W[(size_t)(0 + b_k1) * 256 + n0 + b_n4_1 * 4];

    for (int c = 0; c < 8; c++) {
        const int buf = c & 1;
        {
            #pragma unroll
            for (int p = 0; p < 2; p++) {
                int m  = p ? a_m1 : a_m0;
                int k4 = p ? a_k4_1 : a_k4_0;
                float4 v = p ? ra1 : ra0;
                int frag = (m >> 4) * 4 + (k4 >> 1);
                int idx  = (k4 & 1) * 2 + ((m & 15) >> 3);
                uint32_t* dst = (uint32_t*)&AF[buf][frag * 32 + ((m & 7) * 4)];
                dst[0 * 4 + idx] = f2tf(v.x);
                dst[1 * 4 + idx] = f2tf(v.y);
                dst[2 * 4 + idx] = f2tf(v.z);
                dst[3 * 4 + idx] = f2tf(v.w);
            }
            #pragma unroll
            for (int p = 0; p < 2; p++) {
                int k  = p ? b_k1 : b_k0;
                int n4 = p ? b_n4_1 : b_n4_0;
                float4 v = p ? rb1 : rb0;
                int frag = (n4 >> 1) * 4 + (k >> 3);
                int hi   = (k >> 2) & 1;
                uint32_t* dst = (uint32_t*)&BF[buf][frag * 32 + (n4 & 1) * 16 + (k & 3)];
                dst[0 * 8 + hi] = f2tf(v.x);
                dst[1 * 8 + hi] = f2tf(v.y);
                dst[2 * 8 + hi] = f2tf(v.z);
                dst[3 * 8 + hi] = f2tf(v.w);
            }
        }
        __syncthreads();

        if (c < 7) {
            int kt = (c + 1) * 32;
            ra0 = *(const float4*)&A[(size_t)(m0 + a_m0) * 256 + kt + a_k4_0 * 4];
            ra1 = *(const float4*)&A[(size_t)(m0 + a_m1) * 256 + kt + a_k4_1 * 4];
            rb0 = *(const float4*)&W[(size_t)(kt + b_k0) * 256 + n0 + b_n4_0 * 4];
            rb1 = *(const float4*)&W[(size_t)(kt + b_k1) * 256 + n0 + b_n4_1 * 4];
        }

        #pragma unroll
        for (int ks = 0; ks < 4; ks++) {
            uint4 a = AF[buf][(mf * 4 + ks) * 32 + lane];
            #pragma unroll
            for (int j = 0; j < 4; j++) {
                uint2 b = BF[buf][((nhalf * 4 + j) * 4 + ks) * 32 + lane];
                mma_tf32(acc[j][0], acc[j][1], acc[j][2], acc[j][3],
                         a.x, a.y, a.z, a.w, b.x, b.y);
            }
        }
    }

    const int row0 = m0 + mf * 16 + g;
    const int key0 = mf * 16 + g;
    const int ck   = m0 >> 6;
    #pragma unroll
    for (int j = 0; j < 4; j++) {
        int col = n0 + nhalf * 32 + j * 8 + 2 * q;
        float2 bz = *(const float2*)&bias[col];
        float v00 = acc[j][0] + bz.x, v01 = acc[j][1] + bz.y;
        float v10 = acc[j][2] + bz.x, v11 = acc[j][3] + bz.y;
        if (mode == 0) {
            v00 *= scale; v01 *= scale; v10 *= scale; v11 *= scale;
            size_t base = (size_t)(col >> 5) * ((size_t)N * 32) + (col & 31);
            *(float2*)&out[base + (size_t)row0 * 32]       = make_float2(v00, v01);
            *(float2*)&out[base + (size_t)(row0 + 8) * 32] = make_float2(v10, v11);
        } else {
            int hh = col >> 5, dd = col & 31;
            if (mode == 2) {
                uint32_t* KD = &g_kf[((size_t)hh * NCHUNK + ck) * 1024];
                KD[kaddr16(key0,     dd)] = packh2(v00, v01);
                KD[kaddr16(key0 + 8, dd)] = packh2(v10, v11);
            } else {
                __half* VD = (__half*)&g_vf[((size_t)hh * NCHUNK + ck) * 1024];
                VD[vaddr16h(key0,     dd)]     = __float2half_rn(v00);
                VD[vaddr16h(key0,     dd + 1)] = __float2half_rn(v01);
                VD[vaddr16h(key0 + 8, dd)]     = __float2half_rn(v10);
                VD[vaddr16h(key0 + 8, dd + 1)] = __float2half_rn(v11);
            }
        }
    }
}

// fused Q/K/V projections
__global__ __launch_bounds__(256) void qkv_proj(const float* __restrict__ q,
                                                const float* __restrict__ k,
                                                const float* __restrict__ v,
                                                const float* __restrict__ Wq,
                                                const float* __restrict__ Wk,
                                                const float* __restrict__ Wv,
                                                const float* __restrict__ bq,
                                                const float* __restrict__ bk,
                                                const float* __restrict__ bv,
                                                float* __restrict__ oq,
                                                float scale)
{
    int z = blockIdx.z;
    if (z == 0)      proj_body(q, Wq, bq, oq,      scale, 0);
    else if (z == 1) proj_body(k, Wk, bk, nullptr, 1.f,   2);
    else             proj_body(v, Wv, bv, nullptr, 1.f,   3);
}

// -------------------- O-projection with fused split-K combine -------------
__global__ __launch_bounds__(256) void o_proj_fused(const float* __restrict__ W,
                                                    const float* __restrict__ bo,
                                                    float* __restrict__ out)
{
    __shared__ uint4 AF[2][16 * 32];   // 16 KB
    __shared__ uint2 BF[2][32 * 32];   // 16 KB
    __shared__ float4 WC[64][8];       // 8 KB: [row_local][head] = wgt_s/l

    const int t    = threadIdx.x;
    const int lane = t & 31;
    const int w    = t >> 5;
    const int q    = lane & 3;
    const int g    = lane >> 2;
    const int m0   = blockIdx.x * 64;
    const int n0   = blockIdx.y * 64;
    const int mf    = w >> 1;
    const int nhalf = w & 1;

    // ---- prologue: combine weights for this block's 64 rows x 8 heads ----
    #pragma unroll
    for (int p = 0; p < 2; p++) {
        int idx = t + p * 256;
        int r = idx >> 3, hh = idx & 7;
        int row = m0 + r;
        float pm[4], pl[4];
        float M = -INFINITY;
        #pragma unroll
        for (int s = 0; s < 4; s++) {
            pm[s] = g_pm[(s * HEADS + hh) * N + row];
            pl[s] = g_pl[(s * HEADS + hh) * N + row];
            M = fmaxf(M, pm[s]);
        }
        float wgt[4], l = 0.f;
        #pragma unroll
        for (int s = 0; s < 4; s++) { wgt[s] = __expf(pm[s] - M); l += pl[s] * wgt[s]; }
        float inv = 1.f / l;
        WC[r][hh] = make_float4(wgt[0] * inv, wgt[1] * inv, wgt[2] * inv, wgt[3] * inv);
    }
    __syncthreads();   // WC visible before first store phase reads it

    float acc[4][4];
    #pragma unroll
    for (int j = 0; j < 4; j++)
        #pragma unroll
        for (int e = 0; e < 4; e++) acc[j][e] = 0.f;

    const int a_m0 = t >> 3,         a_k4_0 = t & 7;
    const int a_m1 = (t + 256) >> 3, a_k4_1 = (t + 256) & 7;
    const int b_k0 = t >> 4,         b_n4_0 = t & 15;
    const int b_k1 = (t + 256) >> 4, b_n4_1 = (t + 256) & 15;

    float4 pv[2][4];
    float4 rb0, rb1;
    #pragma unroll
    for (int p = 0; p < 2; p++) {
        int m  = p ? a_m1 : a_m0;
        int d0 = (p ? a_k4_1 : a_k4_0) * 4;
        #pragma unroll
        for (int s = 0; s < 4; s++)
            pv[p][s] = *(const float4*)&g_pav[(((size_t)(s * HEADS + 0)) * N + m0 + m) * DK + d0];
    }
    rb0 = *(const float4*)&W[(size_t)(0 + b_k0) * 256 + n0 + b_n4_0 * 4];
    rb1 = *(const float4*)&W[(size_t)(0 + b_k1) * 256 + n0 + b_n4_1 * 4];

    for (int c = 0; c < 8; c++) {
        const int buf = c & 1;
        {
            #pragma unroll
            for (int p = 0; p < 2; p++) {
                int m  = p ? a_m1 : a_m0;
                int k4 = p ? a_k4_1 : a_k4_0;
                float4 wc = WC[m][c];
                float4 v;
                v.x = wc.x * pv[p][0].x + wc.y * pv[p][1].x + wc.z * pv[p][2].x + wc.w * pv[p][3].x;
                v.y = wc.x * pv[p][0].y + wc.y * pv[p][1].y + wc.z * pv[p][2].y + wc.w * pv[p][3].y;
                v.z = wc.x * pv[p][0].z + wc.y * pv[p][1].z + wc.z * pv[p][2].z + wc.w * pv[p][3].z;
                v.w = wc.x * pv[p][0].w + wc.y * pv[p][1].w + wc.z * pv[p][2].w + wc.w * pv[p][3].w;
                int frag = (m >> 4) * 4 + (k4 >> 1);
                int idx  = (k4 & 1) * 2 + ((m & 15) >> 3);
                uint32_t* dst = (uint32_t*)&AF[buf][frag * 32 + ((m & 7) * 4)];
                dst[0 * 4 + idx] = f2tf(v.x);
                dst[1 * 4 + idx] = f2tf(v.y);
                dst[2 * 4 + idx] = f2tf(v.z);
                dst[3 * 4 + idx] = f2tf(v.w);
            }
            #pragma unroll
            for (int p = 0; p < 2; p++) {
                int k  = p ? b_k1 : b_k0;
                int n4 = p ? b_n4_1 : b_n4_0;
                float4 v = p ? rb1 : rb0;
                int frag = (n4 >> 1) * 4 + (k >> 3);
                int hi   = (k >> 2) & 1;
                uint32_t* dst = (uint32_t*)&BF[buf][frag * 32 + (n4 & 1) * 16 + (k & 3)];
                dst[0 * 8 + hi] = f2tf(v.x);
                dst[1 * 8 + hi] = f2tf(v.y);
                dst[2 * 8 + hi] = f2tf(v.z);
                dst[3 * 8 + hi] = f2tf(v.w);
            }
        }
        __syncthreads();

        if (c < 7) {
            int hh = c + 1;
            #pragma unroll
            for (int p = 0; p < 2; p++) {
                int m  = p ? a_m1 : a_m0;
                int d0 = (p ? a_k4_1 : a_k4_0) * 4;
                #pragma unroll
                for (int s = 0; s < 4; s++)
                    pv[p][s] = *(const float4*)&g_pav[(((size_t)(s * HEADS + hh)) * N + m0 + m) * DK + d0];
            }
            int kt = hh * 32;
            rb0 = *(const float4*)&W[(size_t)(kt + b_k0) * 256 + n0 + b_n4_0 * 4];
            rb1 = *(const float4*)&W[(size_t)(kt + b_k1) * 256 + n0 + b_n4_1 * 4];
        }

        #pragma unroll
        for (int ks = 0; ks < 4; ks++) {
            uint4 a = AF[buf][(mf * 4 + ks) * 32 + lane];
            #pragma unroll
            for (int j = 0; j < 4; j++) {
                uint2 b = BF[buf][((nhalf * 4 + j) * 4 + ks) * 32 + lane];
                mma_tf32(acc[j][0], acc[j][1], acc[j][2], acc[j][3],
                         a.x, a.y, a.z, a.w, b.x, b.y);
            }
        }
    }

    const int row0 = m0 + mf * 16 + g;
    #pragma unroll
    for (int j = 0; j < 4; j++) {
        int col = n0 + nhalf * 32 + j * 8 + 2 * q;
        float2 bz = *(const float2*)&bo[col];
        *(float2*)&out[(size_t)row0 * 256 + col] =
            make_float2(acc[j][0] + bz.x, acc[j][1] + bz.y);
        *(float2*)&out[(size_t)(row0 + 8) * 256 + col] =
            make_float2(acc[j][2] + bz.x, acc[j][3] + bz.y);
    }
}

// -------------------- fp16 tensor-core flash attention ---------------------
// grid (N/64, HEADS, NSPLIT), 128 threads. cp.async double-buffered K/V AND
// fp16 bias tiles (dynamic smem, 34.8 KB).
__global__ __launch_bounds__(128) void attn_mma_kernel()
{
    extern __shared__ uint32_t dsm[];
    uint32_t* KBb = dsm;                     // [2][1024]
    uint32_t* VBb = dsm + 2048;              // [2][1024]
    __half*   BSb = (__half*)(dsm + 4096);   // [2][64*BSTR]

    const int tid  = threadIdx.x;
    const int lane = tid & 31;
    const int warp = tid >> 5;
    const int q    = lane & 3;
    const int g    = lane >> 2;
    const int h  = blockIdx.y;
    const int z  = blockIdx.z;
    const int q0 = blockIdx.x * 64;
    const int wr0 = warp * 16;
    const int row = q0 + wr0 + g;

    uint32_t qa[2][4];
    {
        const float* q0p = &g_qh[((size_t)h * N + row) * DK];
        const float* q8p = q0p + 8 * DK;
        #pragma unroll
        for (int ks = 0; ks < 2; ks++) {
            int d = ks * 16 + 2 * q;
            qa[ks][0] = packh2(q0p[d],     q0p[d + 1]);
            qa[ks][1] = packh2(q8p[d],     q8p[d + 1]);
            qa[ks][2] = packh2(q0p[d + 8], q0p[d + 9]);
            qa[ks][3] = packh2(q8p[d + 8], q8p[d + 9]);
        }
    }

    float o[4][4];
    #pragma unroll
    for (int n = 0; n < 4; n++)
        #pragma unroll
        for (int e = 0; e < 4; e++) o[n][e] = 0.f;

    float m0 = -INFINITY, m8 = -INFINITY, l0 = 0.f, l8 = 0.f;

    const int ck0 = (z * KSPAN) / 64;
    const int nch = KSPAN / 64;

    auto fill = [&](int buf, int ck) {
        const uint4* ks = (const uint4*)&g_kf[(size_t)(h * NCHUNK + ck) * 1024];
        const uint4* vs = (const uint4*)&g_vf[(size_t)(h * NCHUNK + ck) * 1024];
        #pragma unroll
        for (int i = 0; i < 2; i++) {
            int idx = i * 128 + tid;
            cp16((uint32_t)__cvta_generic_to_shared(&KBb[buf * 1024 + idx * 4]), ks + idx);
            cp16((uint32_t)__cvta_generic_to_shared(&VBb[buf * 1024 + idx * 4]), vs + idx);
        }
        const __half* bsrc = &g_bias[(size_t)q0 * N + ck * 64];
        __half* bdst = &BSb[buf * 64 * BSTR];
        #pragma unroll
        for (int i = 0; i < 4; i++) {
            int idx = i * 128 + tid;        // 0..511 16B-chunks
            int r = idx >> 3, c8 = idx & 7;
            cp16((uint32_t)__cvta_generic_to_shared(&bdst[r * BSTR + c8 * 8]),
                 &bsrc[(size_t)r * N + c8 * 8]);
        }
    };

    fill(0, ck0);
    asm volatile("cp.async.commit_group;");

    for (int cc = 0; cc < nch; cc++) {
        const int cur = cc & 1;

        if (cc + 1 < nch) {
            fill(1 - cur, ck0 + cc + 1);
            asm volatile("cp.async.commit_group;");
            asm volatile("cp.async.wait_group 1;");
        } else {
            asm volatile("cp.async.wait_group 0;");
        }
        __syncthreads();

        const uint32_t* KBc = &KBb[cur * 1024];
        const uint32_t* VBc = &VBb[cur * 1024];
        const __half*   BSc = &BSb[cur * 64 * BSTR];

        // ---- S = Q @ K^T ----
        float s[8][4];
        #pragma unroll
        for (int j = 0; j < 8; j++)
            #pragma unroll
            for (int e = 0; e < 4; e++) s[j][e] = 0.f;

        #pragma unroll
        for (int ks = 0; ks < 2; ks++) {
            #pragma unroll
            for (int j = 0; j < 8; j++) {
                uint2 b = *(const uint2*)&KBc[((ks * 8 + j) * 32 + lane) * 2];
                mma_f16(s[j][0], s[j][1], s[j][2], s[j][3],
                        qa[ks][0], qa[ks][1], qa[ks][2], qa[ks][3], b.x, b.y);
            }
        }

        // ---- + bias (fp16 smem tile) ----
        {
            const __half* br0 = &BSc[(wr0 + g) * BSTR];
            const __half* br8 = br0 + 8 * BSTR;
            #pragma unroll
            for (int j = 0; j < 8; j++) {
                float2 b0 = __half22float2(*(const __half2*)&br0[8 * j + 2 * q]);
                float2 b8 = __half22float2(*(const __half2*)&br8[8 * j + 2 * q]);
                s[j][0] += b0.x; s[j][1] += b0.y;
                s[j][2] += b8.x; s[j][3] += b8.y;
            }
        }

        // ---- online softmax ----
        float mx0 = s[0][0], mx8 = s[0][2];
        #pragma unroll
        for (int j = 0; j < 8; j++) {
            mx0 = fmaxf(mx0, fmaxf(s[j][0], s[j][1]));
            mx8 = fmaxf(mx8, fmaxf(s[j][2], s[j][3]));
        }
        mx0 = fmaxf(mx0, __shfl_xor_sync(0xffffffffu, mx0, 1));
        mx0 = fmaxf(mx0, __shfl_xor_sync(0xffffffffu, mx0, 2));
        mx8 = fmaxf(mx8, __shfl_xor_sync(0xffffffffu, mx8, 1));
        mx8 = fmaxf(mx8, __shfl_xor_sync(0xffffffffu, mx8, 2));

        float mn0 = fmaxf(m0, mx0), mn8 = fmaxf(m8, mx8);
        float c0 = __expf(m0 - mn0), c8 = __expf(m8 - mn8);
        m0 = mn0; m8 = mn8;
        l0 *= c0;  l8 *= c8;
        #pragma unroll
        for (int n = 0; n < 4; n++) {
            o[n][0] *= c0; o[n][1] *= c0;
            o[n][2] *= c8; o[n][3] *= c8;
        }

        float p[8][4];
        #pragma unroll
        for (int j = 0; j < 8; j++) {
            p[j][0] = __expf(s[j][0] - m0);
            p[j][1] = __expf(s[j][1] - m0);
            p[j][2] = __expf(s[j][2] - m8);
            p[j][3] = __expf(s[j][3] - m8);
            l0 += p[j][0] + p[j][1];
            l8 += p[j][2] + p[j][3];
        }

        // ---- O += P @ V ----
        #pragma unroll
        for (int kk = 0; kk < 4; kk++) {
            uint32_t a0 = packh2(p[2 * kk][0],     p[2 * kk][1]);
            uint32_t a1 = packh2(p[2 * kk][2],     p[2 * kk][3]);
            uint32_t a2 = packh2(p[2 * kk + 1][0], p[2 * kk + 1][1]);
            uint32_t a3 = packh2(p[2 * kk + 1][2], p[2 * kk + 1][3]);
            #pragma unroll
            for (int n = 0; n < 4; n++) {
                uint2 b = *(const uint2*)&VBc[((kk * 4 + n) * 32 + lane) * 2];
                mma_f16(o[n][0], o[n][1], o[n][2], o[n][3], a0, a1, a2, a3, b.x, b.y);
            }
        }
        __syncthreads();
    }

    l0 += __shfl_xor_sync(0xffffffffu, l0, 1);
    l0 += __shfl_xor_sync(0xffffffffu, l0, 2);
    l8 += __shfl_xor_sync(0xffffffffu, l8, 1);
    l8 += __shfl_xor_sync(0xffffffffu, l8, 2);

    const int rid = (z * HEADS + h) * N + q0 + wr0 + g;
    if (q == 0) {
        g_pm[rid] = m0;     g_pl[rid] = l0;
        g_pm[rid + 8] = m8; g_pl[rid + 8] = l8;
    }
    float* pav0 = &g_pav[(size_t)rid * DK];
    float* pav8 = &g_pav[(size_t)(rid + 8) * DK];
    #pragma unroll
    for (int n = 0; n < 4; n++) {
        *(float2*)&pav0[8 * n + 2 * q] = make_float2(o[n][0], o[n][1]);
        *(float2*)&pav8[8 * n + 2 * q] = make_float2(o[n][2], o[n][3]);
    }
}

// -------------------- launch ------------------------------------------------
extern "C" void kernel_launch(void* const* d_in, const int* in_sizes, int n_in,
                              void* d_out, int out_size)
{
    const int*   label   = (const int*)  d_in[0];
    const float* dist    = (const float*)d_in[1];
    const float* contact = (const float*)d_in[2];
    const float* q       = (const float*)d_in[3];
    const float* k       = (const float*)d_in[4];
    const float* v       = (const float*)d_in[5];
    const float* Wq = (const float*)d_in[6];  const float* bq = (const float*)d_in[7];
    const float* Wk = (const float*)d_in[8];  const float* bk = (const float*)d_in[9];
    const float* Wv = (const float*)d_in[10]; const float* bv = (const float*)d_in[11];
    const float* Wo = (const float*)d_in[12]; const float* bo = (const float*)d_in[13];
    const float* Wd1 = (const float*)d_in[14]; const float* bd1 = (const float*)d_in[15];
    const float* Wd2 = (const float*)d_in[16]; const float* bd2 = (const float*)d_in[17];
    const float* Wc1 = (const float*)d_in[18]; const float* bc1 = (const float*)d_in[19];
    const float* Wc2 = (const float*)d_in[20]; const float* bc2 = (const float*)d_in[21];
    float* out = (float*)d_out;

    float* p_qh;
    cudaGetSymbolAddress((void**)&p_qh, g_qh);

    bias_kernel<<<(N * N / 4) / 256, 256>>>(label, dist, contact,
                                            Wd1, bd1, Wd2, bd2, Wc1, bc1, Wc2, bc2);

    const float scale = 1.f / sqrtf((float)DK);
    qkv_proj<<<dim3(N / 64, HIDDEN / 64, 3), 256>>>(q, k, v, Wq, Wk, Wv,
                                                    bq, bk, bv, p_qh, scale);

    const int attn_smem = 4096 * 4 + 2 * 64 * BSTR * 2;   // 34816 B
    static int smem_set = 0;
    if (!smem_set) {
        cudaFuncSetAttribute(attn_mma_kernel,
                             cudaFuncAttributeMaxDynamicSharedMemorySize, attn_smem);
        smem_set = 1;
    }
    attn_mma_kernel<<<dim3(N / 64, HEADS, NSPLIT), 128, attn_smem>>>();

    o_proj_fused<<<dim3(N / 64, HIDDEN / 64), 256>>>(Wo, bo, out);
}